// round 4
// baseline (speedup 1.0000x reference)
#include <cuda_runtime.h>
#include <math.h>

#define D_MODEL  1024
#define N_HEADS  16
#define HEAD_DIM 64
#define BATCH    4
#define SEQ      2048
#define M_TOTAL  (BATCH * SEQ)   // 8192

// ---------------------------------------------------------------------------
// Scratch (tf32 bit patterns stored as unsigned)
// ---------------------------------------------------------------------------
__device__ unsigned g_xt [(size_t)M_TOTAL * D_MODEL];   // x   in tf32
__device__ unsigned g_Wqt[(size_t)D_MODEL * D_MODEL];
__device__ unsigned g_Wkt[(size_t)D_MODEL * D_MODEL];
__device__ unsigned g_Wvt[(size_t)D_MODEL * D_MODEL];
__device__ unsigned g_Wot[(size_t)D_MODEL * D_MODEL];
__device__ unsigned g_Q  [(size_t)M_TOTAL * D_MODEL];   // [B,H,T,Dh] tf32
__device__ unsigned g_K  [(size_t)M_TOTAL * D_MODEL];
__device__ unsigned g_V  [(size_t)M_TOTAL * D_MODEL];
__device__ unsigned g_Y  [(size_t)M_TOTAL * D_MODEL];   // [B,T,D] tf32

// ---------------------------------------------------------------------------
// tf32 helpers
// ---------------------------------------------------------------------------
__device__ __forceinline__ unsigned f2tf(float f) {
    unsigned r;
    asm("cvt.rna.tf32.f32 %0, %1;" : "=r"(r) : "f"(f));
    return r;
}

__device__ __forceinline__ void mma_tf32(float c[4],
    unsigned a0, unsigned a1, unsigned a2, unsigned a3,
    unsigned b0, unsigned b1)
{
    asm volatile(
        "mma.sync.aligned.m16n8k8.row.col.f32.tf32.tf32.f32 "
        "{%0,%1,%2,%3}, {%4,%5,%6,%7}, {%8,%9}, {%0,%1,%2,%3};"
        : "+f"(c[0]), "+f"(c[1]), "+f"(c[2]), "+f"(c[3])
        : "r"(a0), "r"(a1), "r"(a2), "r"(a3), "r"(b0), "r"(b1));
}

__device__ __forceinline__ void cpa16(unsigned saddr, const void* gptr) {
    asm volatile("cp.async.cg.shared.global [%0], [%1], 16;"
                 :: "r"(saddr), "l"(gptr));
}

// ---------------------------------------------------------------------------
// fp32 -> tf32 conversion pass
// ---------------------------------------------------------------------------
__global__ void cvt_tf32_kernel(const float4* __restrict__ src,
                                uint4* __restrict__ dst, int n4)
{
    int i = blockIdx.x * blockDim.x + threadIdx.x;
    if (i < n4) {
        float4 v = src[i];
        uint4 u;
        u.x = f2tf(v.x); u.y = f2tf(v.y); u.z = f2tf(v.z); u.w = f2tf(v.w);
        dst[i] = u;
    }
}

// ---------------------------------------------------------------------------
// GEMM: C = A[M,K](tf32) @ B[N,K](tf32)^T + bias(fp32)
// BM=256, BN=128, BK=32; 256 threads = 8 warps (4x2), warp tile 64x64.
// 3-stage cp.async pipeline, 1 barrier per iter. MODE1: headed tf32 out.
// ---------------------------------------------------------------------------
#define GK 1024
#define GN 1024
#define G_PA 36
#define G_AW (256 * G_PA)              // 9216 words / stage
#define G_BW (128 * G_PA)              // 4608
#define G_SW (G_AW + G_BW)             // 13824
#define GSTAGES 3
#define GEMM_SMEM (GSTAGES * G_SW * 4) // 165888 bytes
#define G_ITERS (GK / 32)              // 32

template <int MODE>   // 0: plain fp32 [M,N], 1: headed tf32 [B,H,T,Dh]
__global__ void __launch_bounds__(256, 1) gemm_tf32_kernel(
    const unsigned* __restrict__ A,
    const unsigned* __restrict__ B0, const float* __restrict__ bias0, void* __restrict__ C0,
    const unsigned* __restrict__ B1, const float* __restrict__ bias1, void* __restrict__ C1,
    const unsigned* __restrict__ B2, const float* __restrict__ bias2, void* __restrict__ C2)
{
    extern __shared__ unsigned smg[];
    const int z = blockIdx.z;
    const unsigned* B  = (z == 0) ? B0    : (z == 1) ? B1    : B2;
    const float* bias  = (z == 0) ? bias0 : (z == 1) ? bias1 : bias2;
    void*        Cv    = (z == 0) ? C0    : (z == 1) ? C1    : C2;

    const int tid  = threadIdx.x;
    const int lane = tid & 31;
    const int w    = tid >> 5;
    const int wm   = w & 3;
    const int wn   = w >> 2;
    const int g    = lane >> 2;
    const int q    = lane & 3;
    const int bm   = blockIdx.y;
    const int bn   = blockIdx.x;

    const unsigned* Ab = A + (size_t)bm * 256 * GK;
    const unsigned* Bb = B + (size_t)bn * 128 * GK;
    const unsigned sbase = (unsigned)__cvta_generic_to_shared(smg);

    // per-thread copy coordinates (8 A chunks + 4 B chunks of 16B)
    const int cr = tid >> 3;            // 0..31  (row step 32 for A, reuse for B)
    const int cc = (tid & 7) << 2;      // word col 0..28

    float acc[4][8][4];
#pragma unroll
    for (int mt = 0; mt < 4; mt++)
#pragma unroll
        for (int nt = 0; nt < 8; nt++)
#pragma unroll
            for (int i = 0; i < 4; i++) acc[mt][nt][i] = 0.0f;

#define G_ISSUE(S, KK)                                                       \
    {                                                                        \
        unsigned as_ = sbase + (unsigned)((S) * G_SW) * 4u;                  \
        unsigned bs_ = as_ + (unsigned)G_AW * 4u;                            \
        _Pragma("unroll")                                                    \
        for (int i = 0; i < 8; i++) {                                        \
            int r = cr + i * 32;                                             \
            cpa16(as_ + (unsigned)(r * G_PA + cc) * 4u,                      \
                  Ab + (size_t)r * GK + (KK) + cc);                          \
        }                                                                    \
        _Pragma("unroll")                                                    \
        for (int i = 0; i < 4; i++) {                                        \
            int r = cr + i * 32;                                             \
            cpa16(bs_ + (unsigned)(r * G_PA + cc) * 4u,                      \
                  Bb + (size_t)r * GK + (KK) + cc);                          \
        }                                                                    \
    }

    G_ISSUE(0, 0);
    asm volatile("cp.async.commit_group;");
    G_ISSUE(1, 32);
    asm volatile("cp.async.commit_group;");

    for (int it = 0; it < G_ITERS; it++) {
        asm volatile("cp.async.wait_group 1;" ::: "memory");
        __syncthreads();

        if (it + 2 < G_ITERS) {
            int s = (it + 2) % GSTAGES;
            G_ISSUE(s, (it + 2) * 32);
        }
        asm volatile("cp.async.commit_group;");

        const unsigned* As = smg + (it % GSTAGES) * G_SW;
        const unsigned* Bs = As + G_AW;

#pragma unroll
        for (int ks = 0; ks < 4; ks++) {
            const int k = ks * 8;
            unsigned af[4][4], bf[8][2];
#pragma unroll
            for (int mt = 0; mt < 4; mt++) {
                int r = wm * 64 + mt * 16 + g;
                af[mt][0] = As[r * G_PA + k + q];
                af[mt][1] = As[(r + 8) * G_PA + k + q];
                af[mt][2] = As[r * G_PA + k + q + 4];
                af[mt][3] = As[(r + 8) * G_PA + k + q + 4];
            }
#pragma unroll
            for (int nt = 0; nt < 8; nt++) {
                int ccn = wn * 64 + nt * 8 + g;
                bf[nt][0] = Bs[ccn * G_PA + k + q];
                bf[nt][1] = Bs[ccn * G_PA + k + q + 4];
            }
#pragma unroll
            for (int mt = 0; mt < 4; mt++)
#pragma unroll
                for (int nt = 0; nt < 8; nt++)
                    mma_tf32(acc[mt][nt], af[mt][0], af[mt][1], af[mt][2], af[mt][3],
                             bf[nt][0], bf[nt][1]);
        }
    }

    // Epilogue
#pragma unroll
    for (int mt = 0; mt < 4; mt++) {
        int m0 = bm * 256 + wm * 64 + mt * 16 + g;
        int m1 = m0 + 8;
#pragma unroll
        for (int nt = 0; nt < 8; nt++) {
            int n0 = bn * 128 + wn * 64 + nt * 8 + 2 * q;
            int n1 = n0 + 1;
            float b0 = bias[n0], b1 = bias[n1];
            float v00 = acc[mt][nt][0] + b0;
            float v01 = acc[mt][nt][1] + b1;
            float v10 = acc[mt][nt][2] + b0;
            float v11 = acc[mt][nt][3] + b1;
            if (MODE == 1) {
                unsigned* C = (unsigned*)Cv;
                int bb0 = m0 / SEQ, t0 = m0 % SEQ;
                int bb1 = m1 / SEQ, t1 = m1 % SEQ;
                int h0 = n0 >> 6, d0 = n0 & 63;
                int h1 = n1 >> 6, d1 = n1 & 63;
                C[(((size_t)(bb0 * N_HEADS + h0) * SEQ) + t0) * HEAD_DIM + d0] = f2tf(v00);
                C[(((size_t)(bb0 * N_HEADS + h1) * SEQ) + t0) * HEAD_DIM + d1] = f2tf(v01);
                C[(((size_t)(bb1 * N_HEADS + h0) * SEQ) + t1) * HEAD_DIM + d0] = f2tf(v10);
                C[(((size_t)(bb1 * N_HEADS + h1) * SEQ) + t1) * HEAD_DIM + d1] = f2tf(v11);
            } else {
                float* C = (float*)Cv;
                C[(size_t)m0 * GN + n0] = v00;
                C[(size_t)m0 * GN + n1] = v01;
                C[(size_t)m1 * GN + n0] = v10;
                C[(size_t)m1 * GN + n1] = v11;
            }
        }
    }
#undef G_ISSUE
}

// ---------------------------------------------------------------------------
// Flash attention: CTA = 128 q-rows for one (b,h), 64-key tiles.
// Q/K/V already tf32. Output Y written as tf32.
// ---------------------------------------------------------------------------
#define AKP 68
#define AVP 72
#define A_KS 0
#define A_VS (64 * AKP)
#define A_QS (A_VS + 64 * AVP)
#define A_PS (A_QS + 128 * AKP)
#define ATTN_SMEM ((A_PS + 128 * AKP) * 4)

__global__ void __launch_bounds__(256, 2) attn_tf32_kernel(
    const unsigned* __restrict__ Q, const unsigned* __restrict__ K,
    const unsigned* __restrict__ V, unsigned* __restrict__ Y)
{
    extern __shared__ unsigned sma[];
    unsigned* Ks = sma + A_KS;
    unsigned* Vs = sma + A_VS;
    unsigned* Qs = sma + A_QS;
    unsigned* Ps = sma + A_PS;

    const int tid  = threadIdx.x;
    const int lane = tid & 31;
    const int w    = tid >> 5;
    const int g    = lane >> 2;
    const int q    = lane & 3;
    const int qt   = (int)gridDim.x - 1 - (int)blockIdx.x;
    const int bh   = blockIdx.y;
    const int q0   = qt * 128;

    const int r0  = w * 16 + g;
    const int r1  = r0 + 8;
    const int gr0 = q0 + r0;
    const int gr1 = q0 + r1;
    const int gw0 = q0 + w * 16;

    {
        const unsigned* Qp = Q + ((size_t)bh * SEQ + q0) * HEAD_DIM;
#pragma unroll
        for (int i = 0; i < 8; i++) {
            int idx = i * 256 + tid;
            int row = idx >> 4, c4 = (idx & 15) << 2;
            *(uint4*)&Qs[row * AKP + c4] = *(const uint4*)(Qp + row * HEAD_DIM + c4);
        }
    }

    float o[8][4];
#pragma unroll
    for (int nt = 0; nt < 8; nt++)
#pragma unroll
        for (int i = 0; i < 4; i++) o[nt][i] = 0.0f;
    float m0 = -1e30f, m1 = -1e30f, l0 = 0.0f, l1 = 0.0f;

    const int kt_max = 2 * qt + 2;

    for (int kt = 0; kt < kt_max; kt++) {
        __syncthreads();
        const int k0 = kt * 64;
        {
            const unsigned* Kp = K + ((size_t)bh * SEQ + k0) * HEAD_DIM;
            const unsigned* Vp = V + ((size_t)bh * SEQ + k0) * HEAD_DIM;
#pragma unroll
            for (int i = 0; i < 4; i++) {
                int idx = i * 256 + tid;
                int row = idx >> 4, c4 = (idx & 15) << 2;
                *(uint4*)&Ks[row * AKP + c4] = *(const uint4*)(Kp + row * HEAD_DIM + c4);
                *(uint4*)&Vs[row * AVP + c4] = *(const uint4*)(Vp + row * HEAD_DIM + c4);
            }
        }
        __syncthreads();

        if (k0 <= gw0 + 15) {
            float sc[8][4];
#pragma unroll
            for (int nt = 0; nt < 8; nt++)
#pragma unroll
                for (int i = 0; i < 4; i++) sc[nt][i] = 0.0f;

#pragma unroll
            for (int ks = 0; ks < 8; ks++) {
                const int k = ks * 8;
                unsigned a0 = Qs[r0 * AKP + k + q];
                unsigned a1 = Qs[r1 * AKP + k + q];
                unsigned a2 = Qs[r0 * AKP + k + q + 4];
                unsigned a3 = Qs[r1 * AKP + k + q + 4];
#pragma unroll
                for (int nt = 0; nt < 8; nt++) {
                    unsigned b0 = Ks[(nt * 8 + g) * AKP + k + q];
                    unsigned b1 = Ks[(nt * 8 + g) * AKP + k + q + 4];
                    mma_tf32(sc[nt], a0, a1, a2, a3, b0, b1);
                }
            }

            const bool need_mask = (k0 + 63 > gr0 - g);
#pragma unroll
            for (int nt = 0; nt < 8; nt++) {
                int ck = k0 + nt * 8 + 2 * q;
                sc[nt][0] *= 0.125f; sc[nt][1] *= 0.125f;
                sc[nt][2] *= 0.125f; sc[nt][3] *= 0.125f;
                if (need_mask) {
                    if (ck     > gr0) sc[nt][0] = -1e30f;
                    if (ck + 1 > gr0) sc[nt][1] = -1e30f;
                    if (ck     > gr1) sc[nt][2] = -1e30f;
                    if (ck + 1 > gr1) sc[nt][3] = -1e30f;
                }
            }

            float rm0 = -1e30f, rm1 = -1e30f;
#pragma unroll
            for (int nt = 0; nt < 8; nt++) {
                rm0 = fmaxf(rm0, fmaxf(sc[nt][0], sc[nt][1]));
                rm1 = fmaxf(rm1, fmaxf(sc[nt][2], sc[nt][3]));
            }
            rm0 = fmaxf(rm0, __shfl_xor_sync(0xffffffffu, rm0, 1));
            rm0 = fmaxf(rm0, __shfl_xor_sync(0xffffffffu, rm0, 2));
            rm1 = fmaxf(rm1, __shfl_xor_sync(0xffffffffu, rm1, 1));
            rm1 = fmaxf(rm1, __shfl_xor_sync(0xffffffffu, rm1, 2));

            float nm0 = fmaxf(m0, rm0);
            float nm1 = fmaxf(m1, rm1);
            float cr0 = __expf(m0 - nm0);
            float cr1 = __expf(m1 - nm1);

            float s0 = 0.0f, s1 = 0.0f;
#pragma unroll
            for (int nt = 0; nt < 8; nt++) {
                sc[nt][0] = __expf(sc[nt][0] - nm0);
                sc[nt][1] = __expf(sc[nt][1] - nm0);
                sc[nt][2] = __expf(sc[nt][2] - nm1);
                sc[nt][3] = __expf(sc[nt][3] - nm1);
                s0 += sc[nt][0] + sc[nt][1];
                s1 += sc[nt][2] + sc[nt][3];
            }
            s0 += __shfl_xor_sync(0xffffffffu, s0, 1);
            s0 += __shfl_xor_sync(0xffffffffu, s0, 2);
            s1 += __shfl_xor_sync(0xffffffffu, s1, 1);
            s1 += __shfl_xor_sync(0xffffffffu, s1, 2);

            l0 = l0 * cr0 + s0;
            l1 = l1 * cr1 + s1;
            m0 = nm0; m1 = nm1;

#pragma unroll
            for (int nt = 0; nt < 8; nt++) {
                o[nt][0] *= cr0; o[nt][1] *= cr0;
                o[nt][2] *= cr1; o[nt][3] *= cr1;
            }

#pragma unroll
            for (int nt = 0; nt < 8; nt++) {
                int col = nt * 8 + 2 * q;
                uint2 p0; p0.x = f2tf(sc[nt][0]); p0.y = f2tf(sc[nt][1]);
                *(uint2*)&Ps[r0 * AKP + col] = p0;
                uint2 p1; p1.x = f2tf(sc[nt][2]); p1.y = f2tf(sc[nt][3]);
                *(uint2*)&Ps[r1 * AKP + col] = p1;
            }
            __syncwarp();

#pragma unroll
            for (int ks = 0; ks < 8; ks++) {
                const int k = ks * 8;
                unsigned a0 = Ps[r0 * AKP + k + q];
                unsigned a1 = Ps[r1 * AKP + k + q];
                unsigned a2 = Ps[r0 * AKP + k + q + 4];
                unsigned a3 = Ps[r1 * AKP + k + q + 4];
#pragma unroll
                for (int nt = 0; nt < 8; nt++) {
                    unsigned b0 = Vs[(k + q) * AVP + nt * 8 + g];
                    unsigned b1 = Vs[(k + q + 4) * AVP + nt * 8 + g];
                    mma_tf32(o[nt], a0, a1, a2, a3, b0, b1);
                }
            }
        }
    }

    const float inv0 = 1.0f / l0;
    const float inv1 = 1.0f / l1;
    const int b = bh >> 4;
    const int h = bh & 15;
    unsigned* y0 = Y + ((size_t)b * SEQ + gr0) * D_MODEL + h * HEAD_DIM;
    unsigned* y1 = Y + ((size_t)b * SEQ + gr1) * D_MODEL + h * HEAD_DIM;
#pragma unroll
    for (int nt = 0; nt < 8; nt++) {
        int d = nt * 8 + 2 * q;
        uint2 v0; v0.x = f2tf(o[nt][0] * inv0); v0.y = f2tf(o[nt][1] * inv0);
        *(uint2*)&y0[d] = v0;
        uint2 v1; v1.x = f2tf(o[nt][2] * inv1); v1.y = f2tf(o[nt][3] * inv1);
        *(uint2*)&y1[d] = v1;
    }
}

// ---------------------------------------------------------------------------
// Launch
// ---------------------------------------------------------------------------
extern "C" void kernel_launch(void* const* d_in, const int* in_sizes, int n_in,
                              void* d_out, int out_size)
{
    const float* x  = (const float*)d_in[0];
    const float* Wq = (const float*)d_in[1];
    const float* bq = (const float*)d_in[2];
    const float* Wk = (const float*)d_in[3];
    const float* bk = (const float*)d_in[4];
    const float* Wv = (const float*)d_in[5];
    const float* bv = (const float*)d_in[6];
    const float* Wo = (const float*)d_in[7];
    const float* bo = (const float*)d_in[8];
    float* out = (float*)d_out;

    unsigned *xt, *Wqt, *Wkt, *Wvt, *Wot, *Qb, *Kb, *Vb, *Yb;
    cudaGetSymbolAddress((void**)&xt,  g_xt);
    cudaGetSymbolAddress((void**)&Wqt, g_Wqt);
    cudaGetSymbolAddress((void**)&Wkt, g_Wkt);
    cudaGetSymbolAddress((void**)&Wvt, g_Wvt);
    cudaGetSymbolAddress((void**)&Wot, g_Wot);
    cudaGetSymbolAddress((void**)&Qb,  g_Q);
    cudaGetSymbolAddress((void**)&Kb,  g_K);
    cudaGetSymbolAddress((void**)&Vb,  g_V);
    cudaGetSymbolAddress((void**)&Yb,  g_Y);

    static bool attr_set = false;
    if (!attr_set) {
        cudaFuncSetAttribute(gemm_tf32_kernel<1>,
                             cudaFuncAttributeMaxDynamicSharedMemorySize, GEMM_SMEM);
        cudaFuncSetAttribute(gemm_tf32_kernel<0>,
                             cudaFuncAttributeMaxDynamicSharedMemorySize, GEMM_SMEM);
        cudaFuncSetAttribute(attn_tf32_kernel,
                             cudaFuncAttributeMaxDynamicSharedMemorySize, ATTN_SMEM);
        attr_set = true;
    }

    // tf32 pre-conversion
    const int WN4 = D_MODEL * D_MODEL / 4;           // 262144
    const int XN4 = M_TOTAL * D_MODEL / 4;           // 2097152
    cvt_tf32_kernel<<<XN4 / 256, 256>>>((const float4*)x,  (uint4*)xt,  XN4);
    cvt_tf32_kernel<<<WN4 / 256, 256>>>((const float4*)Wq, (uint4*)Wqt, WN4);
    cvt_tf32_kernel<<<WN4 / 256, 256>>>((const float4*)Wk, (uint4*)Wkt, WN4);
    cvt_tf32_kernel<<<WN4 / 256, 256>>>((const float4*)Wv, (uint4*)Wvt, WN4);
    cvt_tf32_kernel<<<WN4 / 256, 256>>>((const float4*)Wo, (uint4*)Wot, WN4);

    // Fused QKV projections
    dim3 qkvgrid(GN / 128, M_TOTAL / 256, 3);
    gemm_tf32_kernel<1><<<qkvgrid, 256, GEMM_SMEM>>>(
        xt, Wqt, bq, Qb, Wkt, bk, Kb, Wvt, bv, Vb);

    dim3 agrid(SEQ / 128, BATCH * N_HEADS);
    attn_tf32_kernel<<<agrid, 256, ATTN_SMEM>>>(Qb, Kb, Vb, Yb);

    dim3 ogrid(GN / 128, M_TOTAL / 256, 1);
    gemm_tf32_kernel<0><<<ogrid, 256, GEMM_SMEM>>>(
        Yb, Wot, bo, out, Wot, bo, out, Wot, bo, out);
}

// round 6
// speedup vs baseline: 1.0132x; 1.0132x over previous
#include <cuda_runtime.h>
#include <math.h>

#define D_MODEL  1024
#define N_HEADS  16
#define HEAD_DIM 64
#define BATCH    4
#define SEQ      2048
#define M_TOTAL  (BATCH * SEQ)   // 8192
#define GK 1024
#define GN 1024

// ---------------------------------------------------------------------------
// Scratch (tf32 bit patterns; k-dim stored in permuted order [0,4,1,5,2,6,3,7])
// ---------------------------------------------------------------------------
__device__ __align__(256) unsigned g_xt [(size_t)M_TOTAL * D_MODEL];
__device__ __align__(256) unsigned g_Wqt[(size_t)D_MODEL * D_MODEL];
__device__ __align__(256) unsigned g_Wkt[(size_t)D_MODEL * D_MODEL];
__device__ __align__(256) unsigned g_Wvt[(size_t)D_MODEL * D_MODEL];
__device__ __align__(256) unsigned g_Wot[(size_t)D_MODEL * D_MODEL];
__device__ __align__(256) unsigned g_Q  [(size_t)M_TOTAL * D_MODEL];  // [B,H,T,Dh] d-permuted
__device__ __align__(256) unsigned g_K  [(size_t)M_TOTAL * D_MODEL];  // [B,H,T,Dh] d-permuted
__device__ __align__(256) unsigned g_V  [(size_t)M_TOTAL * D_MODEL];  // [B,H,T,Dh] natural
__device__ __align__(256) unsigned g_Y  [(size_t)M_TOTAL * D_MODEL];  // [B,T,D] permuted

// ---------------------------------------------------------------------------
// helpers
// ---------------------------------------------------------------------------
__device__ __forceinline__ unsigned f2tf(float f) {
    unsigned r;
    asm("cvt.rna.tf32.f32 %0, %1;" : "=r"(r) : "f"(f));
    return r;
}

__device__ __forceinline__ void mma_tf32(float c[4],
    unsigned a0, unsigned a1, unsigned a2, unsigned a3,
    unsigned b0, unsigned b1)
{
    asm volatile(
        "mma.sync.aligned.m16n8k8.row.col.f32.tf32.tf32.f32 "
        "{%0,%1,%2,%3}, {%4,%5,%6,%7}, {%8,%9}, {%0,%1,%2,%3};"
        : "+f"(c[0]), "+f"(c[1]), "+f"(c[2]), "+f"(c[3])
        : "r"(a0), "r"(a1), "r"(a2), "r"(a3), "r"(b0), "r"(b1));
}

__device__ __forceinline__ void cpa16(unsigned saddr, const void* gptr) {
    asm volatile("cp.async.cg.shared.global [%0], [%1], 16;"
                 :: "r"(saddr), "l"(gptr));
}

// ---------------------------------------------------------------------------
// fp32 -> tf32 + k-permute pass. Orig col j (within 8-group) -> pos:
// j<4 -> 2j ; j>=4 -> 2(j-4)+1.  A float4 covers {4j..4j+3} -> stride-2 slots.
// ---------------------------------------------------------------------------
__global__ void cvt_perm_kernel(const float4* __restrict__ src,
                                unsigned* __restrict__ dst, int n4)
{
    int i = blockIdx.x * blockDim.x + threadIdx.x;
    if (i < n4) {
        float4 v = src[i];
        int wi = i * 4;
        int base = (wi & ~7) + ((wi & 4) ? 1 : 0);
        dst[base + 0] = f2tf(v.x);
        dst[base + 2] = f2tf(v.y);
        dst[base + 4] = f2tf(v.z);
        dst[base + 6] = f2tf(v.w);
    }
}

// ---------------------------------------------------------------------------
// GEMM: C = A[M,K] @ B[N,K]^T + bias  (A, B tf32 k-permuted)
// BM=256, BN=128, BK=32; 256 threads = 8 warps (4x2), warp tile 64x64.
// 3-stage cp.async pipeline; pitch 40 words (conflict-free LDS.64 frags);
// register double-buffered fragments.
// MODE 0: fp32 [M,N].  MODE 1: headed tf32 [B,H,T,Dh]; z<2 d-permuted, z=2 natural.
// ---------------------------------------------------------------------------
#define G_P   40
#define G_AW  (256 * G_P)              // 10240 words
#define G_BW  (128 * G_P)              // 5120
#define G_SW  (G_AW + G_BW)            // 15360 words = 61440 B
#define G_SMEM (3 * G_SW * 4)          // 184320 B
#define G_ITERS (GK / 32)

template <int MODE>
__global__ void __launch_bounds__(256) gemm_tf32_kernel(
    const unsigned* __restrict__ A,
    const unsigned* __restrict__ B0, const float* __restrict__ bias0, void* __restrict__ C0,
    const unsigned* __restrict__ B1, const float* __restrict__ bias1, void* __restrict__ C1,
    const unsigned* __restrict__ B2, const float* __restrict__ bias2, void* __restrict__ C2)
{
    extern __shared__ __align__(128) unsigned smg[];
    const int z = blockIdx.z;
    const unsigned* B  = (z == 0) ? B0    : (z == 1) ? B1    : B2;
    const float* bias  = (z == 0) ? bias0 : (z == 1) ? bias1 : bias2;
    void*        Cv    = (z == 0) ? C0    : (z == 1) ? C1    : C2;
    const bool permd   = (z != 2);   // Q,K d-permuted; V natural

    const int tid  = threadIdx.x;
    const int lane = tid & 31;
    const int w    = tid >> 5;
    const int wm   = w & 3;
    const int wn   = w >> 2;
    const int g    = lane >> 2;
    const int q    = lane & 3;
    const int bm   = blockIdx.y;
    const int bn   = blockIdx.x;

    const unsigned* Ab = A + (size_t)bm * 256 * GK;
    const unsigned* Bb = B + (size_t)bn * 128 * GK;
    const unsigned sb  = (unsigned)__cvta_generic_to_shared(smg);

    float acc[4][8][4];
#pragma unroll
    for (int mt = 0; mt < 4; mt++)
#pragma unroll
        for (int nt = 0; nt < 8; nt++)
#pragma unroll
            for (int i = 0; i < 4; i++) acc[mt][nt][i] = 0.0f;

#define G_FILL(S, C)                                                         \
    {                                                                        \
        unsigned abase = sb + (unsigned)(S) * (G_SW * 4);                    \
        unsigned bbase = abase + (G_AW * 4);                                 \
        _Pragma("unroll")                                                    \
        for (int i = 0; i < 8; i++) {                                        \
            int idx = i * 256 + tid;                                         \
            int r = idx >> 3, c16 = idx & 7;                                 \
            cpa16(abase + (unsigned)(r * G_P + c16 * 4) * 4u,                \
                  Ab + (size_t)r * GK + (C) * 32 + c16 * 4);                 \
        }                                                                    \
        _Pragma("unroll")                                                    \
        for (int i = 0; i < 4; i++) {                                        \
            int idx = i * 256 + tid;                                         \
            int r = idx >> 3, c16 = idx & 7;                                 \
            cpa16(bbase + (unsigned)(r * G_P + c16 * 4) * 4u,                \
                  Bb + (size_t)r * GK + (C) * 32 + c16 * 4);                 \
        }                                                                    \
    }

    G_FILL(0, 0);
    asm volatile("cp.async.commit_group;" ::: "memory");
    G_FILL(1, 1);
    asm volatile("cp.async.commit_group;" ::: "memory");

    uint2 af[2][4][2];
    uint2 bf[2][8];

#define G_LOADF(BUF, KS)                                                     \
    {                                                                        \
        _Pragma("unroll")                                                    \
        for (int mt = 0; mt < 4; mt++) {                                     \
            int r = wm * 64 + mt * 16 + g;                                   \
            af[BUF][mt][0] = *(const uint2*)&As[r * G_P + (KS) * 8 + 2 * q]; \
            af[BUF][mt][1] = *(const uint2*)&As[(r + 8) * G_P + (KS) * 8 + 2 * q]; \
        }                                                                    \
        _Pragma("unroll")                                                    \
        for (int nt = 0; nt < 8; nt++) {                                     \
            int c = wn * 64 + nt * 8 + g;                                    \
            bf[BUF][nt] = *(const uint2*)&Bs[c * G_P + (KS) * 8 + 2 * q];    \
        }                                                                    \
    }

    for (int it = 0; it < G_ITERS; it++) {
        asm volatile("cp.async.wait_group 1;" ::: "memory");
        __syncthreads();

        if (it + 2 < G_ITERS) {
            G_FILL((it + 2) % 3, it + 2);
        }
        asm volatile("cp.async.commit_group;" ::: "memory");

        const unsigned* As = smg + (it % 3) * G_SW;
        const unsigned* Bs = As + G_AW;

        G_LOADF(0, 0);
#pragma unroll
        for (int ks = 0; ks < 4; ks++) {
            const int cur = ks & 1;
            if (ks < 3) G_LOADF(cur ^ 1, ks + 1);
#pragma unroll
            for (int mt = 0; mt < 4; mt++)
#pragma unroll
                for (int nt = 0; nt < 8; nt++)
                    mma_tf32(acc[mt][nt],
                             af[cur][mt][0].x, af[cur][mt][1].x,
                             af[cur][mt][0].y, af[cur][mt][1].y,
                             bf[cur][nt].x,    bf[cur][nt].y);
        }
    }
#undef G_FILL
#undef G_LOADF

    // Epilogue
    const int p0 = permd ? ((q < 2) ? 4 * q : 4 * q - 7) : 2 * q;
    const int stp = permd ? 2 : 1;
#pragma unroll
    for (int mt = 0; mt < 4; mt++) {
        int m0 = bm * 256 + wm * 64 + mt * 16 + g;
        int m1 = m0 + 8;
#pragma unroll
        for (int nt = 0; nt < 8; nt++) {
            int nb = wn * 64 + nt * 8;
            int n0 = bn * 128 + nb + 2 * q;
            float b0 = bias[n0], b1 = bias[n0 + 1];
            float v00 = acc[mt][nt][0] + b0;
            float v01 = acc[mt][nt][1] + b1;
            float v10 = acc[mt][nt][2] + b0;
            float v11 = acc[mt][nt][3] + b1;
            if (MODE == 1) {
                unsigned* C = (unsigned*)Cv;
                int h  = (bn * 128 + nb) >> 6;
                int d0 = (nb & 63) + p0;
                int d1 = d0 + stp;
                int bb0 = m0 / SEQ, t0 = m0 % SEQ;
                int bb1 = m1 / SEQ, t1 = m1 % SEQ;
                size_t r0o = (((size_t)(bb0 * N_HEADS + h) * SEQ) + t0) * HEAD_DIM;
                size_t r1o = (((size_t)(bb1 * N_HEADS + h) * SEQ) + t1) * HEAD_DIM;
                C[r0o + d0] = f2tf(v00);
                C[r0o + d1] = f2tf(v01);
                C[r1o + d0] = f2tf(v10);
                C[r1o + d1] = f2tf(v11);
            } else {
                float* C = (float*)Cv;
                float2 u0; u0.x = v00; u0.y = v01;
                *(float2*)&C[(size_t)m0 * GN + n0] = u0;
                float2 u1; u1.x = v10; u1.y = v11;
                *(float2*)&C[(size_t)m1 * GN + n0] = u1;
            }
        }
    }
}

// ---------------------------------------------------------------------------
// Flash attention: CTA = 128 q-rows for one (b,h), 64-key tiles.
// Q/K d-permuted in global; V natural. P stored permuted by us.
// Pitch 72 everywhere -> conflict-free LDS.64 frags. Y written permuted.
// ---------------------------------------------------------------------------
#define AP 72
#define A_KS 0
#define A_VS (64 * AP)                 // 4608
#define A_QS (A_VS + 64 * AP)          // 9216
#define A_PS (A_QS + 128 * AP)         // 18432
#define ATTN_SMEM ((A_PS + 128 * AP) * 4)   // 110592 B

__global__ void __launch_bounds__(256, 2) attn_tf32_kernel(
    const unsigned* __restrict__ Q, const unsigned* __restrict__ K,
    const unsigned* __restrict__ V, unsigned* __restrict__ Y)
{
    extern __shared__ unsigned sma[];
    unsigned* Ks = sma + A_KS;
    unsigned* Vs = sma + A_VS;
    unsigned* Qs = sma + A_QS;
    unsigned* Ps = sma + A_PS;

    const int tid  = threadIdx.x;
    const int lane = tid & 31;
    const int w    = tid >> 5;
    const int g    = lane >> 2;
    const int q    = lane & 3;
    const int qt   = (int)gridDim.x - 1 - (int)blockIdx.x;
    const int bh   = blockIdx.y;
    const int q0   = qt * 128;

    const int r0  = w * 16 + g;
    const int r1  = r0 + 8;
    const int gr0 = q0 + r0;
    const int gr1 = q0 + r1;
    const int gw0 = q0 + w * 16;
    const int p0  = (q < 2) ? 4 * q : 4 * q - 7;   // perm slot of orig col 2q

    {
        const unsigned* Qp = Q + ((size_t)bh * SEQ + q0) * HEAD_DIM;
#pragma unroll
        for (int i = 0; i < 8; i++) {
            int idx = i * 256 + tid;
            int row = idx >> 4, c4 = (idx & 15) << 2;
            *(uint4*)&Qs[row * AP + c4] = *(const uint4*)(Qp + row * HEAD_DIM + c4);
        }
    }

    float o[8][4];
#pragma unroll
    for (int nt = 0; nt < 8; nt++)
#pragma unroll
        for (int i = 0; i < 4; i++) o[nt][i] = 0.0f;
    float m0 = -1e30f, m1 = -1e30f, l0 = 0.0f, l1 = 0.0f;

    const int kt_max = 2 * qt + 2;

    for (int kt = 0; kt < kt_max; kt++) {
        __syncthreads();
        const int k0 = kt * 64;
        {
            const unsigned* Kp = K + ((size_t)bh * SEQ + k0) * HEAD_DIM;
            const unsigned* Vp = V + ((size_t)bh * SEQ + k0) * HEAD_DIM;
#pragma unroll
            for (int i = 0; i < 4; i++) {
                int idx = i * 256 + tid;
                int row = idx >> 4, c4 = (idx & 15) << 2;
                *(uint4*)&Ks[row * AP + c4] = *(const uint4*)(Kp + row * HEAD_DIM + c4);
                *(uint4*)&Vs[row * AP + c4] = *(const uint4*)(Vp + row * HEAD_DIM + c4);
            }
        }
        __syncthreads();

        if (k0 <= gw0 + 15) {
            // ---- S = Q @ K^T
            float sc[8][4];
#pragma unroll
            for (int nt = 0; nt < 8; nt++)
#pragma unroll
                for (int i = 0; i < 4; i++) sc[nt][i] = 0.0f;

#pragma unroll
            for (int ks = 0; ks < 8; ks++) {
                const int k = ks * 8;
                uint2 a0 = *(const uint2*)&Qs[r0 * AP + k + 2 * q];
                uint2 a1 = *(const uint2*)&Qs[r1 * AP + k + 2 * q];
#pragma unroll
                for (int nt = 0; nt < 8; nt++) {
                    uint2 b = *(const uint2*)&Ks[(nt * 8 + g) * AP + k + 2 * q];
                    mma_tf32(sc[nt], a0.x, a1.x, a0.y, a1.y, b.x, b.y);
                }
            }

            const bool need_mask = (k0 + 63 > gr0 - g);
#pragma unroll
            for (int nt = 0; nt < 8; nt++) {
                int ck = k0 + nt * 8 + 2 * q;
                sc[nt][0] *= 0.125f; sc[nt][1] *= 0.125f;
                sc[nt][2] *= 0.125f; sc[nt][3] *= 0.125f;
                if (need_mask) {
                    if (ck     > gr0) sc[nt][0] = -1e30f;
                    if (ck + 1 > gr0) sc[nt][1] = -1e30f;
                    if (ck     > gr1) sc[nt][2] = -1e30f;
                    if (ck + 1 > gr1) sc[nt][3] = -1e30f;
                }
            }

            // ---- warp-local online softmax
            float rm0 = -1e30f, rm1 = -1e30f;
#pragma unroll
            for (int nt = 0; nt < 8; nt++) {
                rm0 = fmaxf(rm0, fmaxf(sc[nt][0], sc[nt][1]));
                rm1 = fmaxf(rm1, fmaxf(sc[nt][2], sc[nt][3]));
            }
            rm0 = fmaxf(rm0, __shfl_xor_sync(0xffffffffu, rm0, 1));
            rm0 = fmaxf(rm0, __shfl_xor_sync(0xffffffffu, rm0, 2));
            rm1 = fmaxf(rm1, __shfl_xor_sync(0xffffffffu, rm1, 1));
            rm1 = fmaxf(rm1, __shfl_xor_sync(0xffffffffu, rm1, 2));

            float nm0 = fmaxf(m0, rm0);
            float nm1 = fmaxf(m1, rm1);
            float cr0 = __expf(m0 - nm0);
            float cr1 = __expf(m1 - nm1);

            float s0 = 0.0f, s1 = 0.0f;
#pragma unroll
            for (int nt = 0; nt < 8; nt++) {
                sc[nt][0] = __expf(sc[nt][0] - nm0);
                sc[nt][1] = __expf(sc[nt][1] - nm0);
                sc[nt][2] = __expf(sc[nt][2] - nm1);
                sc[nt][3] = __expf(sc[nt][3] - nm1);
                s0 += sc[nt][0] + sc[nt][1];
                s1 += sc[nt][2] + sc[nt][3];
            }
            s0 += __shfl_xor_sync(0xffffffffu, s0, 1);
            s0 += __shfl_xor_sync(0xffffffffu, s0, 2);
            s1 += __shfl_xor_sync(0xffffffffu, s1, 1);
            s1 += __shfl_xor_sync(0xffffffffu, s1, 2);

            l0 = l0 * cr0 + s0;
            l1 = l1 * cr1 + s1;
            m0 = nm0; m1 = nm1;

#pragma unroll
            for (int nt = 0; nt < 8; nt++) {
                o[nt][0] *= cr0; o[nt][1] *= cr0;
                o[nt][2] *= cr1; o[nt][3] *= cr1;
            }

            // ---- P -> per-warp smem, stored k-permuted
#pragma unroll
            for (int nt = 0; nt < 8; nt++) {
                int col = nt * 8 + p0;
                Ps[r0 * AP + col]     = f2tf(sc[nt][0]);
                Ps[r0 * AP + col + 2] = f2tf(sc[nt][1]);
                Ps[r1 * AP + col]     = f2tf(sc[nt][2]);
                Ps[r1 * AP + col + 2] = f2tf(sc[nt][3]);
            }
            __syncwarp();

            // ---- O += P @ V
#pragma unroll
            for (int ks = 0; ks < 8; ks++) {
                const int k = ks * 8;
                uint2 a0 = *(const uint2*)&Ps[r0 * AP + k + 2 * q];
                uint2 a1 = *(const uint2*)&Ps[r1 * AP + k + 2 * q];
#pragma unroll
                for (int nt = 0; nt < 8; nt++) {
                    unsigned b0 = Vs[(k + q) * AP + nt * 8 + g];
                    unsigned b1 = Vs[(k + q + 4) * AP + nt * 8 + g];
                    mma_tf32(o[nt], a0.x, a1.x, a0.y, a1.y, b0, b1);
                }
            }
        }
    }

    // ---- epilogue: normalize; write Y permuted (consumed by O-proj GEMM)
    const float inv0 = 1.0f / l0;
    const float inv1 = 1.0f / l1;
    const int b = bh >> 4;
    const int h = bh & 15;
    unsigned* y0 = Y + ((size_t)b * SEQ + gr0) * D_MODEL + h * HEAD_DIM;
    unsigned* y1 = Y + ((size_t)b * SEQ + gr1) * D_MODEL + h * HEAD_DIM;
#pragma unroll
    for (int nt = 0; nt < 8; nt++) {
        int d = nt * 8 + p0;
        y0[d]     = f2tf(o[nt][0] * inv0);
        y0[d + 2] = f2tf(o[nt][1] * inv0);
        y1[d]     = f2tf(o[nt][2] * inv1);
        y1[d + 2] = f2tf(o[nt][3] * inv1);
    }
}

// ---------------------------------------------------------------------------
// Launch
// ---------------------------------------------------------------------------
extern "C" void kernel_launch(void* const* d_in, const int* in_sizes, int n_in,
                              void* d_out, int out_size)
{
    const float* x  = (const float*)d_in[0];
    const float* Wq = (const float*)d_in[1];
    const float* bq = (const float*)d_in[2];
    const float* Wk = (const float*)d_in[3];
    const float* bk = (const float*)d_in[4];
    const float* Wv = (const float*)d_in[5];
    const float* bv = (const float*)d_in[6];
    const float* Wo = (const float*)d_in[7];
    const float* bo = (const float*)d_in[8];
    float* out = (float*)d_out;

    unsigned *xt, *Wqt, *Wkt, *Wvt, *Wot, *Qb, *Kb, *Vb, *Yb;
    cudaGetSymbolAddress((void**)&xt,  g_xt);
    cudaGetSymbolAddress((void**)&Wqt, g_Wqt);
    cudaGetSymbolAddress((void**)&Wkt, g_Wkt);
    cudaGetSymbolAddress((void**)&Wvt, g_Wvt);
    cudaGetSymbolAddress((void**)&Wot, g_Wot);
    cudaGetSymbolAddress((void**)&Qb,  g_Q);
    cudaGetSymbolAddress((void**)&Kb,  g_K);
    cudaGetSymbolAddress((void**)&Vb,  g_V);
    cudaGetSymbolAddress((void**)&Yb,  g_Y);

    static bool attr_set = false;
    if (!attr_set) {
        cudaFuncSetAttribute(gemm_tf32_kernel<1>,
                             cudaFuncAttributeMaxDynamicSharedMemorySize, G_SMEM);
        cudaFuncSetAttribute(gemm_tf32_kernel<0>,
                             cudaFuncAttributeMaxDynamicSharedMemorySize, G_SMEM);
        cudaFuncSetAttribute(attn_tf32_kernel,
                             cudaFuncAttributeMaxDynamicSharedMemorySize, ATTN_SMEM);
        attr_set = true;
    }

    // tf32 + k-permute pre-conversion
    const int WN4 = D_MODEL * D_MODEL / 4;
    const int XN4 = M_TOTAL * D_MODEL / 4;
    cvt_perm_kernel<<<XN4 / 256, 256>>>((const float4*)x,  xt,  XN4);
    cvt_perm_kernel<<<WN4 / 256, 256>>>((const float4*)Wq, Wqt, WN4);
    cvt_perm_kernel<<<WN4 / 256, 256>>>((const float4*)Wk, Wkt, WN4);
    cvt_perm_kernel<<<WN4 / 256, 256>>>((const float4*)Wv, Wvt, WN4);
    cvt_perm_kernel<<<WN4 / 256, 256>>>((const float4*)Wo, Wot, WN4);

    // Fused QKV projections
    dim3 qkvgrid(GN / 128, M_TOTAL / 256, 3);   // (8, 32, 3)
    gemm_tf32_kernel<1><<<qkvgrid, 256, G_SMEM>>>(
        xt, Wqt, bq, Qb, Wkt, bk, Kb, Wvt, bv, Vb);

    dim3 agrid(SEQ / 128, BATCH * N_HEADS);     // (16, 64)
    attn_tf32_kernel<<<agrid, 256, ATTN_SMEM>>>(Qb, Kb, Vb, Yb);

    // Output projection
    dim3 ogrid(GN / 128, M_TOTAL / 256, 1);     // (8, 32)
    gemm_tf32_kernel<0><<<ogrid, 256, G_SMEM>>>(
        Yb, Wot, bo, out, Wot, bo, out, Wot, bo, out);
}

// round 7
// speedup vs baseline: 1.0325x; 1.0191x over previous
#include <cuda_runtime.h>
#include <math.h>

#define D_MODEL  1024
#define N_HEADS  16
#define HEAD_DIM 64
#define BATCH    4
#define SEQ      2048
#define M_TOTAL  (BATCH * SEQ)   // 8192
#define GK 1024
#define GN 1024

// ---------------------------------------------------------------------------
// Scratch (tf32 bit patterns; k-dim stored in permuted order [0,4,1,5,2,6,3,7])
// ---------------------------------------------------------------------------
__device__ __align__(256) unsigned g_xt [(size_t)M_TOTAL * D_MODEL];
__device__ __align__(256) unsigned g_Wqt[(size_t)D_MODEL * D_MODEL];
__device__ __align__(256) unsigned g_Wkt[(size_t)D_MODEL * D_MODEL];
__device__ __align__(256) unsigned g_Wvt[(size_t)D_MODEL * D_MODEL];
__device__ __align__(256) unsigned g_Wot[(size_t)D_MODEL * D_MODEL];
__device__ __align__(256) unsigned g_Q  [(size_t)M_TOTAL * D_MODEL];  // [B,H,T,Dh] d-permuted
__device__ __align__(256) unsigned g_K  [(size_t)M_TOTAL * D_MODEL];  // [B,H,T,Dh] d-permuted
__device__ __align__(256) unsigned g_V  [(size_t)M_TOTAL * D_MODEL];  // [B,H,T,Dh] natural
__device__ __align__(256) unsigned g_Y  [(size_t)M_TOTAL * D_MODEL];  // [B,T,D] permuted

// ---------------------------------------------------------------------------
// helpers
// ---------------------------------------------------------------------------
__device__ __forceinline__ unsigned f2tf(float f) {
    unsigned r;
    asm("cvt.rna.tf32.f32 %0, %1;" : "=r"(r) : "f"(f));
    return r;
}

__device__ __forceinline__ void mma_tf32(float c[4],
    unsigned a0, unsigned a1, unsigned a2, unsigned a3,
    unsigned b0, unsigned b1)
{
    asm volatile(
        "mma.sync.aligned.m16n8k8.row.col.f32.tf32.tf32.f32 "
        "{%0,%1,%2,%3}, {%4,%5,%6,%7}, {%8,%9}, {%0,%1,%2,%3};"
        : "+f"(c[0]), "+f"(c[1]), "+f"(c[2]), "+f"(c[3])
        : "r"(a0), "r"(a1), "r"(a2), "r"(a3), "r"(b0), "r"(b1));
}

__device__ __forceinline__ void cpa16(unsigned saddr, const void* gptr) {
    asm volatile("cp.async.cg.shared.global [%0], [%1], 16;"
                 :: "r"(saddr), "l"(gptr));
}

// ---------------------------------------------------------------------------
// fp32 -> tf32 + k-permute pass.
// ---------------------------------------------------------------------------
__global__ void cvt_perm_kernel(const float4* __restrict__ src,
                                unsigned* __restrict__ dst, int n4)
{
    int i = blockIdx.x * blockDim.x + threadIdx.x;
    if (i < n4) {
        float4 v = src[i];
        int wi = i * 4;
        int base = (wi & ~7) + ((wi & 4) ? 1 : 0);
        dst[base + 0] = f2tf(v.x);
        dst[base + 2] = f2tf(v.y);
        dst[base + 4] = f2tf(v.z);
        dst[base + 6] = f2tf(v.w);
    }
}

// ---------------------------------------------------------------------------
// GEMM: C = A[M,K] @ B[N,K]^T + bias  (A, B tf32 k-permuted)
// BM=256, BN=128, BK=32; 512 threads = 16 warps (4m x 4n), warp tile 64x32.
// 3-stage cp.async pipeline; pitch 40 (conflict-free LDS.64 frags).
// MODE 0: fp32 [M,N].  MODE 1: headed tf32 [B,H,T,Dh]; z<2 d-permuted, z=2 natural.
// ---------------------------------------------------------------------------
#define G_P   40
#define G_AW  (256 * G_P)              // 10240 words
#define G_BW  (128 * G_P)              // 5120
#define G_SW  (G_AW + G_BW)            // 15360 words
#define G_SMEM (3 * G_SW * 4)          // 184320 B
#define G_ITERS (GK / 32)
#define G_THREADS 512

template <int MODE>
__global__ void __launch_bounds__(G_THREADS, 1) gemm_tf32_kernel(
    const unsigned* __restrict__ A,
    const unsigned* __restrict__ B0, const float* __restrict__ bias0, void* __restrict__ C0,
    const unsigned* __restrict__ B1, const float* __restrict__ bias1, void* __restrict__ C1,
    const unsigned* __restrict__ B2, const float* __restrict__ bias2, void* __restrict__ C2)
{
    extern __shared__ __align__(128) unsigned smg[];
    const int z = blockIdx.z;
    const unsigned* B  = (z == 0) ? B0    : (z == 1) ? B1    : B2;
    const float* bias  = (z == 0) ? bias0 : (z == 1) ? bias1 : bias2;
    void*        Cv    = (z == 0) ? C0    : (z == 1) ? C1    : C2;
    const bool permd   = (z != 2);   // Q,K d-permuted; V natural

    const int tid  = threadIdx.x;
    const int lane = tid & 31;
    const int w    = tid >> 5;       // 0..15
    const int wm   = w >> 2;         // 0..3 (64-row slab)
    const int wn   = w & 3;          // 0..3 (32-col slab)
    const int g    = lane >> 2;
    const int q    = lane & 3;
    const int bm   = blockIdx.y;
    const int bn   = blockIdx.x;

    const unsigned* Ab = A + (size_t)bm * 256 * GK;
    const unsigned* Bb = B + (size_t)bn * 128 * GK;
    const unsigned sb  = (unsigned)__cvta_generic_to_shared(smg);

    float acc[4][4][4];
#pragma unroll
    for (int mt = 0; mt < 4; mt++)
#pragma unroll
        for (int nt = 0; nt < 4; nt++)
#pragma unroll
            for (int i = 0; i < 4; i++) acc[mt][nt][i] = 0.0f;

#define G_FILL(S, C)                                                         \
    {                                                                        \
        unsigned abase = sb + (unsigned)(S) * (G_SW * 4);                    \
        unsigned bbase = abase + (G_AW * 4);                                 \
        _Pragma("unroll")                                                    \
        for (int i = 0; i < 4; i++) {                                        \
            int idx = i * G_THREADS + tid;                                   \
            int r = idx >> 3, c16 = idx & 7;                                 \
            cpa16(abase + (unsigned)(r * G_P + c16 * 4) * 4u,                \
                  Ab + (size_t)r * GK + (C) * 32 + c16 * 4);                 \
        }                                                                    \
        _Pragma("unroll")                                                    \
        for (int i = 0; i < 2; i++) {                                        \
            int idx = i * G_THREADS + tid;                                   \
            int r = idx >> 3, c16 = idx & 7;                                 \
            cpa16(bbase + (unsigned)(r * G_P + c16 * 4) * 4u,                \
                  Bb + (size_t)r * GK + (C) * 32 + c16 * 4);                 \
        }                                                                    \
    }

    G_FILL(0, 0);
    asm volatile("cp.async.commit_group;" ::: "memory");
    G_FILL(1, 1);
    asm volatile("cp.async.commit_group;" ::: "memory");

    for (int it = 0; it < G_ITERS; it++) {
        asm volatile("cp.async.wait_group 1;" ::: "memory");
        __syncthreads();

        if (it + 2 < G_ITERS) {
            G_FILL((it + 2) % 3, it + 2);
        }
        asm volatile("cp.async.commit_group;" ::: "memory");

        const unsigned* As = smg + (it % 3) * G_SW;
        const unsigned* Bs = As + G_AW;

#pragma unroll
        for (int ks = 0; ks < 4; ks++) {
            uint2 af[4][2];
            uint2 bf[4];
#pragma unroll
            for (int mt = 0; mt < 4; mt++) {
                int r = wm * 64 + mt * 16 + g;
                af[mt][0] = *(const uint2*)&As[r * G_P + ks * 8 + 2 * q];
                af[mt][1] = *(const uint2*)&As[(r + 8) * G_P + ks * 8 + 2 * q];
            }
#pragma unroll
            for (int nt = 0; nt < 4; nt++) {
                int c = wn * 32 + nt * 8 + g;
                bf[nt] = *(const uint2*)&Bs[c * G_P + ks * 8 + 2 * q];
            }
#pragma unroll
            for (int mt = 0; mt < 4; mt++)
#pragma unroll
                for (int nt = 0; nt < 4; nt++)
                    mma_tf32(acc[mt][nt],
                             af[mt][0].x, af[mt][1].x,
                             af[mt][0].y, af[mt][1].y,
                             bf[nt].x,    bf[nt].y);
        }
    }
#undef G_FILL

    // Epilogue
    const int p0 = permd ? ((q < 2) ? 4 * q : 4 * q - 7) : 2 * q;
    const int stp = permd ? 2 : 1;
#pragma unroll
    for (int mt = 0; mt < 4; mt++) {
        int m0 = bm * 256 + wm * 64 + mt * 16 + g;
        int m1 = m0 + 8;
#pragma unroll
        for (int nt = 0; nt < 4; nt++) {
            int nb = wn * 32 + nt * 8;
            int n0 = bn * 128 + nb + 2 * q;
            float b0 = bias[n0], b1 = bias[n0 + 1];
            float v00 = acc[mt][nt][0] + b0;
            float v01 = acc[mt][nt][1] + b1;
            float v10 = acc[mt][nt][2] + b0;
            float v11 = acc[mt][nt][3] + b1;
            if (MODE == 1) {
                unsigned* C = (unsigned*)Cv;
                int h  = (bn * 128 + nb) >> 6;
                int d0 = (nb & 63) + p0;
                int d1 = d0 + stp;
                int bb0 = m0 / SEQ, t0 = m0 % SEQ;
                int bb1 = m1 / SEQ, t1 = m1 % SEQ;
                size_t r0o = (((size_t)(bb0 * N_HEADS + h) * SEQ) + t0) * HEAD_DIM;
                size_t r1o = (((size_t)(bb1 * N_HEADS + h) * SEQ) + t1) * HEAD_DIM;
                C[r0o + d0] = f2tf(v00);
                C[r0o + d1] = f2tf(v01);
                C[r1o + d0] = f2tf(v10);
                C[r1o + d1] = f2tf(v11);
            } else {
                float* C = (float*)Cv;
                float2 u0; u0.x = v00; u0.y = v01;
                *(float2*)&C[(size_t)m0 * GN + n0] = u0;
                float2 u1; u1.x = v10; u1.y = v11;
                *(float2*)&C[(size_t)m1 * GN + n0] = u1;
            }
        }
    }
}

// ---------------------------------------------------------------------------
// Flash attention: CTA = 128 q-rows for one (b,h), 64-key tiles.
// Q/K d-permuted in global; V natural. P stored permuted by us.
// Pitch 72 everywhere -> conflict-free LDS.64 frags. Y written permuted.
// ---------------------------------------------------------------------------
#define AP 72
#define A_KS 0
#define A_VS (64 * AP)
#define A_QS (A_VS + 64 * AP)
#define A_PS (A_QS + 128 * AP)
#define ATTN_SMEM ((A_PS + 128 * AP) * 4)   // 110592 B

__global__ void __launch_bounds__(256, 2) attn_tf32_kernel(
    const unsigned* __restrict__ Q, const unsigned* __restrict__ K,
    const unsigned* __restrict__ V, unsigned* __restrict__ Y)
{
    extern __shared__ unsigned sma[];
    unsigned* Ks = sma + A_KS;
    unsigned* Vs = sma + A_VS;
    unsigned* Qs = sma + A_QS;
    unsigned* Ps = sma + A_PS;

    const int tid  = threadIdx.x;
    const int lane = tid & 31;
    const int w    = tid >> 5;
    const int g    = lane >> 2;
    const int q    = lane & 3;
    const int qt   = (int)gridDim.x - 1 - (int)blockIdx.x;
    const int bh   = blockIdx.y;
    const int q0   = qt * 128;

    const int r0  = w * 16 + g;
    const int r1  = r0 + 8;
    const int gr0 = q0 + r0;
    const int gr1 = q0 + r1;
    const int gw0 = q0 + w * 16;
    const int p0  = (q < 2) ? 4 * q : 4 * q - 7;   // perm slot of orig col 2q

    {
        const unsigned* Qp = Q + ((size_t)bh * SEQ + q0) * HEAD_DIM;
#pragma unroll
        for (int i = 0; i < 8; i++) {
            int idx = i * 256 + tid;
            int row = idx >> 4, c4 = (idx & 15) << 2;
            *(uint4*)&Qs[row * AP + c4] = *(const uint4*)(Qp + row * HEAD_DIM + c4);
        }
    }

    float o[8][4];
#pragma unroll
    for (int nt = 0; nt < 8; nt++)
#pragma unroll
        for (int i = 0; i < 4; i++) o[nt][i] = 0.0f;
    float m0 = -1e30f, m1 = -1e30f, l0 = 0.0f, l1 = 0.0f;

    const int kt_max = 2 * qt + 2;

    for (int kt = 0; kt < kt_max; kt++) {
        __syncthreads();
        const int k0 = kt * 64;
        {
            const unsigned* Kp = K + ((size_t)bh * SEQ + k0) * HEAD_DIM;
            const unsigned* Vp = V + ((size_t)bh * SEQ + k0) * HEAD_DIM;
#pragma unroll
            for (int i = 0; i < 4; i++) {
                int idx = i * 256 + tid;
                int row = idx >> 4, c4 = (idx & 15) << 2;
                *(uint4*)&Ks[row * AP + c4] = *(const uint4*)(Kp + row * HEAD_DIM + c4);
                *(uint4*)&Vs[row * AP + c4] = *(const uint4*)(Vp + row * HEAD_DIM + c4);
            }
        }
        __syncthreads();

        if (k0 <= gw0 + 15) {
            // ---- S = Q @ K^T
            float sc[8][4];
#pragma unroll
            for (int nt = 0; nt < 8; nt++)
#pragma unroll
                for (int i = 0; i < 4; i++) sc[nt][i] = 0.0f;

#pragma unroll
            for (int ks = 0; ks < 8; ks++) {
                const int k = ks * 8;
                uint2 a0 = *(const uint2*)&Qs[r0 * AP + k + 2 * q];
                uint2 a1 = *(const uint2*)&Qs[r1 * AP + k + 2 * q];
#pragma unroll
                for (int nt = 0; nt < 8; nt++) {
                    uint2 b = *(const uint2*)&Ks[(nt * 8 + g) * AP + k + 2 * q];
                    mma_tf32(sc[nt], a0.x, a1.x, a0.y, a1.y, b.x, b.y);
                }
            }

            const bool need_mask = (k0 + 63 > gr0 - g);
#pragma unroll
            for (int nt = 0; nt < 8; nt++) {
                int ck = k0 + nt * 8 + 2 * q;
                sc[nt][0] *= 0.125f; sc[nt][1] *= 0.125f;
                sc[nt][2] *= 0.125f; sc[nt][3] *= 0.125f;
                if (need_mask) {
                    if (ck     > gr0) sc[nt][0] = -1e30f;
                    if (ck + 1 > gr0) sc[nt][1] = -1e30f;
                    if (ck     > gr1) sc[nt][2] = -1e30f;
                    if (ck + 1 > gr1) sc[nt][3] = -1e30f;
                }
            }

            // ---- warp-local online softmax
            float rm0 = -1e30f, rm1 = -1e30f;
#pragma unroll
            for (int nt = 0; nt < 8; nt++) {
                rm0 = fmaxf(rm0, fmaxf(sc[nt][0], sc[nt][1]));
                rm1 = fmaxf(rm1, fmaxf(sc[nt][2], sc[nt][3]));
            }
            rm0 = fmaxf(rm0, __shfl_xor_sync(0xffffffffu, rm0, 1));
            rm0 = fmaxf(rm0, __shfl_xor_sync(0xffffffffu, rm0, 2));
            rm1 = fmaxf(rm1, __shfl_xor_sync(0xffffffffu, rm1, 1));
            rm1 = fmaxf(rm1, __shfl_xor_sync(0xffffffffu, rm1, 2));

            float nm0 = fmaxf(m0, rm0);
            float nm1 = fmaxf(m1, rm1);
            float cr0 = __expf(m0 - nm0);
            float cr1 = __expf(m1 - nm1);

            float s0 = 0.0f, s1 = 0.0f;
#pragma unroll
            for (int nt = 0; nt < 8; nt++) {
                sc[nt][0] = __expf(sc[nt][0] - nm0);
                sc[nt][1] = __expf(sc[nt][1] - nm0);
                sc[nt][2] = __expf(sc[nt][2] - nm1);
                sc[nt][3] = __expf(sc[nt][3] - nm1);
                s0 += sc[nt][0] + sc[nt][1];
                s1 += sc[nt][2] + sc[nt][3];
            }
            s0 += __shfl_xor_sync(0xffffffffu, s0, 1);
            s0 += __shfl_xor_sync(0xffffffffu, s0, 2);
            s1 += __shfl_xor_sync(0xffffffffu, s1, 1);
            s1 += __shfl_xor_sync(0xffffffffu, s1, 2);

            l0 = l0 * cr0 + s0;
            l1 = l1 * cr1 + s1;
            m0 = nm0; m1 = nm1;

#pragma unroll
            for (int nt = 0; nt < 8; nt++) {
                o[nt][0] *= cr0; o[nt][1] *= cr0;
                o[nt][2] *= cr1; o[nt][3] *= cr1;
            }

            // ---- P -> per-warp smem, stored k-permuted
#pragma unroll
            for (int nt = 0; nt < 8; nt++) {
                int col = nt * 8 + p0;
                Ps[r0 * AP + col]     = f2tf(sc[nt][0]);
                Ps[r0 * AP + col + 2] = f2tf(sc[nt][1]);
                Ps[r1 * AP + col]     = f2tf(sc[nt][2]);
                Ps[r1 * AP + col + 2] = f2tf(sc[nt][3]);
            }
            __syncwarp();

            // ---- O += P @ V
#pragma unroll
            for (int ks = 0; ks < 8; ks++) {
                const int k = ks * 8;
                uint2 a0 = *(const uint2*)&Ps[r0 * AP + k + 2 * q];
                uint2 a1 = *(const uint2*)&Ps[r1 * AP + k + 2 * q];
#pragma unroll
                for (int nt = 0; nt < 8; nt++) {
                    unsigned b0 = Vs[(k + q) * AP + nt * 8 + g];
                    unsigned b1 = Vs[(k + q + 4) * AP + nt * 8 + g];
                    mma_tf32(o[nt], a0.x, a1.x, a0.y, a1.y, b0, b1);
                }
            }
        }
    }

    // ---- epilogue: normalize; write Y permuted (consumed by O-proj GEMM)
    const float inv0 = 1.0f / l0;
    const float inv1 = 1.0f / l1;
    const int b = bh >> 4;
    const int h = bh & 15;
    unsigned* y0 = Y + ((size_t)b * SEQ + gr0) * D_MODEL + h * HEAD_DIM;
    unsigned* y1 = Y + ((size_t)b * SEQ + gr1) * D_MODEL + h * HEAD_DIM;
#pragma unroll
    for (int nt = 0; nt < 8; nt++) {
        int d = nt * 8 + p0;
        y0[d]     = f2tf(o[nt][0] * inv0);
        y0[d + 2] = f2tf(o[nt][1] * inv0);
        y1[d]     = f2tf(o[nt][2] * inv1);
        y1[d + 2] = f2tf(o[nt][3] * inv1);
    }
}

// ---------------------------------------------------------------------------
// Launch
// ---------------------------------------------------------------------------
extern "C" void kernel_launch(void* const* d_in, const int* in_sizes, int n_in,
                              void* d_out, int out_size)
{
    const float* x  = (const float*)d_in[0];
    const float* Wq = (const float*)d_in[1];
    const float* bq = (const float*)d_in[2];
    const float* Wk = (const float*)d_in[3];
    const float* bk = (const float*)d_in[4];
    const float* Wv = (const float*)d_in[5];
    const float* bv = (const float*)d_in[6];
    const float* Wo = (const float*)d_in[7];
    const float* bo = (const float*)d_in[8];
    float* out = (float*)d_out;

    unsigned *xt, *Wqt, *Wkt, *Wvt, *Wot, *Qb, *Kb, *Vb, *Yb;
    cudaGetSymbolAddress((void**)&xt,  g_xt);
    cudaGetSymbolAddress((void**)&Wqt, g_Wqt);
    cudaGetSymbolAddress((void**)&Wkt, g_Wkt);
    cudaGetSymbolAddress((void**)&Wvt, g_Wvt);
    cudaGetSymbolAddress((void**)&Wot, g_Wot);
    cudaGetSymbolAddress((void**)&Qb,  g_Q);
    cudaGetSymbolAddress((void**)&Kb,  g_K);
    cudaGetSymbolAddress((void**)&Vb,  g_V);
    cudaGetSymbolAddress((void**)&Yb,  g_Y);

    static bool attr_set = false;
    if (!attr_set) {
        cudaFuncSetAttribute(gemm_tf32_kernel<1>,
                             cudaFuncAttributeMaxDynamicSharedMemorySize, G_SMEM);
        cudaFuncSetAttribute(gemm_tf32_kernel<0>,
                             cudaFuncAttributeMaxDynamicSharedMemorySize, G_SMEM);
        cudaFuncSetAttribute(attn_tf32_kernel,
                             cudaFuncAttributeMaxDynamicSharedMemorySize, ATTN_SMEM);
        attr_set = true;
    }

    // tf32 + k-permute pre-conversion
    const int WN4 = D_MODEL * D_MODEL / 4;
    const int XN4 = M_TOTAL * D_MODEL / 4;
    cvt_perm_kernel<<<XN4 / 256, 256>>>((const float4*)x,  xt,  XN4);
    cvt_perm_kernel<<<WN4 / 256, 256>>>((const float4*)Wq, Wqt, WN4);
    cvt_perm_kernel<<<WN4 / 256, 256>>>((const float4*)Wk, Wkt, WN4);
    cvt_perm_kernel<<<WN4 / 256, 256>>>((const float4*)Wv, Wvt, WN4);
    cvt_perm_kernel<<<WN4 / 256, 256>>>((const float4*)Wo, Wot, WN4);

    // Fused QKV projections
    dim3 qkvgrid(GN / 128, M_TOTAL / 256, 3);   // (8, 32, 3)
    gemm_tf32_kernel<1><<<qkvgrid, G_THREADS, G_SMEM>>>(
        xt, Wqt, bq, Qb, Wkt, bk, Kb, Wvt, bv, Vb);

    dim3 agrid(SEQ / 128, BATCH * N_HEADS);     // (16, 64)
    attn_tf32_kernel<<<agrid, 256, ATTN_SMEM>>>(Qb, Kb, Vb, Yb);

    // Output projection
    dim3 ogrid(GN / 128, M_TOTAL / 256, 1);     // (8, 32)
    gemm_tf32_kernel<0><<<ogrid, G_THREADS, G_SMEM>>>(
        Yb, Wot, bo, out, Wot, bo, out, Wot, bo, out);
}

// round 8
// speedup vs baseline: 1.8826x; 1.8233x over previous
#include <cuda_runtime.h>
#include <cuda_fp16.h>
#include <math.h>

#define D_MODEL  1024
#define N_HEADS  16
#define HEAD_DIM 64
#define BATCH    4
#define SEQ      2048
#define M_TOTAL  (BATCH * SEQ)   // 8192
#define GK 1024
#define GN 1024

// ---------------------------------------------------------------------------
// Scratch (fp16; k-dims stored permuted per 16-group: j=8h+2q+e -> 4q+2h+e)
// ---------------------------------------------------------------------------
__device__ __align__(256) __half g_xt [(size_t)M_TOTAL * D_MODEL];
__device__ __align__(256) __half g_Wqt[(size_t)D_MODEL * D_MODEL];
__device__ __align__(256) __half g_Wkt[(size_t)D_MODEL * D_MODEL];
__device__ __align__(256) __half g_Wvt[(size_t)D_MODEL * D_MODEL];
__device__ __align__(256) __half g_Wot[(size_t)D_MODEL * D_MODEL];
__device__ __align__(256) __half g_Q  [(size_t)M_TOTAL * D_MODEL];  // [B,H,T,Dh] d-perm
__device__ __align__(256) __half g_K  [(size_t)M_TOTAL * D_MODEL];  // [B,H,T,Dh] d-perm
__device__ __align__(256) __half g_Vt [(size_t)M_TOTAL * D_MODEL];  // [B,H,Dh,T] t-perm
__device__ __align__(256) __half g_Y  [(size_t)M_TOTAL * D_MODEL];  // [B,T,D] D-perm

// ---------------------------------------------------------------------------
// helpers
// ---------------------------------------------------------------------------
__device__ __forceinline__ unsigned f2h2(float lo, float hi) {
    __half2 h = __floats2half2_rn(lo, hi);   // .x = lo (low half)
    return *(unsigned*)&h;
}
__device__ __forceinline__ unsigned short f2h(float v) {
    __half h = __float2half_rn(v);
    return *(unsigned short*)&h;
}

__device__ __forceinline__ void mma_f16(float c[4],
    unsigned a0, unsigned a1, unsigned a2, unsigned a3,
    unsigned b0, unsigned b1)
{
    asm volatile(
        "mma.sync.aligned.m16n8k16.row.col.f32.f16.f16.f32 "
        "{%0,%1,%2,%3}, {%4,%5,%6,%7}, {%8,%9}, {%0,%1,%2,%3};"
        : "+f"(c[0]), "+f"(c[1]), "+f"(c[2]), "+f"(c[3])
        : "r"(a0), "r"(a1), "r"(a2), "r"(a3), "r"(b0), "r"(b1));
}

__device__ __forceinline__ void cpa16(unsigned saddr, const void* gptr) {
    asm volatile("cp.async.cg.shared.global [%0], [%1], 16;"
                 :: "r"(saddr), "l"(gptr));
}

// ---------------------------------------------------------------------------
// fp32 -> fp16 + k-permute. Word wi (mult of 4): pairs (wi,wi+1),(wi+2,wi+3)
// land at half2 slots h2 and h2+2, h2 = base16/2 + 2*((wi>>1)&3) + ((wi>>3)&1).
// ---------------------------------------------------------------------------
__global__ void cvt_h_kernel(const float4* __restrict__ src,
                             unsigned* __restrict__ dst, int n4)
{
    int i = blockIdx.x * blockDim.x + threadIdx.x;
    if (i < n4) {
        float4 v = src[i];
        int wi = i * 4;
        int h2 = ((wi & ~15) >> 1) + 2 * ((wi >> 1) & 3) + ((wi >> 3) & 1);
        dst[h2]     = f2h2(v.x, v.y);
        dst[h2 + 2] = f2h2(v.z, v.w);
    }
}

// ---------------------------------------------------------------------------
// GEMM: C = A[M,K] @ B[N,K]^T + bias (A,B fp16 k-permuted)
// BM=256, BN=128, BK=64; 512 threads = 16 warps (4m x 4n), warp tile 64x32.
// 3-stage cp.async; pitch 80 halves (conflict-free LDS.64 frags).
// MODE 1: z=0,1 -> [B,H,T,Dh] fp16 d-perm; z=2 -> [B,H,Dh,T] fp16 t-perm.
// MODE 0: fp32 [M,N].
// ---------------------------------------------------------------------------
#define G_P   80                       // halves per row
#define G_AH  (256 * G_P)              // 20480 halves
#define G_BH  (128 * G_P)              // 10240
#define G_SH  (G_AH + G_BH)            // 30720 halves = 61440 B
#define G_SMEM (3 * G_SH * 2)          // 184320 B
#define G_ITERS (GK / 64)              // 16
#define G_THREADS 512

template <int MODE>
__global__ void __launch_bounds__(G_THREADS, 1) gemm_h_kernel(
    const __half* __restrict__ A,
    const __half* __restrict__ B0, const float* __restrict__ bias0, void* __restrict__ C0,
    const __half* __restrict__ B1, const float* __restrict__ bias1, void* __restrict__ C1,
    const __half* __restrict__ B2, const float* __restrict__ bias2, void* __restrict__ C2)
{
    extern __shared__ __align__(128) __half smh[];
    const int z = blockIdx.z;
    const __half* B    = (z == 0) ? B0    : (z == 1) ? B1    : B2;
    const float* bias  = (z == 0) ? bias0 : (z == 1) ? bias1 : bias2;
    void*        Cv    = (z == 0) ? C0    : (z == 1) ? C1    : C2;

    const int tid  = threadIdx.x;
    const int lane = tid & 31;
    const int w    = tid >> 5;
    const int wm   = w >> 2;
    const int wn   = w & 3;
    const int g    = lane >> 2;
    const int q    = lane & 3;
    const int bm   = blockIdx.y;
    const int bn   = blockIdx.x;

    const __half* Ab = A + (size_t)bm * 256 * GK;
    const __half* Bb = B + (size_t)bn * 128 * GK;
    const unsigned sb = (unsigned)__cvta_generic_to_shared(smh);

    float acc[4][4][4];
#pragma unroll
    for (int mt = 0; mt < 4; mt++)
#pragma unroll
        for (int nt = 0; nt < 4; nt++)
#pragma unroll
            for (int i = 0; i < 4; i++) acc[mt][nt][i] = 0.0f;

    // A: 256 rows x 8 chunks(16B=8 halves) = 2048; B: 1024.
#define G_FILL(S, C)                                                         \
    {                                                                        \
        unsigned abase = sb + (unsigned)(S) * (G_SH * 2);                    \
        unsigned bbase = abase + (G_AH * 2);                                 \
        _Pragma("unroll")                                                    \
        for (int i = 0; i < 4; i++) {                                        \
            int idx = i * G_THREADS + tid;                                   \
            int r = idx >> 3, c8 = idx & 7;                                  \
            cpa16(abase + (unsigned)(r * G_P + c8 * 8) * 2u,                 \
                  Ab + (size_t)r * GK + (C) * 64 + c8 * 8);                  \
        }                                                                    \
        _Pragma("unroll")                                                    \
        for (int i = 0; i < 2; i++) {                                        \
            int idx = i * G_THREADS + tid;                                   \
            int r = idx >> 3, c8 = idx & 7;                                  \
            cpa16(bbase + (unsigned)(r * G_P + c8 * 8) * 2u,                 \
                  Bb + (size_t)r * GK + (C) * 64 + c8 * 8);                  \
        }                                                                    \
    }

    G_FILL(0, 0);
    asm volatile("cp.async.commit_group;" ::: "memory");
    G_FILL(1, 1);
    asm volatile("cp.async.commit_group;" ::: "memory");

    for (int it = 0; it < G_ITERS; it++) {
        asm volatile("cp.async.wait_group 1;" ::: "memory");
        __syncthreads();

        if (it + 2 < G_ITERS) {
            G_FILL((it + 2) % 3, it + 2);
        }
        asm volatile("cp.async.commit_group;" ::: "memory");

        const __half* As = smh + (it % 3) * G_SH;
        const __half* Bs = As + G_AH;

#pragma unroll
        for (int ks = 0; ks < 4; ks++) {
            uint2 af[4][2];
            uint2 bf[4];
#pragma unroll
            for (int mt = 0; mt < 4; mt++) {
                int r = wm * 64 + mt * 16 + g;
                af[mt][0] = *(const uint2*)(As + r * G_P + ks * 16 + 4 * q);
                af[mt][1] = *(const uint2*)(As + (r + 8) * G_P + ks * 16 + 4 * q);
            }
#pragma unroll
            for (int nt = 0; nt < 4; nt++) {
                int c = wn * 32 + nt * 8 + g;
                bf[nt] = *(const uint2*)(Bs + c * G_P + ks * 16 + 4 * q);
            }
#pragma unroll
            for (int mt = 0; mt < 4; mt++)
#pragma unroll
                for (int nt = 0; nt < 4; nt++)
                    mma_f16(acc[mt][nt],
                            af[mt][0].x, af[mt][1].x,
                            af[mt][0].y, af[mt][1].y,
                            bf[nt].x,    bf[nt].y);
        }
    }
#undef G_FILL

    // Epilogue
#pragma unroll
    for (int mt = 0; mt < 4; mt++) {
        int m0 = bm * 256 + wm * 64 + mt * 16 + g;
        int m1 = m0 + 8;
#pragma unroll
        for (int nt = 0; nt < 4; nt++) {
            int nb = wn * 32 + nt * 8;
            int n0 = bn * 128 + nb + 2 * q;
            float b0 = bias[n0], b1 = bias[n0 + 1];
            float v00 = acc[mt][nt][0] + b0;
            float v01 = acc[mt][nt][1] + b1;
            float v10 = acc[mt][nt][2] + b0;
            float v11 = acc[mt][nt][3] + b1;
            if (MODE == 1) {
                int h = (bn * 128 + nb) >> 6;
                if (z != 2) {
                    // Q/K: [B,H,T,Dh], d-permuted. half2 store.
                    __half* C = (__half*)Cv;
                    int slot = ((nb & 63) & ~15) + 4 * q + 2 * (nt & 1);
                    int bb0 = m0 / SEQ, t0 = m0 % SEQ;
                    int bb1 = m1 / SEQ, t1 = m1 % SEQ;
                    size_t r0o = (((size_t)(bb0 * N_HEADS + h) * SEQ) + t0) * HEAD_DIM;
                    size_t r1o = (((size_t)(bb1 * N_HEADS + h) * SEQ) + t1) * HEAD_DIM;
                    *(unsigned*)(C + r0o + slot) = f2h2(v00, v01);
                    *(unsigned*)(C + r1o + slot) = f2h2(v10, v11);
                } else {
                    // V: [B,H,Dh,T], t-permuted. 4 scalar stores.
                    __half* C = (__half*)Cv;
                    int d0 = (nb & 63) + 2 * q;
                    int bb0 = m0 / SEQ, t0 = m0 % SEQ;
                    int bb1 = m1 / SEQ, t1 = m1 % SEQ;
                    int t0p = (t0 & ~15) + 4 * (g >> 1) + (g & 1);
                    int t1p = (t1 & ~15) + 4 * (g >> 1) + 2 + (g & 1);
                    size_t base0 = ((size_t)(bb0 * N_HEADS + h) * HEAD_DIM + d0) * SEQ;
                    size_t base1 = ((size_t)(bb1 * N_HEADS + h) * HEAD_DIM + d0) * SEQ;
                    ((unsigned short*)C)[base0 + t0p]       = f2h(v00);
                    ((unsigned short*)C)[base0 + SEQ + t0p] = f2h(v01);
                    ((unsigned short*)C)[base1 + t1p]       = f2h(v10);
                    ((unsigned short*)C)[base1 + SEQ + t1p] = f2h(v11);
                }
            } else {
                float* C = (float*)Cv;
                float2 u0; u0.x = v00; u0.y = v01;
                *(float2*)&C[(size_t)m0 * GN + n0] = u0;
                float2 u1; u1.x = v10; u1.y = v11;
                *(float2*)&C[(size_t)m1 * GN + n0] = u1;
            }
        }
    }
}

// ---------------------------------------------------------------------------
// Flash attention (fp16 mma): CTA = 128 q-rows for one (b,h), 64-key tiles.
// Q/K d-permuted [B,H,T,Dh]; V transposed t-permuted [B,H,Dh,T].
// All smem pitches 80 halves -> conflict-free LDS.64 fragments.
// ---------------------------------------------------------------------------
#define AP 80
#define A_KS 0
#define A_VS (64 * AP)                 // 5120 halves
#define A_QS (A_VS + 64 * AP)          // 10240
#define A_PS (A_QS + 128 * AP)         // 20480
#define ATTN_SMEM ((A_PS + 128 * AP) * 2)   // 61440 B

__global__ void __launch_bounds__(256, 2) attn_h_kernel(
    const __half* __restrict__ Q, const __half* __restrict__ K,
    const __half* __restrict__ Vt, __half* __restrict__ Y)
{
    extern __shared__ __half smha[];
    __half* Ks = smha + A_KS;          // [key][d-perm]
    __half* Vs = smha + A_VS;          // [d][key-perm]
    __half* Qs = smha + A_QS;          // [row][d-perm]
    __half* Ps = smha + A_PS;          // [row][key-perm]

    const int tid  = threadIdx.x;
    const int lane = tid & 31;
    const int w    = tid >> 5;
    const int g    = lane >> 2;
    const int q    = lane & 3;
    const int qt   = (int)gridDim.x - 1 - (int)blockIdx.x;
    const int bh   = blockIdx.y;
    const int q0   = qt * 128;

    const int r0  = w * 16 + g;
    const int r1  = r0 + 8;
    const int gr0 = q0 + r0;
    const int gr1 = q0 + r1;
    const int gw0 = q0 + w * 16;

    {   // Q: 128 rows x 8 chunks of 8 halves
        const __half* Qp = Q + ((size_t)bh * SEQ + q0) * HEAD_DIM;
#pragma unroll
        for (int i = 0; i < 4; i++) {
            int idx = i * 256 + tid;
            int row = idx >> 3, c8 = idx & 7;
            *(uint4*)(Qs + row * AP + c8 * 8) =
                *(const uint4*)(Qp + row * HEAD_DIM + c8 * 8);
        }
    }

    float o[8][4];
#pragma unroll
    for (int nt = 0; nt < 8; nt++)
#pragma unroll
        for (int i = 0; i < 4; i++) o[nt][i] = 0.0f;
    float m0 = -1e30f, m1 = -1e30f, l0 = 0.0f, l1 = 0.0f;

    const int kt_max = 2 * qt + 2;

    for (int kt = 0; kt < kt_max; kt++) {
        __syncthreads();
        const int k0 = kt * 64;
        {
            const __half* Kp = K + ((size_t)bh * SEQ + k0) * HEAD_DIM;
            const __half* Vp = Vt + ((size_t)bh * HEAD_DIM) * SEQ + k0;
#pragma unroll
            for (int i = 0; i < 2; i++) {
                int idx = i * 256 + tid;
                int row = idx >> 3, c8 = idx & 7;
                *(uint4*)(Ks + row * AP + c8 * 8) =
                    *(const uint4*)(Kp + row * HEAD_DIM + c8 * 8);
                *(uint4*)(Vs + row * AP + c8 * 8) =
                    *(const uint4*)(Vp + (size_t)row * SEQ + c8 * 8);
            }
        }
        __syncthreads();

        if (k0 <= gw0 + 15) {
            // ---- S = Q @ K^T  (16 rows x 64 keys; 4 k16-steps)
            float sc[8][4];
#pragma unroll
            for (int nt = 0; nt < 8; nt++)
#pragma unroll
                for (int i = 0; i < 4; i++) sc[nt][i] = 0.0f;

#pragma unroll
            for (int ks = 0; ks < 4; ks++) {
                uint2 a0 = *(const uint2*)(Qs + r0 * AP + ks * 16 + 4 * q);
                uint2 a1 = *(const uint2*)(Qs + r1 * AP + ks * 16 + 4 * q);
#pragma unroll
                for (int nt = 0; nt < 8; nt++) {
                    uint2 b = *(const uint2*)(Ks + (nt * 8 + g) * AP + ks * 16 + 4 * q);
                    mma_f16(sc[nt], a0.x, a1.x, a0.y, a1.y, b.x, b.y);
                }
            }

            const bool need_mask = (k0 + 63 > gr0 - g);
#pragma unroll
            for (int nt = 0; nt < 8; nt++) {
                int ck = k0 + nt * 8 + 2 * q;
                sc[nt][0] *= 0.125f; sc[nt][1] *= 0.125f;
                sc[nt][2] *= 0.125f; sc[nt][3] *= 0.125f;
                if (need_mask) {
                    if (ck     > gr0) sc[nt][0] = -1e30f;
                    if (ck + 1 > gr0) sc[nt][1] = -1e30f;
                    if (ck     > gr1) sc[nt][2] = -1e30f;
                    if (ck + 1 > gr1) sc[nt][3] = -1e30f;
                }
            }

            // ---- warp-local online softmax
            float rm0 = -1e30f, rm1 = -1e30f;
#pragma unroll
            for (int nt = 0; nt < 8; nt++) {
                rm0 = fmaxf(rm0, fmaxf(sc[nt][0], sc[nt][1]));
                rm1 = fmaxf(rm1, fmaxf(sc[nt][2], sc[nt][3]));
            }
            rm0 = fmaxf(rm0, __shfl_xor_sync(0xffffffffu, rm0, 1));
            rm0 = fmaxf(rm0, __shfl_xor_sync(0xffffffffu, rm0, 2));
            rm1 = fmaxf(rm1, __shfl_xor_sync(0xffffffffu, rm1, 1));
            rm1 = fmaxf(rm1, __shfl_xor_sync(0xffffffffu, rm1, 2));

            float nm0 = fmaxf(m0, rm0);
            float nm1 = fmaxf(m1, rm1);
            float cr0 = __expf(m0 - nm0);
            float cr1 = __expf(m1 - nm1);

            float s0 = 0.0f, s1 = 0.0f;
#pragma unroll
            for (int nt = 0; nt < 8; nt++) {
                sc[nt][0] = __expf(sc[nt][0] - nm0);
                sc[nt][1] = __expf(sc[nt][1] - nm0);
                sc[nt][2] = __expf(sc[nt][2] - nm1);
                sc[nt][3] = __expf(sc[nt][3] - nm1);
                s0 += sc[nt][0] + sc[nt][1];
                s1 += sc[nt][2] + sc[nt][3];
            }
            s0 += __shfl_xor_sync(0xffffffffu, s0, 1);
            s0 += __shfl_xor_sync(0xffffffffu, s0, 2);
            s1 += __shfl_xor_sync(0xffffffffu, s1, 1);
            s1 += __shfl_xor_sync(0xffffffffu, s1, 2);

            l0 = l0 * cr0 + s0;
            l1 = l1 * cr1 + s1;
            m0 = nm0; m1 = nm1;

#pragma unroll
            for (int nt = 0; nt < 8; nt++) {
                o[nt][0] *= cr0; o[nt][1] *= cr0;
                o[nt][2] *= cr1; o[nt][3] *= cr1;
            }

            // ---- P -> per-warp smem, key-permuted (half2 stores)
#pragma unroll
            for (int nt = 0; nt < 8; nt++) {
                int slot = (nt >> 1) * 16 + 4 * q + 2 * (nt & 1);
                *(unsigned*)(Ps + r0 * AP + slot) = f2h2(sc[nt][0], sc[nt][1]);
                *(unsigned*)(Ps + r1 * AP + slot) = f2h2(sc[nt][2], sc[nt][3]);
            }
            __syncwarp();

            // ---- O += P @ V  (B-frags from transposed V, key-permuted)
#pragma unroll
            for (int ks = 0; ks < 4; ks++) {
                uint2 a0 = *(const uint2*)(Ps + r0 * AP + ks * 16 + 4 * q);
                uint2 a1 = *(const uint2*)(Ps + r1 * AP + ks * 16 + 4 * q);
#pragma unroll
                for (int nt = 0; nt < 8; nt++) {
                    uint2 b = *(const uint2*)(Vs + (nt * 8 + g) * AP + ks * 16 + 4 * q);
                    mma_f16(o[nt], a0.x, a1.x, a0.y, a1.y, b.x, b.y);
                }
            }
        }
    }

    // ---- epilogue: normalize; write Y fp16 D-permuted [B,T,D]
    const float inv0 = 1.0f / l0;
    const float inv1 = 1.0f / l1;
    const int b = bh >> 4;
    const int h = bh & 15;
    __half* y0 = Y + ((size_t)b * SEQ + gr0) * D_MODEL + h * HEAD_DIM;
    __half* y1 = Y + ((size_t)b * SEQ + gr1) * D_MODEL + h * HEAD_DIM;
#pragma unroll
    for (int nt = 0; nt < 8; nt++) {
        int slot = (nt >> 1) * 16 + 4 * q + 2 * (nt & 1);
        *(unsigned*)(y0 + slot) = f2h2(o[nt][0] * inv0, o[nt][1] * inv0);
        *(unsigned*)(y1 + slot) = f2h2(o[nt][2] * inv1, o[nt][3] * inv1);
    }
}

// ---------------------------------------------------------------------------
// Launch
// ---------------------------------------------------------------------------
extern "C" void kernel_launch(void* const* d_in, const int* in_sizes, int n_in,
                              void* d_out, int out_size)
{
    const float* x  = (const float*)d_in[0];
    const float* Wq = (const float*)d_in[1];
    const float* bq = (const float*)d_in[2];
    const float* Wk = (const float*)d_in[3];
    const float* bk = (const float*)d_in[4];
    const float* Wv = (const float*)d_in[5];
    const float* bv = (const float*)d_in[6];
    const float* Wo = (const float*)d_in[7];
    const float* bo = (const float*)d_in[8];
    float* out = (float*)d_out;

    __half *xt, *Wqt, *Wkt, *Wvt, *Wot, *Qb, *Kb, *Vb, *Yb;
    cudaGetSymbolAddress((void**)&xt,  g_xt);
    cudaGetSymbolAddress((void**)&Wqt, g_Wqt);
    cudaGetSymbolAddress((void**)&Wkt, g_Wkt);
    cudaGetSymbolAddress((void**)&Wvt, g_Wvt);
    cudaGetSymbolAddress((void**)&Wot, g_Wot);
    cudaGetSymbolAddress((void**)&Qb,  g_Q);
    cudaGetSymbolAddress((void**)&Kb,  g_K);
    cudaGetSymbolAddress((void**)&Vb,  g_Vt);
    cudaGetSymbolAddress((void**)&Yb,  g_Y);

    static bool attr_set = false;
    if (!attr_set) {
        cudaFuncSetAttribute(gemm_h_kernel<1>,
                             cudaFuncAttributeMaxDynamicSharedMemorySize, G_SMEM);
        cudaFuncSetAttribute(gemm_h_kernel<0>,
                             cudaFuncAttributeMaxDynamicSharedMemorySize, G_SMEM);
        cudaFuncSetAttribute(attn_h_kernel,
                             cudaFuncAttributeMaxDynamicSharedMemorySize, ATTN_SMEM);
        attr_set = true;
    }

    // fp16 + k-permute pre-conversion
    const int WN4 = D_MODEL * D_MODEL / 4;
    const int XN4 = M_TOTAL * D_MODEL / 4;
    cvt_h_kernel<<<XN4 / 256, 256>>>((const float4*)x,  (unsigned*)xt,  XN4);
    cvt_h_kernel<<<WN4 / 256, 256>>>((const float4*)Wq, (unsigned*)Wqt, WN4);
    cvt_h_kernel<<<WN4 / 256, 256>>>((const float4*)Wk, (unsigned*)Wkt, WN4);
    cvt_h_kernel<<<WN4 / 256, 256>>>((const float4*)Wv, (unsigned*)Wvt, WN4);
    cvt_h_kernel<<<WN4 / 256, 256>>>((const float4*)Wo, (unsigned*)Wot, WN4);

    // Fused QKV projections
    dim3 qkvgrid(GN / 128, M_TOTAL / 256, 3);   // (8, 32, 3)
    gemm_h_kernel<1><<<qkvgrid, G_THREADS, G_SMEM>>>(
        xt, Wqt, bq, Qb, Wkt, bk, Kb, Wvt, bv, Vb);

    dim3 agrid(SEQ / 128, BATCH * N_HEADS);     // (16, 64)
    attn_h_kernel<<<agrid, 256, ATTN_SMEM>>>(Qb, Kb, Vb, Yb);

    // Output projection
    dim3 ogrid(GN / 128, M_TOTAL / 256, 1);     // (8, 32)
    gemm_h_kernel<0><<<ogrid, G_THREADS, G_SMEM>>>(
        Yb, Wot, bo, out, Wot, bo, out, Wot, bo, out);
}

// round 9
// speedup vs baseline: 1.9722x; 1.0476x over previous
#include <cuda_runtime.h>
#include <cuda_fp16.h>
#include <math.h>

#define D_MODEL  1024
#define N_HEADS  16
#define HEAD_DIM 64
#define BATCH    4
#define SEQ      2048
#define M_TOTAL  (BATCH * SEQ)   // 8192
#define GK 1024
#define GN 1024

// ---------------------------------------------------------------------------
// Scratch (fp16; k-dims stored permuted per 16-group: j=8h+2q+e -> 4q+2h+e)
// ---------------------------------------------------------------------------
__device__ __align__(256) __half g_xt [(size_t)M_TOTAL * D_MODEL];
__device__ __align__(256) __half g_Wqt[(size_t)D_MODEL * D_MODEL];
__device__ __align__(256) __half g_Wkt[(size_t)D_MODEL * D_MODEL];
__device__ __align__(256) __half g_Wvt[(size_t)D_MODEL * D_MODEL];
__device__ __align__(256) __half g_Wot[(size_t)D_MODEL * D_MODEL];
__device__ __align__(256) __half g_Q  [(size_t)M_TOTAL * D_MODEL];  // [B,H,T,Dh] d-perm
__device__ __align__(256) __half g_K  [(size_t)M_TOTAL * D_MODEL];  // [B,H,T,Dh] d-perm
__device__ __align__(256) __half g_Vt [(size_t)M_TOTAL * D_MODEL];  // [B,H,Dh,T] t-perm
__device__ __align__(256) __half g_Y  [(size_t)M_TOTAL * D_MODEL];  // [B,T,D] D-perm

// ---------------------------------------------------------------------------
// helpers
// ---------------------------------------------------------------------------
__device__ __forceinline__ unsigned f2h2(float lo, float hi) {
    __half2 h = __floats2half2_rn(lo, hi);
    return *(unsigned*)&h;
}
__device__ __forceinline__ unsigned short f2h(float v) {
    __half h = __float2half_rn(v);
    return *(unsigned short*)&h;
}

__device__ __forceinline__ void mma_f16(float c[4],
    unsigned a0, unsigned a1, unsigned a2, unsigned a3,
    unsigned b0, unsigned b1)
{
    asm volatile(
        "mma.sync.aligned.m16n8k16.row.col.f32.f16.f16.f32 "
        "{%0,%1,%2,%3}, {%4,%5,%6,%7}, {%8,%9}, {%0,%1,%2,%3};"
        : "+f"(c[0]), "+f"(c[1]), "+f"(c[2]), "+f"(c[3])
        : "r"(a0), "r"(a1), "r"(a2), "r"(a3), "r"(b0), "r"(b1));
}

__device__ __forceinline__ void cpa16(unsigned saddr, const void* gptr) {
    asm volatile("cp.async.cg.shared.global [%0], [%1], 16;"
                 :: "r"(saddr), "l"(gptr));
}

// ---------------------------------------------------------------------------
// fp32 -> fp16 + k-permute, fused over x + 4 weights (one launch).
// ---------------------------------------------------------------------------
#define XN4 (M_TOTAL * D_MODEL / 4)    // 2097152
#define WN4 (D_MODEL * D_MODEL / 4)    // 262144

__device__ __forceinline__ void cvt_one(const float4* __restrict__ src,
                                        unsigned* __restrict__ dst, int i)
{
    float4 v = src[i];
    int wi = i * 4;
    int h2 = ((wi & ~15) >> 1) + 2 * ((wi >> 1) & 3) + ((wi >> 3) & 1);
    dst[h2]     = f2h2(v.x, v.y);
    dst[h2 + 2] = f2h2(v.z, v.w);
}

__global__ void cvt_all_kernel(
    const float4* __restrict__ x,  unsigned* __restrict__ xt,
    const float4* __restrict__ w0, unsigned* __restrict__ t0,
    const float4* __restrict__ w1, unsigned* __restrict__ t1,
    const float4* __restrict__ w2, unsigned* __restrict__ t2,
    const float4* __restrict__ w3, unsigned* __restrict__ t3)
{
    int i = blockIdx.x * blockDim.x + threadIdx.x;
    if (i < XN4) { cvt_one(x, xt, i); return; }
    int j = i - XN4;
    int wsel = j >> 18;              // / WN4
    int r    = j & (WN4 - 1);
    if      (wsel == 0) cvt_one(w0, t0, r);
    else if (wsel == 1) cvt_one(w1, t1, r);
    else if (wsel == 2) cvt_one(w2, t2, r);
    else                cvt_one(w3, t3, r);
}

// ---------------------------------------------------------------------------
// GEMM: C = A[M,K] @ B[N,K]^T + bias (A,B fp16 k-permuted)
// BM=256, BN=128, BK=64; 512 threads = 16 warps (4m x 4n), warp tile 64x32.
// 3-stage cp.async; pitch 80 halves (conflict-free LDS.64 frags).
// ---------------------------------------------------------------------------
#define G_P   80
#define G_AH  (256 * G_P)
#define G_BH  (128 * G_P)
#define G_SH  (G_AH + G_BH)
#define G_SMEM (3 * G_SH * 2)          // 184320 B
#define G_ITERS (GK / 64)              // 16
#define G_THREADS 512

template <int MODE>
__global__ void __launch_bounds__(G_THREADS, 1) gemm_h_kernel(
    const __half* __restrict__ A,
    const __half* __restrict__ B0, const float* __restrict__ bias0, void* __restrict__ C0,
    const __half* __restrict__ B1, const float* __restrict__ bias1, void* __restrict__ C1,
    const __half* __restrict__ B2, const float* __restrict__ bias2, void* __restrict__ C2)
{
    extern __shared__ __align__(128) __half smh[];
    const int z = blockIdx.z;
    const __half* B    = (z == 0) ? B0    : (z == 1) ? B1    : B2;
    const float* bias  = (z == 0) ? bias0 : (z == 1) ? bias1 : bias2;
    void*        Cv    = (z == 0) ? C0    : (z == 1) ? C1    : C2;

    const int tid  = threadIdx.x;
    const int lane = tid & 31;
    const int w    = tid >> 5;
    const int wm   = w >> 2;
    const int wn   = w & 3;
    const int g    = lane >> 2;
    const int q    = lane & 3;
    const int bm   = blockIdx.y;
    const int bn   = blockIdx.x;

    const __half* Ab = A + (size_t)bm * 256 * GK;
    const __half* Bb = B + (size_t)bn * 128 * GK;
    const unsigned sb = (unsigned)__cvta_generic_to_shared(smh);

    float acc[4][4][4];
#pragma unroll
    for (int mt = 0; mt < 4; mt++)
#pragma unroll
        for (int nt = 0; nt < 4; nt++)
#pragma unroll
            for (int i = 0; i < 4; i++) acc[mt][nt][i] = 0.0f;

#define G_FILL(S, C)                                                         \
    {                                                                        \
        unsigned abase = sb + (unsigned)(S) * (G_SH * 2);                    \
        unsigned bbase = abase + (G_AH * 2);                                 \
        _Pragma("unroll")                                                    \
        for (int i = 0; i < 4; i++) {                                        \
            int idx = i * G_THREADS + tid;                                   \
            int r = idx >> 3, c8 = idx & 7;                                  \
            cpa16(abase + (unsigned)(r * G_P + c8 * 8) * 2u,                 \
                  Ab + (size_t)r * GK + (C) * 64 + c8 * 8);                  \
        }                                                                    \
        _Pragma("unroll")                                                    \
        for (int i = 0; i < 2; i++) {                                        \
            int idx = i * G_THREADS + tid;                                   \
            int r = idx >> 3, c8 = idx & 7;                                  \
            cpa16(bbase + (unsigned)(r * G_P + c8 * 8) * 2u,                 \
                  Bb + (size_t)r * GK + (C) * 64 + c8 * 8);                  \
        }                                                                    \
    }

    G_FILL(0, 0);
    asm volatile("cp.async.commit_group;" ::: "memory");
    G_FILL(1, 1);
    asm volatile("cp.async.commit_group;" ::: "memory");

    for (int it = 0; it < G_ITERS; it++) {
        asm volatile("cp.async.wait_group 1;" ::: "memory");
        __syncthreads();

        if (it + 2 < G_ITERS) {
            G_FILL((it + 2) % 3, it + 2);
        }
        asm volatile("cp.async.commit_group;" ::: "memory");

        const __half* As = smh + (it % 3) * G_SH;
        const __half* Bs = As + G_AH;

#pragma unroll
        for (int ks = 0; ks < 4; ks++) {
            uint2 af[4][2];
            uint2 bf[4];
#pragma unroll
            for (int mt = 0; mt < 4; mt++) {
                int r = wm * 64 + mt * 16 + g;
                af[mt][0] = *(const uint2*)(As + r * G_P + ks * 16 + 4 * q);
                af[mt][1] = *(const uint2*)(As + (r + 8) * G_P + ks * 16 + 4 * q);
            }
#pragma unroll
            for (int nt = 0; nt < 4; nt++) {
                int c = wn * 32 + nt * 8 + g;
                bf[nt] = *(const uint2*)(Bs + c * G_P + ks * 16 + 4 * q);
            }
#pragma unroll
            for (int mt = 0; mt < 4; mt++)
#pragma unroll
                for (int nt = 0; nt < 4; nt++)
                    mma_f16(acc[mt][nt],
                            af[mt][0].x, af[mt][1].x,
                            af[mt][0].y, af[mt][1].y,
                            bf[nt].x,    bf[nt].y);
        }
    }
#undef G_FILL

    // Epilogue
#pragma unroll
    for (int mt = 0; mt < 4; mt++) {
        int m0 = bm * 256 + wm * 64 + mt * 16 + g;
        int m1 = m0 + 8;
#pragma unroll
        for (int nt = 0; nt < 4; nt++) {
            int nb = wn * 32 + nt * 8;
            int n0 = bn * 128 + nb + 2 * q;
            float b0 = bias[n0], b1 = bias[n0 + 1];
            float v00 = acc[mt][nt][0] + b0;
            float v01 = acc[mt][nt][1] + b1;
            float v10 = acc[mt][nt][2] + b0;
            float v11 = acc[mt][nt][3] + b1;
            if (MODE == 1) {
                int h = (bn * 128 + nb) >> 6;
                if (z != 2) {
                    __half* C = (__half*)Cv;
                    int slot = ((nb & 63) & ~15) + 4 * q + 2 * (nt & 1);
                    int bb0 = m0 / SEQ, t0 = m0 % SEQ;
                    int bb1 = m1 / SEQ, t1 = m1 % SEQ;
                    size_t r0o = (((size_t)(bb0 * N_HEADS + h) * SEQ) + t0) * HEAD_DIM;
                    size_t r1o = (((size_t)(bb1 * N_HEADS + h) * SEQ) + t1) * HEAD_DIM;
                    *(unsigned*)(C + r0o + slot) = f2h2(v00, v01);
                    *(unsigned*)(C + r1o + slot) = f2h2(v10, v11);
                } else {
                    __half* C = (__half*)Cv;
                    int d0 = (nb & 63) + 2 * q;
                    int bb0 = m0 / SEQ, t0 = m0 % SEQ;
                    int bb1 = m1 / SEQ, t1 = m1 % SEQ;
                    int t0p = (t0 & ~15) + 4 * (g >> 1) + (g & 1);
                    int t1p = (t1 & ~15) + 4 * (g >> 1) + 2 + (g & 1);
                    size_t base0 = ((size_t)(bb0 * N_HEADS + h) * HEAD_DIM + d0) * SEQ;
                    size_t base1 = ((size_t)(bb1 * N_HEADS + h) * HEAD_DIM + d0) * SEQ;
                    ((unsigned short*)C)[base0 + t0p]       = f2h(v00);
                    ((unsigned short*)C)[base0 + SEQ + t0p] = f2h(v01);
                    ((unsigned short*)C)[base1 + t1p]       = f2h(v10);
                    ((unsigned short*)C)[base1 + SEQ + t1p] = f2h(v11);
                }
            } else {
                float* C = (float*)Cv;
                float2 u0; u0.x = v00; u0.y = v01;
                *(float2*)&C[(size_t)m0 * GN + n0] = u0;
                float2 u1; u1.x = v10; u1.y = v11;
                *(float2*)&C[(size_t)m1 * GN + n0] = u1;
            }
        }
    }
}

// ---------------------------------------------------------------------------
// Flash attention (fp16 mma): CTA = 128 q-rows for one (b,h), 64-key tiles.
// Q/K d-permuted [B,H,T,Dh]; V transposed t-permuted [B,H,Dh,T].
// K/V staged via cp.async double buffer (latency hidden under prev tile).
// All smem pitches 80 halves -> conflict-free LDS.64 fragments.
// ---------------------------------------------------------------------------
#define AP 80
#define A_TILEH (64 * AP)               // 5120 halves per K or V tile
#define A_KS0 0
#define A_VS0 A_TILEH
#define A_KS1 (2 * A_TILEH)
#define A_VS1 (3 * A_TILEH)
#define A_QS  (4 * A_TILEH)             // 20480
#define A_PS  (A_QS + 128 * AP)         // 30720
#define ATTN_SMEM ((A_PS + 128 * AP) * 2)   // 81920 B

__global__ void __launch_bounds__(256, 2) attn_h_kernel(
    const __half* __restrict__ Q, const __half* __restrict__ K,
    const __half* __restrict__ Vt, __half* __restrict__ Y)
{
    extern __shared__ __half smha[];
    __half* Qs = smha + A_QS;
    __half* Ps = smha + A_PS;

    const int tid  = threadIdx.x;
    const int lane = tid & 31;
    const int w    = tid >> 5;
    const int g    = lane >> 2;
    const int q    = lane & 3;
    const int qt   = (int)gridDim.x - 1 - (int)blockIdx.x;
    const int bh   = blockIdx.y;
    const int q0   = qt * 128;

    const int r0  = w * 16 + g;
    const int r1  = r0 + 8;
    const int gr0 = q0 + r0;
    const int gr1 = q0 + r1;
    const int gw0 = q0 + w * 16;

    const unsigned sb = (unsigned)__cvta_generic_to_shared(smha);
    const __half* Kb = K  + (size_t)bh * SEQ * HEAD_DIM;
    const __half* Vb = Vt + (size_t)bh * HEAD_DIM * SEQ;

    // stage K/V tile for key block K0 into buffer S (4 chunks/thread)
#define A_FILL(S, K0)                                                        \
    {                                                                        \
        unsigned kba = sb + (unsigned)((S) ? A_KS1 : A_KS0) * 2u;            \
        unsigned vba = sb + (unsigned)((S) ? A_VS1 : A_VS0) * 2u;            \
        _Pragma("unroll")                                                    \
        for (int i = 0; i < 2; i++) {                                        \
            int idx = i * 256 + tid;                                         \
            int row = idx >> 3, c8 = idx & 7;                                \
            cpa16(kba + (unsigned)(row * AP + c8 * 8) * 2u,                  \
                  Kb + ((size_t)(K0) + row) * HEAD_DIM + c8 * 8);            \
            cpa16(vba + (unsigned)(row * AP + c8 * 8) * 2u,                  \
                  Vb + (size_t)row * SEQ + (K0) + c8 * 8);                   \
        }                                                                    \
    }

    {   // Q: 128 rows x 8 chunks of 8 halves
        const __half* Qp = Q + ((size_t)bh * SEQ + q0) * HEAD_DIM;
#pragma unroll
        for (int i = 0; i < 4; i++) {
            int idx = i * 256 + tid;
            int row = idx >> 3, c8 = idx & 7;
            *(uint4*)(Qs + row * AP + c8 * 8) =
                *(const uint4*)(Qp + row * HEAD_DIM + c8 * 8);
        }
    }

    float o[8][4];
#pragma unroll
    for (int nt = 0; nt < 8; nt++)
#pragma unroll
        for (int i = 0; i < 4; i++) o[nt][i] = 0.0f;
    float m0 = -1e30f, m1 = -1e30f, l0 = 0.0f, l1 = 0.0f;

    const int kt_max = 2 * qt + 2;

    A_FILL(0, 0);
    asm volatile("cp.async.commit_group;" ::: "memory");

    for (int kt = 0; kt < kt_max; kt++) {
        const int buf = kt & 1;
        if (kt + 1 < kt_max) {
            A_FILL(buf ^ 1, (kt + 1) * 64);
        }
        asm volatile("cp.async.commit_group;" ::: "memory");
        asm volatile("cp.async.wait_group 1;" ::: "memory");
        __syncthreads();   // tile kt visible to all warps

        const __half* Ks = smha + (buf ? A_KS1 : A_KS0);
        const __half* Vs = smha + (buf ? A_VS1 : A_VS0);
        const int k0 = kt * 64;

        if (k0 <= gw0 + 15) {
            // ---- S = Q @ K^T  (16 rows x 64 keys; 4 k16-steps)
            float sc[8][4];
#pragma unroll
            for (int nt = 0; nt < 8; nt++)
#pragma unroll
                for (int i = 0; i < 4; i++) sc[nt][i] = 0.0f;

#pragma unroll
            for (int ks = 0; ks < 4; ks++) {
                uint2 a0 = *(const uint2*)(Qs + r0 * AP + ks * 16 + 4 * q);
                uint2 a1 = *(const uint2*)(Qs + r1 * AP + ks * 16 + 4 * q);
#pragma unroll
                for (int nt = 0; nt < 8; nt++) {
                    uint2 b = *(const uint2*)(Ks + (nt * 8 + g) * AP + ks * 16 + 4 * q);
                    mma_f16(sc[nt], a0.x, a1.x, a0.y, a1.y, b.x, b.y);
                }
            }

            const bool need_mask = (k0 + 63 > gr0 - g);
#pragma unroll
            for (int nt = 0; nt < 8; nt++) {
                int ck = k0 + nt * 8 + 2 * q;
                sc[nt][0] *= 0.125f; sc[nt][1] *= 0.125f;
                sc[nt][2] *= 0.125f; sc[nt][3] *= 0.125f;
                if (need_mask) {
                    if (ck     > gr0) sc[nt][0] = -1e30f;
                    if (ck + 1 > gr0) sc[nt][1] = -1e30f;
                    if (ck     > gr1) sc[nt][2] = -1e30f;
                    if (ck + 1 > gr1) sc[nt][3] = -1e30f;
                }
            }

            // ---- warp-local online softmax
            float rm0 = -1e30f, rm1 = -1e30f;
#pragma unroll
            for (int nt = 0; nt < 8; nt++) {
                rm0 = fmaxf(rm0, fmaxf(sc[nt][0], sc[nt][1]));
                rm1 = fmaxf(rm1, fmaxf(sc[nt][2], sc[nt][3]));
            }
            rm0 = fmaxf(rm0, __shfl_xor_sync(0xffffffffu, rm0, 1));
            rm0 = fmaxf(rm0, __shfl_xor_sync(0xffffffffu, rm0, 2));
            rm1 = fmaxf(rm1, __shfl_xor_sync(0xffffffffu, rm1, 1));
            rm1 = fmaxf(rm1, __shfl_xor_sync(0xffffffffu, rm1, 2));

            float nm0 = fmaxf(m0, rm0);
            float nm1 = fmaxf(m1, rm1);
            float cr0 = __expf(m0 - nm0);
            float cr1 = __expf(m1 - nm1);

            float s0 = 0.0f, s1 = 0.0f;
#pragma unroll
            for (int nt = 0; nt < 8; nt++) {
                sc[nt][0] = __expf(sc[nt][0] - nm0);
                sc[nt][1] = __expf(sc[nt][1] - nm0);
                sc[nt][2] = __expf(sc[nt][2] - nm1);
                sc[nt][3] = __expf(sc[nt][3] - nm1);
                s0 += sc[nt][0] + sc[nt][1];
                s1 += sc[nt][2] + sc[nt][3];
            }
            s0 += __shfl_xor_sync(0xffffffffu, s0, 1);
            s0 += __shfl_xor_sync(0xffffffffu, s0, 2);
            s1 += __shfl_xor_sync(0xffffffffu, s1, 1);
            s1 += __shfl_xor_sync(0xffffffffu, s1, 2);

            l0 = l0 * cr0 + s0;
            l1 = l1 * cr1 + s1;
            m0 = nm0; m1 = nm1;

#pragma unroll
            for (int nt = 0; nt < 8; nt++) {
                o[nt][0] *= cr0; o[nt][1] *= cr0;
                o[nt][2] *= cr1; o[nt][3] *= cr1;
            }

            // ---- P -> per-warp smem, key-permuted (half2 stores)
#pragma unroll
            for (int nt = 0; nt < 8; nt++) {
                int slot = (nt >> 1) * 16 + 4 * q + 2 * (nt & 1);
                *(unsigned*)(Ps + r0 * AP + slot) = f2h2(sc[nt][0], sc[nt][1]);
                *(unsigned*)(Ps + r1 * AP + slot) = f2h2(sc[nt][2], sc[nt][3]);
            }
            __syncwarp();

            // ---- O += P @ V
#pragma unroll
            for (int ks = 0; ks < 4; ks++) {
                uint2 a0 = *(const uint2*)(Ps + r0 * AP + ks * 16 + 4 * q);
                uint2 a1 = *(const uint2*)(Ps + r1 * AP + ks * 16 + 4 * q);
#pragma unroll
                for (int nt = 0; nt < 8; nt++) {
                    uint2 b = *(const uint2*)(Vs + (nt * 8 + g) * AP + ks * 16 + 4 * q);
                    mma_f16(o[nt], a0.x, a1.x, a0.y, a1.y, b.x, b.y);
                }
            }
        }
        __syncthreads();   // all warps done with buf before it is refilled
    }

    // ---- epilogue: normalize; write Y fp16 D-permuted [B,T,D]
    const float inv0 = 1.0f / l0;
    const float inv1 = 1.0f / l1;
    const int b = bh >> 4;
    const int h = bh & 15;
    __half* y0 = Y + ((size_t)b * SEQ + gr0) * D_MODEL + h * HEAD_DIM;
    __half* y1 = Y + ((size_t)b * SEQ + gr1) * D_MODEL + h * HEAD_DIM;
#pragma unroll
    for (int nt = 0; nt < 8; nt++) {
        int slot = (nt >> 1) * 16 + 4 * q + 2 * (nt & 1);
        *(unsigned*)(y0 + slot) = f2h2(o[nt][0] * inv0, o[nt][1] * inv0);
        *(unsigned*)(y1 + slot) = f2h2(o[nt][2] * inv1, o[nt][3] * inv1);
    }
#undef A_FILL
}

// ---------------------------------------------------------------------------
// Launch
// ---------------------------------------------------------------------------
extern "C" void kernel_launch(void* const* d_in, const int* in_sizes, int n_in,
                              void* d_out, int out_size)
{
    const float* x  = (const float*)d_in[0];
    const float* Wq = (const float*)d_in[1];
    const float* bq = (const float*)d_in[2];
    const float* Wk = (const float*)d_in[3];
    const float* bk = (const float*)d_in[4];
    const float* Wv = (const float*)d_in[5];
    const float* bv = (const float*)d_in[6];
    const float* Wo = (const float*)d_in[7];
    const float* bo = (const float*)d_in[8];
    float* out = (float*)d_out;

    __half *xt, *Wqt, *Wkt, *Wvt, *Wot, *Qb, *Kb, *Vb, *Yb;
    cudaGetSymbolAddress((void**)&xt,  g_xt);
    cudaGetSymbolAddress((void**)&Wqt, g_Wqt);
    cudaGetSymbolAddress((void**)&Wkt, g_Wkt);
    cudaGetSymbolAddress((void**)&Wvt, g_Wvt);
    cudaGetSymbolAddress((void**)&Wot, g_Wot);
    cudaGetSymbolAddress((void**)&Qb,  g_Q);
    cudaGetSymbolAddress((void**)&Kb,  g_K);
    cudaGetSymbolAddress((void**)&Vb,  g_Vt);
    cudaGetSymbolAddress((void**)&Yb,  g_Y);

    static bool attr_set = false;
    if (!attr_set) {
        cudaFuncSetAttribute(gemm_h_kernel<1>,
                             cudaFuncAttributeMaxDynamicSharedMemorySize, G_SMEM);
        cudaFuncSetAttribute(gemm_h_kernel<0>,
                             cudaFuncAttributeMaxDynamicSharedMemorySize, G_SMEM);
        cudaFuncSetAttribute(attn_h_kernel,
                             cudaFuncAttributeMaxDynamicSharedMemorySize, ATTN_SMEM);
        attr_set = true;
    }

    // fp16 + k-permute pre-conversion: one fused launch
    const int TOT4 = XN4 + 4 * WN4;          // 3145728
    cvt_all_kernel<<<TOT4 / 256, 256>>>(
        (const float4*)x,  (unsigned*)xt,
        (const float4*)Wq, (unsigned*)Wqt,
        (const float4*)Wk, (unsigned*)Wkt,
        (const float4*)Wv, (unsigned*)Wvt,
        (const float4*)Wo, (unsigned*)Wot);

    // Fused QKV projections
    dim3 qkvgrid(GN / 128, M_TOTAL / 256, 3);   // (8, 32, 3)
    gemm_h_kernel<1><<<qkvgrid, G_THREADS, G_SMEM>>>(
        xt, Wqt, bq, Qb, Wkt, bk, Kb, Wvt, bv, Vb);

    dim3 agrid(SEQ / 128, BATCH * N_HEADS);     // (16, 64)
    attn_h_kernel<<<agrid, 256, ATTN_SMEM>>>(Qb, Kb, Vb, Yb);

    // Output projection
    dim3 ogrid(GN / 128, M_TOTAL / 256, 1);     // (8, 32)
    gemm_h_kernel<0><<<ogrid, G_THREADS, G_SMEM>>>(
        Yb, Wot, bo, out, Wot, bo, out, Wot, bo, out);
}

// round 10
// speedup vs baseline: 2.1050x; 1.0673x over previous
#include <cuda_runtime.h>
#include <cuda_fp16.h>
#include <math.h>

#define D_MODEL  1024
#define N_HEADS  16
#define HEAD_DIM 64
#define BATCH    4
#define SEQ      2048
#define M_TOTAL  (BATCH * SEQ)   // 8192
#define GK 1024
#define GN 1024

// ---------------------------------------------------------------------------
// Scratch (fp16; k-dims stored permuted per 16-group: j=8h+2q+e -> 4q+2h+e)
// ---------------------------------------------------------------------------
__device__ __align__(256) __half g_xt [(size_t)M_TOTAL * D_MODEL];
__device__ __align__(256) __half g_Wqt[(size_t)D_MODEL * D_MODEL];
__device__ __align__(256) __half g_Wkt[(size_t)D_MODEL * D_MODEL];
__device__ __align__(256) __half g_Wvt[(size_t)D_MODEL * D_MODEL];
__device__ __align__(256) __half g_Wot[(size_t)D_MODEL * D_MODEL];
__device__ __align__(256) __half g_Q  [(size_t)M_TOTAL * D_MODEL];  // [B,H,T,Dh] d-perm
__device__ __align__(256) __half g_K  [(size_t)M_TOTAL * D_MODEL];  // [B,H,T,Dh] d-perm
__device__ __align__(256) __half g_Vt [(size_t)M_TOTAL * D_MODEL];  // [B,H,Dh,T] t-perm
__device__ __align__(256) __half g_Y  [(size_t)M_TOTAL * D_MODEL];  // [B,T,D] D-perm

// ---------------------------------------------------------------------------
// helpers
// ---------------------------------------------------------------------------
__device__ __forceinline__ unsigned f2h2(float lo, float hi) {
    __half2 h = __floats2half2_rn(lo, hi);
    return *(unsigned*)&h;
}
__device__ __forceinline__ unsigned short f2h(float v) {
    __half h = __float2half_rn(v);
    return *(unsigned short*)&h;
}

__device__ __forceinline__ void mma_f16(float c[4],
    unsigned a0, unsigned a1, unsigned a2, unsigned a3,
    unsigned b0, unsigned b1)
{
    asm volatile(
        "mma.sync.aligned.m16n8k16.row.col.f32.f16.f16.f32 "
        "{%0,%1,%2,%3}, {%4,%5,%6,%7}, {%8,%9}, {%0,%1,%2,%3};"
        : "+f"(c[0]), "+f"(c[1]), "+f"(c[2]), "+f"(c[3])
        : "r"(a0), "r"(a1), "r"(a2), "r"(a3), "r"(b0), "r"(b1));
}

__device__ __forceinline__ void cpa16(unsigned saddr, const void* gptr) {
    asm volatile("cp.async.cg.shared.global [%0], [%1], 16;"
                 :: "r"(saddr), "l"(gptr));
}

// ---------------------------------------------------------------------------
// fp32 -> fp16 + k-permute, fused over x + 4 weights (one launch).
// ---------------------------------------------------------------------------
#define XN4 (M_TOTAL * D_MODEL / 4)    // 2097152
#define WN4 (D_MODEL * D_MODEL / 4)    // 262144

__device__ __forceinline__ void cvt_one(const float4* __restrict__ src,
                                        unsigned* __restrict__ dst, int i)
{
    float4 v = src[i];
    int wi = i * 4;
    int h2 = ((wi & ~15) >> 1) + 2 * ((wi >> 1) & 3) + ((wi >> 3) & 1);
    dst[h2]     = f2h2(v.x, v.y);
    dst[h2 + 2] = f2h2(v.z, v.w);
}

__global__ void cvt_all_kernel(
    const float4* __restrict__ x,  unsigned* __restrict__ xt,
    const float4* __restrict__ w0, unsigned* __restrict__ t0,
    const float4* __restrict__ w1, unsigned* __restrict__ t1,
    const float4* __restrict__ w2, unsigned* __restrict__ t2,
    const float4* __restrict__ w3, unsigned* __restrict__ t3)
{
    int i = blockIdx.x * blockDim.x + threadIdx.x;
    if (i < XN4) { cvt_one(x, xt, i); return; }
    int j = i - XN4;
    int wsel = j >> 18;
    int r    = j & (WN4 - 1);
    if      (wsel == 0) cvt_one(w0, t0, r);
    else if (wsel == 1) cvt_one(w1, t1, r);
    else if (wsel == 2) cvt_one(w2, t2, r);
    else                cvt_one(w3, t3, r);
}

// ---------------------------------------------------------------------------
// GEMM: C = A[M,K] @ B[N,K]^T + bias (A,B fp16 k-permuted)
// BM=128, BN=128, BK=64; 256 threads = 8 warps (2m x 4n), warp tile 64x32.
// 2-stage cp.async; 80 KB smem -> 2 CTAs/SM (bubble overlap across CTAs).
// ---------------------------------------------------------------------------
#define G_P   80
#define G_AH  (128 * G_P)              // 10240 halves
#define G_BH  (128 * G_P)              // 10240
#define G_SH  (G_AH + G_BH)            // 20480 halves = 40960 B / stage
#define G_SMEM (2 * G_SH * 2)          // 81920 B
#define G_ITERS (GK / 64)              // 16
#define G_THREADS 256

template <int MODE>
__global__ void __launch_bounds__(G_THREADS, 2) gemm_h_kernel(
    const __half* __restrict__ A,
    const __half* __restrict__ B0, const float* __restrict__ bias0, void* __restrict__ C0,
    const __half* __restrict__ B1, const float* __restrict__ bias1, void* __restrict__ C1,
    const __half* __restrict__ B2, const float* __restrict__ bias2, void* __restrict__ C2)
{
    extern __shared__ __align__(128) __half smh[];
    const int z = blockIdx.z;
    const __half* B    = (z == 0) ? B0    : (z == 1) ? B1    : B2;
    const float* bias  = (z == 0) ? bias0 : (z == 1) ? bias1 : bias2;
    void*        Cv    = (z == 0) ? C0    : (z == 1) ? C1    : C2;

    const int tid  = threadIdx.x;
    const int lane = tid & 31;
    const int w    = tid >> 5;       // 0..7
    const int wm   = w >> 2;         // 0..1 (64-row slab)
    const int wn   = w & 3;          // 0..3 (32-col slab)
    const int g    = lane >> 2;
    const int q    = lane & 3;
    const int bm   = blockIdx.y;
    const int bn   = blockIdx.x;

    const __half* Ab = A + (size_t)bm * 128 * GK;
    const __half* Bb = B + (size_t)bn * 128 * GK;
    const unsigned sb = (unsigned)__cvta_generic_to_shared(smh);

    float acc[4][4][4];
#pragma unroll
    for (int mt = 0; mt < 4; mt++)
#pragma unroll
        for (int nt = 0; nt < 4; nt++)
#pragma unroll
            for (int i = 0; i < 4; i++) acc[mt][nt][i] = 0.0f;

    // A: 128 rows x 8 chunks(16B) = 1024 = 4/thread; B same.
#define G_FILL(S, C)                                                         \
    {                                                                        \
        unsigned abase = sb + (unsigned)(S) * (G_SH * 2);                    \
        unsigned bbase = abase + (G_AH * 2);                                 \
        _Pragma("unroll")                                                    \
        for (int i = 0; i < 4; i++) {                                        \
            int idx = i * G_THREADS + tid;                                   \
            int r = idx >> 3, c8 = idx & 7;                                  \
            cpa16(abase + (unsigned)(r * G_P + c8 * 8) * 2u,                 \
                  Ab + (size_t)r * GK + (C) * 64 + c8 * 8);                  \
        }                                                                    \
        _Pragma("unroll")                                                    \
        for (int i = 0; i < 4; i++) {                                        \
            int idx = i * G_THREADS + tid;                                   \
            int r = idx >> 3, c8 = idx & 7;                                  \
            cpa16(bbase + (unsigned)(r * G_P + c8 * 8) * 2u,                 \
                  Bb + (size_t)r * GK + (C) * 64 + c8 * 8);                  \
        }                                                                    \
    }

    G_FILL(0, 0);
    asm volatile("cp.async.commit_group;" ::: "memory");

    for (int it = 0; it < G_ITERS; it++) {
        const int buf = it & 1;
        if (it + 1 < G_ITERS) {
            G_FILL(buf ^ 1, it + 1);
        }
        asm volatile("cp.async.commit_group;" ::: "memory");
        // FIFO completion: only the newest group may remain pending,
        // so fill(it) is guaranteed complete.
        asm volatile("cp.async.wait_group 1;" ::: "memory");
        __syncthreads();

        const __half* As = smh + buf * G_SH;
        const __half* Bs = As + G_AH;

#pragma unroll
        for (int ks = 0; ks < 4; ks++) {
            uint2 af[4][2];
            uint2 bf[4];
#pragma unroll
            for (int mt = 0; mt < 4; mt++) {
                int r = wm * 64 + mt * 16 + g;
                af[mt][0] = *(const uint2*)(As + r * G_P + ks * 16 + 4 * q);
                af[mt][1] = *(const uint2*)(As + (r + 8) * G_P + ks * 16 + 4 * q);
            }
#pragma unroll
            for (int nt = 0; nt < 4; nt++) {
                int c = wn * 32 + nt * 8 + g;
                bf[nt] = *(const uint2*)(Bs + c * G_P + ks * 16 + 4 * q);
            }
#pragma unroll
            for (int mt = 0; mt < 4; mt++)
#pragma unroll
                for (int nt = 0; nt < 4; nt++)
                    mma_f16(acc[mt][nt],
                            af[mt][0].x, af[mt][1].x,
                            af[mt][0].y, af[mt][1].y,
                            bf[nt].x,    bf[nt].y);
        }
        __syncthreads();   // buf free for refill next iter
    }
#undef G_FILL

    // Epilogue
#pragma unroll
    for (int mt = 0; mt < 4; mt++) {
        int m0 = bm * 128 + wm * 64 + mt * 16 + g;
        int m1 = m0 + 8;
#pragma unroll
        for (int nt = 0; nt < 4; nt++) {
            int nb = wn * 32 + nt * 8;
            int n0 = bn * 128 + nb + 2 * q;
            float b0 = bias[n0], b1 = bias[n0 + 1];
            float v00 = acc[mt][nt][0] + b0;
            float v01 = acc[mt][nt][1] + b1;
            float v10 = acc[mt][nt][2] + b0;
            float v11 = acc[mt][nt][3] + b1;
            if (MODE == 1) {
                int h = (bn * 128 + nb) >> 6;
                if (z != 2) {
                    __half* C = (__half*)Cv;
                    int slot = ((nb & 63) & ~15) + 4 * q + 2 * (nt & 1);
                    int bb0 = m0 / SEQ, t0 = m0 % SEQ;
                    int bb1 = m1 / SEQ, t1 = m1 % SEQ;
                    size_t r0o = (((size_t)(bb0 * N_HEADS + h) * SEQ) + t0) * HEAD_DIM;
                    size_t r1o = (((size_t)(bb1 * N_HEADS + h) * SEQ) + t1) * HEAD_DIM;
                    *(unsigned*)(C + r0o + slot) = f2h2(v00, v01);
                    *(unsigned*)(C + r1o + slot) = f2h2(v10, v11);
                } else {
                    __half* C = (__half*)Cv;
                    int d0 = (nb & 63) + 2 * q;
                    int bb0 = m0 / SEQ, t0 = m0 % SEQ;
                    int bb1 = m1 / SEQ, t1 = m1 % SEQ;
                    int t0p = (t0 & ~15) + 4 * (g >> 1) + (g & 1);
                    int t1p = (t1 & ~15) + 4 * (g >> 1) + 2 + (g & 1);
                    size_t base0 = ((size_t)(bb0 * N_HEADS + h) * HEAD_DIM + d0) * SEQ;
                    size_t base1 = ((size_t)(bb1 * N_HEADS + h) * HEAD_DIM + d0) * SEQ;
                    ((unsigned short*)C)[base0 + t0p]       = f2h(v00);
                    ((unsigned short*)C)[base0 + SEQ + t0p] = f2h(v01);
                    ((unsigned short*)C)[base1 + t1p]       = f2h(v10);
                    ((unsigned short*)C)[base1 + SEQ + t1p] = f2h(v11);
                }
            } else {
                float* C = (float*)Cv;
                float2 u0; u0.x = v00; u0.y = v01;
                *(float2*)&C[(size_t)m0 * GN + n0] = u0;
                float2 u1; u1.x = v10; u1.y = v11;
                *(float2*)&C[(size_t)m1 * GN + n0] = u1;
            }
        }
    }
}

// ---------------------------------------------------------------------------
// Flash attention (fp16 mma): CTA = 128 q-rows for one (b,h), 64-key tiles.
// K/V staged via cp.async double buffer. Pitch 80 -> conflict-free LDS.64.
// ---------------------------------------------------------------------------
#define AP 80
#define A_TILEH (64 * AP)
#define A_KS0 0
#define A_VS0 A_TILEH
#define A_KS1 (2 * A_TILEH)
#define A_VS1 (3 * A_TILEH)
#define A_QS  (4 * A_TILEH)
#define A_PS  (A_QS + 128 * AP)
#define ATTN_SMEM ((A_PS + 128 * AP) * 2)   // 81920 B

__global__ void __launch_bounds__(256, 2) attn_h_kernel(
    const __half* __restrict__ Q, const __half* __restrict__ K,
    const __half* __restrict__ Vt, __half* __restrict__ Y)
{
    extern __shared__ __half smha[];
    __half* Qs = smha + A_QS;
    __half* Ps = smha + A_PS;

    const int tid  = threadIdx.x;
    const int lane = tid & 31;
    const int w    = tid >> 5;
    const int g    = lane >> 2;
    const int q    = lane & 3;
    const int qt   = (int)gridDim.x - 1 - (int)blockIdx.x;
    const int bh   = blockIdx.y;
    const int q0   = qt * 128;

    const int r0  = w * 16 + g;
    const int r1  = r0 + 8;
    const int gr0 = q0 + r0;
    const int gr1 = q0 + r1;
    const int gw0 = q0 + w * 16;

    const unsigned sb = (unsigned)__cvta_generic_to_shared(smha);
    const __half* Kb = K  + (size_t)bh * SEQ * HEAD_DIM;
    const __half* Vb = Vt + (size_t)bh * HEAD_DIM * SEQ;

#define A_FILL(S, K0)                                                        \
    {                                                                        \
        unsigned kba = sb + (unsigned)((S) ? A_KS1 : A_KS0) * 2u;            \
        unsigned vba = sb + (unsigned)((S) ? A_VS1 : A_VS0) * 2u;            \
        _Pragma("unroll")                                                    \
        for (int i = 0; i < 2; i++) {                                        \
            int idx = i * 256 + tid;                                         \
            int row = idx >> 3, c8 = idx & 7;                                \
            cpa16(kba + (unsigned)(row * AP + c8 * 8) * 2u,                  \
                  Kb + ((size_t)(K0) + row) * HEAD_DIM + c8 * 8);            \
            cpa16(vba + (unsigned)(row * AP + c8 * 8) * 2u,                  \
                  Vb + (size_t)row * SEQ + (K0) + c8 * 8);                   \
        }                                                                    \
    }

    {
        const __half* Qp = Q + ((size_t)bh * SEQ + q0) * HEAD_DIM;
#pragma unroll
        for (int i = 0; i < 4; i++) {
            int idx = i * 256 + tid;
            int row = idx >> 3, c8 = idx & 7;
            *(uint4*)(Qs + row * AP + c8 * 8) =
                *(const uint4*)(Qp + row * HEAD_DIM + c8 * 8);
        }
    }

    float o[8][4];
#pragma unroll
    for (int nt = 0; nt < 8; nt++)
#pragma unroll
        for (int i = 0; i < 4; i++) o[nt][i] = 0.0f;
    float m0 = -1e30f, m1 = -1e30f, l0 = 0.0f, l1 = 0.0f;

    const int kt_max = 2 * qt + 2;

    A_FILL(0, 0);
    asm volatile("cp.async.commit_group;" ::: "memory");

    for (int kt = 0; kt < kt_max; kt++) {
        const int buf = kt & 1;
        if (kt + 1 < kt_max) {
            A_FILL(buf ^ 1, (kt + 1) * 64);
        }
        asm volatile("cp.async.commit_group;" ::: "memory");
        asm volatile("cp.async.wait_group 1;" ::: "memory");
        __syncthreads();

        const __half* Ks = smha + (buf ? A_KS1 : A_KS0);
        const __half* Vs = smha + (buf ? A_VS1 : A_VS0);
        const int k0 = kt * 64;

        if (k0 <= gw0 + 15) {
            float sc[8][4];
#pragma unroll
            for (int nt = 0; nt < 8; nt++)
#pragma unroll
                for (int i = 0; i < 4; i++) sc[nt][i] = 0.0f;

#pragma unroll
            for (int ks = 0; ks < 4; ks++) {
                uint2 a0 = *(const uint2*)(Qs + r0 * AP + ks * 16 + 4 * q);
                uint2 a1 = *(const uint2*)(Qs + r1 * AP + ks * 16 + 4 * q);
#pragma unroll
                for (int nt = 0; nt < 8; nt++) {
                    uint2 b = *(const uint2*)(Ks + (nt * 8 + g) * AP + ks * 16 + 4 * q);
                    mma_f16(sc[nt], a0.x, a1.x, a0.y, a1.y, b.x, b.y);
                }
            }

            const bool need_mask = (k0 + 63 > gr0 - g);
#pragma unroll
            for (int nt = 0; nt < 8; nt++) {
                int ck = k0 + nt * 8 + 2 * q;
                sc[nt][0] *= 0.125f; sc[nt][1] *= 0.125f;
                sc[nt][2] *= 0.125f; sc[nt][3] *= 0.125f;
                if (need_mask) {
                    if (ck     > gr0) sc[nt][0] = -1e30f;
                    if (ck + 1 > gr0) sc[nt][1] = -1e30f;
                    if (ck     > gr1) sc[nt][2] = -1e30f;
                    if (ck + 1 > gr1) sc[nt][3] = -1e30f;
                }
            }

            float rm0 = -1e30f, rm1 = -1e30f;
#pragma unroll
            for (int nt = 0; nt < 8; nt++) {
                rm0 = fmaxf(rm0, fmaxf(sc[nt][0], sc[nt][1]));
                rm1 = fmaxf(rm1, fmaxf(sc[nt][2], sc[nt][3]));
            }
            rm0 = fmaxf(rm0, __shfl_xor_sync(0xffffffffu, rm0, 1));
            rm0 = fmaxf(rm0, __shfl_xor_sync(0xffffffffu, rm0, 2));
            rm1 = fmaxf(rm1, __shfl_xor_sync(0xffffffffu, rm1, 1));
            rm1 = fmaxf(rm1, __shfl_xor_sync(0xffffffffu, rm1, 2));

            float nm0 = fmaxf(m0, rm0);
            float nm1 = fmaxf(m1, rm1);
            float cr0 = __expf(m0 - nm0);
            float cr1 = __expf(m1 - nm1);

            float s0 = 0.0f, s1 = 0.0f;
#pragma unroll
            for (int nt = 0; nt < 8; nt++) {
                sc[nt][0] = __expf(sc[nt][0] - nm0);
                sc[nt][1] = __expf(sc[nt][1] - nm0);
                sc[nt][2] = __expf(sc[nt][2] - nm1);
                sc[nt][3] = __expf(sc[nt][3] - nm1);
                s0 += sc[nt][0] + sc[nt][1];
                s1 += sc[nt][2] + sc[nt][3];
            }
            s0 += __shfl_xor_sync(0xffffffffu, s0, 1);
            s0 += __shfl_xor_sync(0xffffffffu, s0, 2);
            s1 += __shfl_xor_sync(0xffffffffu, s1, 1);
            s1 += __shfl_xor_sync(0xffffffffu, s1, 2);

            l0 = l0 * cr0 + s0;
            l1 = l1 * cr1 + s1;
            m0 = nm0; m1 = nm1;

#pragma unroll
            for (int nt = 0; nt < 8; nt++) {
                o[nt][0] *= cr0; o[nt][1] *= cr0;
                o[nt][2] *= cr1; o[nt][3] *= cr1;
            }

#pragma unroll
            for (int nt = 0; nt < 8; nt++) {
                int slot = (nt >> 1) * 16 + 4 * q + 2 * (nt & 1);
                *(unsigned*)(Ps + r0 * AP + slot) = f2h2(sc[nt][0], sc[nt][1]);
                *(unsigned*)(Ps + r1 * AP + slot) = f2h2(sc[nt][2], sc[nt][3]);
            }
            __syncwarp();

#pragma unroll
            for (int ks = 0; ks < 4; ks++) {
                uint2 a0 = *(const uint2*)(Ps + r0 * AP + ks * 16 + 4 * q);
                uint2 a1 = *(const uint2*)(Ps + r1 * AP + ks * 16 + 4 * q);
#pragma unroll
                for (int nt = 0; nt < 8; nt++) {
                    uint2 b = *(const uint2*)(Vs + (nt * 8 + g) * AP + ks * 16 + 4 * q);
                    mma_f16(o[nt], a0.x, a1.x, a0.y, a1.y, b.x, b.y);
                }
            }
        }
        __syncthreads();
    }

    const float inv0 = 1.0f / l0;
    const float inv1 = 1.0f / l1;
    const int b = bh >> 4;
    const int h = bh & 15;
    __half* y0 = Y + ((size_t)b * SEQ + gr0) * D_MODEL + h * HEAD_DIM;
    __half* y1 = Y + ((size_t)b * SEQ + gr1) * D_MODEL + h * HEAD_DIM;
#pragma unroll
    for (int nt = 0; nt < 8; nt++) {
        int slot = (nt >> 1) * 16 + 4 * q + 2 * (nt & 1);
        *(unsigned*)(y0 + slot) = f2h2(o[nt][0] * inv0, o[nt][1] * inv0);
        *(unsigned*)(y1 + slot) = f2h2(o[nt][2] * inv1, o[nt][3] * inv1);
    }
#undef A_FILL
}

// ---------------------------------------------------------------------------
// Launch
// ---------------------------------------------------------------------------
extern "C" void kernel_launch(void* const* d_in, const int* in_sizes, int n_in,
                              void* d_out, int out_size)
{
    const float* x  = (const float*)d_in[0];
    const float* Wq = (const float*)d_in[1];
    const float* bq = (const float*)d_in[2];
    const float* Wk = (const float*)d_in[3];
    const float* bk = (const float*)d_in[4];
    const float* Wv = (const float*)d_in[5];
    const float* bv = (const float*)d_in[6];
    const float* Wo = (const float*)d_in[7];
    const float* bo = (const float*)d_in[8];
    float* out = (float*)d_out;

    __half *xt, *Wqt, *Wkt, *Wvt, *Wot, *Qb, *Kb, *Vb, *Yb;
    cudaGetSymbolAddress((void**)&xt,  g_xt);
    cudaGetSymbolAddress((void**)&Wqt, g_Wqt);
    cudaGetSymbolAddress((void**)&Wkt, g_Wkt);
    cudaGetSymbolAddress((void**)&Wvt, g_Wvt);
    cudaGetSymbolAddress((void**)&Wot, g_Wot);
    cudaGetSymbolAddress((void**)&Qb,  g_Q);
    cudaGetSymbolAddress((void**)&Kb,  g_K);
    cudaGetSymbolAddress((void**)&Vb,  g_Vt);
    cudaGetSymbolAddress((void**)&Yb,  g_Y);

    static bool attr_set = false;
    if (!attr_set) {
        cudaFuncSetAttribute(gemm_h_kernel<1>,
                             cudaFuncAttributeMaxDynamicSharedMemorySize, G_SMEM);
        cudaFuncSetAttribute(gemm_h_kernel<0>,
                             cudaFuncAttributeMaxDynamicSharedMemorySize, G_SMEM);
        cudaFuncSetAttribute(attn_h_kernel,
                             cudaFuncAttributeMaxDynamicSharedMemorySize, ATTN_SMEM);
        attr_set = true;
    }

    // fp16 + k-permute pre-conversion: one fused launch
    const int TOT4 = XN4 + 4 * WN4;
    cvt_all_kernel<<<TOT4 / 256, 256>>>(
        (const float4*)x,  (unsigned*)xt,
        (const float4*)Wq, (unsigned*)Wqt,
        (const float4*)Wk, (unsigned*)Wkt,
        (const float4*)Wv, (unsigned*)Wvt,
        (const float4*)Wo, (unsigned*)Wot);

    // Fused QKV projections
    dim3 qkvgrid(GN / 128, M_TOTAL / 128, 3);   // (8, 64, 3)
    gemm_h_kernel<1><<<qkvgrid, G_THREADS, G_SMEM>>>(
        xt, Wqt, bq, Qb, Wkt, bk, Kb, Wvt, bv, Vb);

    dim3 agrid(SEQ / 128, BATCH * N_HEADS);     // (16, 64)
    attn_h_kernel<<<agrid, 256, ATTN_SMEM>>>(Qb, Kb, Vb, Yb);

    // Output projection
    dim3 ogrid(GN / 128, M_TOTAL / 128, 1);     // (8, 64)
    gemm_h_kernel<0><<<ogrid, G_THREADS, G_SMEM>>>(
        Yb, Wot, bo, out, Wot, bo, out, Wot, bo, out);
}

// round 11
// speedup vs baseline: 2.1342x; 1.0139x over previous
#include <cuda_runtime.h>
#include <cuda_fp16.h>
#include <math.h>

#define D_MODEL  1024
#define N_HEADS  16
#define HEAD_DIM 64
#define BATCH    4
#define SEQ      2048
#define M_TOTAL  (BATCH * SEQ)   // 8192
#define GK 1024
#define GN 1024

// ---------------------------------------------------------------------------
// Scratch (fp16; k-dims stored permuted per 16-group: j=8h+2q+e -> 4q+2h+e)
// ---------------------------------------------------------------------------
__device__ __align__(256) __half g_xt [(size_t)M_TOTAL * D_MODEL];
__device__ __align__(256) __half g_Wqt[(size_t)D_MODEL * D_MODEL];
__device__ __align__(256) __half g_Wkt[(size_t)D_MODEL * D_MODEL];
__device__ __align__(256) __half g_Wvt[(size_t)D_MODEL * D_MODEL];
__device__ __align__(256) __half g_Wot[(size_t)D_MODEL * D_MODEL];
__device__ __align__(256) __half g_Q  [(size_t)M_TOTAL * D_MODEL];  // [B,H,T,Dh] d-perm
__device__ __align__(256) __half g_K  [(size_t)M_TOTAL * D_MODEL];  // [B,H,T,Dh] d-perm
__device__ __align__(256) __half g_Vt [(size_t)M_TOTAL * D_MODEL];  // [B,H,Dh,T] t-perm
__device__ __align__(256) __half g_Y  [(size_t)M_TOTAL * D_MODEL];  // [B,T,D] D-perm

// ---------------------------------------------------------------------------
// helpers
// ---------------------------------------------------------------------------
__device__ __forceinline__ unsigned f2h2(float lo, float hi) {
    __half2 h = __floats2half2_rn(lo, hi);
    return *(unsigned*)&h;
}
__device__ __forceinline__ unsigned short f2h(float v) {
    __half h = __float2half_rn(v);
    return *(unsigned short*)&h;
}

__device__ __forceinline__ void mma_f16(float c[4],
    unsigned a0, unsigned a1, unsigned a2, unsigned a3,
    unsigned b0, unsigned b1)
{
    asm volatile(
        "mma.sync.aligned.m16n8k16.row.col.f32.f16.f16.f32 "
        "{%0,%1,%2,%3}, {%4,%5,%6,%7}, {%8,%9}, {%0,%1,%2,%3};"
        : "+f"(c[0]), "+f"(c[1]), "+f"(c[2]), "+f"(c[3])
        : "r"(a0), "r"(a1), "r"(a2), "r"(a3), "r"(b0), "r"(b1));
}

__device__ __forceinline__ void cpa16(unsigned saddr, const void* gptr) {
    asm volatile("cp.async.cg.shared.global [%0], [%1], 16;"
                 :: "r"(saddr), "l"(gptr));
}

// ---------------------------------------------------------------------------
// fp32 -> fp16 + k-permute, fused over x + 4 weights (one launch).
// ---------------------------------------------------------------------------
#define XN4 (M_TOTAL * D_MODEL / 4)    // 2097152
#define WN4 (D_MODEL * D_MODEL / 4)    // 262144

__device__ __forceinline__ void cvt_one(const float4* __restrict__ src,
                                        unsigned* __restrict__ dst, int i)
{
    float4 v = src[i];
    int wi = i * 4;
    int h2 = ((wi & ~15) >> 1) + 2 * ((wi >> 1) & 3) + ((wi >> 3) & 1);
    dst[h2]     = f2h2(v.x, v.y);
    dst[h2 + 2] = f2h2(v.z, v.w);
}

__global__ void cvt_all_kernel(
    const float4* __restrict__ x,  unsigned* __restrict__ xt,
    const float4* __restrict__ w0, unsigned* __restrict__ t0,
    const float4* __restrict__ w1, unsigned* __restrict__ t1,
    const float4* __restrict__ w2, unsigned* __restrict__ t2,
    const float4* __restrict__ w3, unsigned* __restrict__ t3)
{
    int i = blockIdx.x * blockDim.x + threadIdx.x;
    if (i < XN4) { cvt_one(x, xt, i); return; }
    int j = i - XN4;
    int wsel = j >> 18;
    int r    = j & (WN4 - 1);
    if      (wsel == 0) cvt_one(w0, t0, r);
    else if (wsel == 1) cvt_one(w1, t1, r);
    else if (wsel == 2) cvt_one(w2, t2, r);
    else                cvt_one(w3, t3, r);
}

// ---------------------------------------------------------------------------
// QKV GEMM: BM=128, BN=64, BK=64; 128 threads = 4 warps (2m x 2n),
// warp tile 64x32. 2-stage cp.async; 61.4 KB smem -> 3 CTAs/SM.
// Fine tiles: 3072 CTAs / 444 concurrent = 6.92 -> 7 waves (1.2% tail).
// z selects (B,bias,C); z<2 -> [B,H,T,Dh] d-perm; z=2 -> [B,H,Dh,T] t-perm.
// ---------------------------------------------------------------------------
#define Q_P   80
#define Q_AH  (128 * Q_P)              // 10240 halves
#define Q_BH  (64 * Q_P)               // 5120
#define Q_SH  (Q_AH + Q_BH)            // 15360 halves = 30720 B / stage
#define Q_SMEM (2 * Q_SH * 2)          // 61440 B
#define Q_ITERS (GK / 64)              // 16
#define Q_THREADS 128

__global__ void __launch_bounds__(Q_THREADS, 3) gemm_qkv_kernel(
    const __half* __restrict__ A,
    const __half* __restrict__ B0, const float* __restrict__ bias0, __half* __restrict__ C0,
    const __half* __restrict__ B1, const float* __restrict__ bias1, __half* __restrict__ C1,
    const __half* __restrict__ B2, const float* __restrict__ bias2, __half* __restrict__ C2)
{
    extern __shared__ __align__(128) __half smh[];
    const int z = blockIdx.z;
    const __half* B    = (z == 0) ? B0    : (z == 1) ? B1    : B2;
    const float* bias  = (z == 0) ? bias0 : (z == 1) ? bias1 : bias2;
    __half*      C     = (z == 0) ? C0    : (z == 1) ? C1    : C2;

    const int tid  = threadIdx.x;
    const int lane = tid & 31;
    const int w    = tid >> 5;       // 0..3
    const int wm   = w >> 1;         // 0..1
    const int wn   = w & 1;          // 0..1
    const int g    = lane >> 2;
    const int q    = lane & 3;
    const int bm   = blockIdx.y;
    const int bn   = blockIdx.x;     // 0..15 == head index

    const __half* Ab = A + (size_t)bm * 128 * GK;
    const __half* Bb = B + (size_t)bn * 64 * GK;
    const unsigned sb = (unsigned)__cvta_generic_to_shared(smh);

    float acc[4][4][4];
#pragma unroll
    for (int mt = 0; mt < 4; mt++)
#pragma unroll
        for (int nt = 0; nt < 4; nt++)
#pragma unroll
            for (int i = 0; i < 4; i++) acc[mt][nt][i] = 0.0f;

    // A: 128 rows x 8 chunks = 1024 -> 8/thread; B: 64 x 8 = 512 -> 4/thread.
#define Q_FILL(S, KC)                                                        \
    {                                                                        \
        unsigned abase = sb + (unsigned)(S) * (Q_SH * 2);                    \
        unsigned bbase = abase + (Q_AH * 2);                                 \
        _Pragma("unroll")                                                    \
        for (int i = 0; i < 8; i++) {                                        \
            int idx = i * Q_THREADS + tid;                                   \
            int r = idx >> 3, c8 = idx & 7;                                  \
            cpa16(abase + (unsigned)(r * Q_P + c8 * 8) * 2u,                 \
                  Ab + (size_t)r * GK + (KC) * 64 + c8 * 8);                 \
        }                                                                    \
        _Pragma("unroll")                                                    \
        for (int i = 0; i < 4; i++) {                                        \
            int idx = i * Q_THREADS + tid;                                   \
            int r = idx >> 3, c8 = idx & 7;                                  \
            cpa16(bbase + (unsigned)(r * Q_P + c8 * 8) * 2u,                 \
                  Bb + (size_t)r * GK + (KC) * 64 + c8 * 8);                 \
        }                                                                    \
    }

    Q_FILL(0, 0);
    asm volatile("cp.async.commit_group;" ::: "memory");

    for (int it = 0; it < Q_ITERS; it++) {
        const int buf = it & 1;
        if (it + 1 < Q_ITERS) {
            Q_FILL(buf ^ 1, it + 1);
        }
        asm volatile("cp.async.commit_group;" ::: "memory");
        asm volatile("cp.async.wait_group 1;" ::: "memory");
        __syncthreads();

        const __half* As = smh + buf * Q_SH;
        const __half* Bs = As + Q_AH;

#pragma unroll
        for (int ks = 0; ks < 4; ks++) {
            uint2 af[4][2];
            uint2 bf[4];
#pragma unroll
            for (int mt = 0; mt < 4; mt++) {
                int r = wm * 64 + mt * 16 + g;
                af[mt][0] = *(const uint2*)(As + r * Q_P + ks * 16 + 4 * q);
                af[mt][1] = *(const uint2*)(As + (r + 8) * Q_P + ks * 16 + 4 * q);
            }
#pragma unroll
            for (int nt = 0; nt < 4; nt++) {
                int c = wn * 32 + nt * 8 + g;
                bf[nt] = *(const uint2*)(Bs + c * Q_P + ks * 16 + 4 * q);
            }
#pragma unroll
            for (int mt = 0; mt < 4; mt++)
#pragma unroll
                for (int nt = 0; nt < 4; nt++)
                    mma_f16(acc[mt][nt],
                            af[mt][0].x, af[mt][1].x,
                            af[mt][0].y, af[mt][1].y,
                            bf[nt].x,    bf[nt].y);
        }
        __syncthreads();
    }
#undef Q_FILL

    // Epilogue: head h == bn (BN=64 aligns to heads)
    const int h = bn;
#pragma unroll
    for (int mt = 0; mt < 4; mt++) {
        int m0 = bm * 128 + wm * 64 + mt * 16 + g;
        int m1 = m0 + 8;
        int bb0 = m0 / SEQ, t0 = m0 % SEQ;
        int bb1 = m1 / SEQ, t1 = m1 % SEQ;
#pragma unroll
        for (int nt = 0; nt < 4; nt++) {
            int nb = wn * 32 + nt * 8;       // 0..56 within head
            int n0 = bn * 64 + nb + 2 * q;
            float b0 = bias[n0], b1 = bias[n0 + 1];
            float v00 = acc[mt][nt][0] + b0;
            float v01 = acc[mt][nt][1] + b1;
            float v10 = acc[mt][nt][2] + b0;
            float v11 = acc[mt][nt][3] + b1;
            if (z != 2) {
                // Q/K: [B,H,T,Dh] d-permuted, half2 stores
                int slot = (nb & ~15) + 4 * q + 2 * (nt & 1);
                size_t r0o = (((size_t)(bb0 * N_HEADS + h) * SEQ) + t0) * HEAD_DIM;
                size_t r1o = (((size_t)(bb1 * N_HEADS + h) * SEQ) + t1) * HEAD_DIM;
                *(unsigned*)(C + r0o + slot) = f2h2(v00, v01);
                *(unsigned*)(C + r1o + slot) = f2h2(v10, v11);
            } else {
                // V: [B,H,Dh,T] t-permuted
                int d0 = nb + 2 * q;
                int t0p = (t0 & ~15) + 4 * (g >> 1) + (g & 1);
                int t1p = (t1 & ~15) + 4 * (g >> 1) + 2 + (g & 1);
                size_t base0 = ((size_t)(bb0 * N_HEADS + h) * HEAD_DIM + d0) * SEQ;
                size_t base1 = ((size_t)(bb1 * N_HEADS + h) * HEAD_DIM + d0) * SEQ;
                ((unsigned short*)C)[base0 + t0p]       = f2h(v00);
                ((unsigned short*)C)[base0 + SEQ + t0p] = f2h(v01);
                ((unsigned short*)C)[base1 + t1p]       = f2h(v10);
                ((unsigned short*)C)[base1 + SEQ + t1p] = f2h(v11);
            }
        }
    }
}

// ---------------------------------------------------------------------------
// O-proj GEMM: BM=128, BN=128, 256 threads = 8 warps (2m x 4n), 2-stage,
// 80 KB smem -> 2 CTAs/SM. fp32 [M,N] output. (Best packing for 512 tiles.)
// ---------------------------------------------------------------------------
#define G_P   80
#define G_AH  (128 * G_P)
#define G_BH  (128 * G_P)
#define G_SH  (G_AH + G_BH)
#define G_SMEM (2 * G_SH * 2)          // 81920 B
#define G_ITERS (GK / 64)
#define G_THREADS 256

__global__ void __launch_bounds__(G_THREADS, 2) gemm_o_kernel(
    const __half* __restrict__ A, const __half* __restrict__ B,
    const float* __restrict__ bias, float* __restrict__ C)
{
    extern __shared__ __align__(128) __half smh[];

    const int tid  = threadIdx.x;
    const int lane = tid & 31;
    const int w    = tid >> 5;
    const int wm   = w >> 2;
    const int wn   = w & 3;
    const int g    = lane >> 2;
    const int q    = lane & 3;
    const int bm   = blockIdx.y;
    const int bn   = blockIdx.x;

    const __half* Ab = A + (size_t)bm * 128 * GK;
    const __half* Bb = B + (size_t)bn * 128 * GK;
    const unsigned sb = (unsigned)__cvta_generic_to_shared(smh);

    float acc[4][4][4];
#pragma unroll
    for (int mt = 0; mt < 4; mt++)
#pragma unroll
        for (int nt = 0; nt < 4; nt++)
#pragma unroll
            for (int i = 0; i < 4; i++) acc[mt][nt][i] = 0.0f;

#define G_FILL(S, KC)                                                        \
    {                                                                        \
        unsigned abase = sb + (unsigned)(S) * (G_SH * 2);                    \
        unsigned bbase = abase + (G_AH * 2);                                 \
        _Pragma("unroll")                                                    \
        for (int i = 0; i < 4; i++) {                                        \
            int idx = i * G_THREADS + tid;                                   \
            int r = idx >> 3, c8 = idx & 7;                                  \
            cpa16(abase + (unsigned)(r * G_P + c8 * 8) * 2u,                 \
                  Ab + (size_t)r * GK + (KC) * 64 + c8 * 8);                 \
        }                                                                    \
        _Pragma("unroll")                                                    \
        for (int i = 0; i < 4; i++) {                                        \
            int idx = i * G_THREADS + tid;                                   \
            int r = idx >> 3, c8 = idx & 7;                                  \
            cpa16(bbase + (unsigned)(r * G_P + c8 * 8) * 2u,                 \
                  Bb + (size_t)r * GK + (KC) * 64 + c8 * 8);                 \
        }                                                                    \
    }

    G_FILL(0, 0);
    asm volatile("cp.async.commit_group;" ::: "memory");

    for (int it = 0; it < G_ITERS; it++) {
        const int buf = it & 1;
        if (it + 1 < G_ITERS) {
            G_FILL(buf ^ 1, it + 1);
        }
        asm volatile("cp.async.commit_group;" ::: "memory");
        asm volatile("cp.async.wait_group 1;" ::: "memory");
        __syncthreads();

        const __half* As = smh + buf * G_SH;
        const __half* Bs = As + G_AH;

#pragma unroll
        for (int ks = 0; ks < 4; ks++) {
            uint2 af[4][2];
            uint2 bf[4];
#pragma unroll
            for (int mt = 0; mt < 4; mt++) {
                int r = wm * 64 + mt * 16 + g;
                af[mt][0] = *(const uint2*)(As + r * G_P + ks * 16 + 4 * q);
                af[mt][1] = *(const uint2*)(As + (r + 8) * G_P + ks * 16 + 4 * q);
            }
#pragma unroll
            for (int nt = 0; nt < 4; nt++) {
                int c = wn * 32 + nt * 8 + g;
                bf[nt] = *(const uint2*)(Bs + c * G_P + ks * 16 + 4 * q);
            }
#pragma unroll
            for (int mt = 0; mt < 4; mt++)
#pragma unroll
                for (int nt = 0; nt < 4; nt++)
                    mma_f16(acc[mt][nt],
                            af[mt][0].x, af[mt][1].x,
                            af[mt][0].y, af[mt][1].y,
                            bf[nt].x,    bf[nt].y);
        }
        __syncthreads();
    }
#undef G_FILL

#pragma unroll
    for (int mt = 0; mt < 4; mt++) {
        int m0 = bm * 128 + wm * 64 + mt * 16 + g;
        int m1 = m0 + 8;
#pragma unroll
        for (int nt = 0; nt < 4; nt++) {
            int n0 = bn * 128 + wn * 32 + nt * 8 + 2 * q;
            float b0 = bias[n0], b1 = bias[n0 + 1];
            float2 u0; u0.x = acc[mt][nt][0] + b0; u0.y = acc[mt][nt][1] + b1;
            *(float2*)&C[(size_t)m0 * GN + n0] = u0;
            float2 u1; u1.x = acc[mt][nt][2] + b0; u1.y = acc[mt][nt][3] + b1;
            *(float2*)&C[(size_t)m1 * GN + n0] = u1;
        }
    }
}

// ---------------------------------------------------------------------------
// Flash attention (fp16 mma): CTA = 128 q-rows for one (b,h), 64-key tiles.
// K/V staged via cp.async double buffer. Pitch 80 -> conflict-free LDS.64.
// ---------------------------------------------------------------------------
#define AP 80
#define A_TILEH (64 * AP)
#define A_KS0 0
#define A_VS0 A_TILEH
#define A_KS1 (2 * A_TILEH)
#define A_VS1 (3 * A_TILEH)
#define A_QS  (4 * A_TILEH)
#define A_PS  (A_QS + 128 * AP)
#define ATTN_SMEM ((A_PS + 128 * AP) * 2)   // 81920 B

__global__ void __launch_bounds__(256, 2) attn_h_kernel(
    const __half* __restrict__ Q, const __half* __restrict__ K,
    const __half* __restrict__ Vt, __half* __restrict__ Y)
{
    extern __shared__ __half smha[];
    __half* Qs = smha + A_QS;
    __half* Ps = smha + A_PS;

    const int tid  = threadIdx.x;
    const int lane = tid & 31;
    const int w    = tid >> 5;
    const int g    = lane >> 2;
    const int q    = lane & 3;
    const int qt   = (int)gridDim.x - 1 - (int)blockIdx.x;
    const int bh   = blockIdx.y;
    const int q0   = qt * 128;

    const int r0  = w * 16 + g;
    const int r1  = r0 + 8;
    const int gr0 = q0 + r0;
    const int gr1 = q0 + r1;
    const int gw0 = q0 + w * 16;

    const unsigned sb = (unsigned)__cvta_generic_to_shared(smha);
    const __half* Kb = K  + (size_t)bh * SEQ * HEAD_DIM;
    const __half* Vb = Vt + (size_t)bh * HEAD_DIM * SEQ;

#define A_FILL(S, K0)                                                        \
    {                                                                        \
        unsigned kba = sb + (unsigned)((S) ? A_KS1 : A_KS0) * 2u;            \
        unsigned vba = sb + (unsigned)((S) ? A_VS1 : A_VS0) * 2u;            \
        _Pragma("unroll")                                                    \
        for (int i = 0; i < 2; i++) {                                        \
            int idx = i * 256 + tid;                                         \
            int row = idx >> 3, c8 = idx & 7;                                \
            cpa16(kba + (unsigned)(row * AP + c8 * 8) * 2u,                  \
                  Kb + ((size_t)(K0) + row) * HEAD_DIM + c8 * 8);            \
            cpa16(vba + (unsigned)(row * AP + c8 * 8) * 2u,                  \
                  Vb + (size_t)row * SEQ + (K0) + c8 * 8);                   \
        }                                                                    \
    }

    {
        const __half* Qp = Q + ((size_t)bh * SEQ + q0) * HEAD_DIM;
#pragma unroll
        for (int i = 0; i < 4; i++) {
            int idx = i * 256 + tid;
            int row = idx >> 3, c8 = idx & 7;
            *(uint4*)(Qs + row * AP + c8 * 8) =
                *(const uint4*)(Qp + row * HEAD_DIM + c8 * 8);
        }
    }

    float o[8][4];
#pragma unroll
    for (int nt = 0; nt < 8; nt++)
#pragma unroll
        for (int i = 0; i < 4; i++) o[nt][i] = 0.0f;
    float m0 = -1e30f, m1 = -1e30f, l0 = 0.0f, l1 = 0.0f;

    const int kt_max = 2 * qt + 2;

    A_FILL(0, 0);
    asm volatile("cp.async.commit_group;" ::: "memory");

    for (int kt = 0; kt < kt_max; kt++) {
        const int buf = kt & 1;
        if (kt + 1 < kt_max) {
            A_FILL(buf ^ 1, (kt + 1) * 64);
        }
        asm volatile("cp.async.commit_group;" ::: "memory");
        asm volatile("cp.async.wait_group 1;" ::: "memory");
        __syncthreads();

        const __half* Ks = smha + (buf ? A_KS1 : A_KS0);
        const __half* Vs = smha + (buf ? A_VS1 : A_VS0);
        const int k0 = kt * 64;

        if (k0 <= gw0 + 15) {
            float sc[8][4];
#pragma unroll
            for (int nt = 0; nt < 8; nt++)
#pragma unroll
                for (int i = 0; i < 4; i++) sc[nt][i] = 0.0f;

#pragma unroll
            for (int ks = 0; ks < 4; ks++) {
                uint2 a0 = *(const uint2*)(Qs + r0 * AP + ks * 16 + 4 * q);
                uint2 a1 = *(const uint2*)(Qs + r1 * AP + ks * 16 + 4 * q);
#pragma unroll
                for (int nt = 0; nt < 8; nt++) {
                    uint2 b = *(const uint2*)(Ks + (nt * 8 + g) * AP + ks * 16 + 4 * q);
                    mma_f16(sc[nt], a0.x, a1.x, a0.y, a1.y, b.x, b.y);
                }
            }

            const bool need_mask = (k0 + 63 > gr0 - g);
#pragma unroll
            for (int nt = 0; nt < 8; nt++) {
                int ck = k0 + nt * 8 + 2 * q;
                sc[nt][0] *= 0.125f; sc[nt][1] *= 0.125f;
                sc[nt][2] *= 0.125f; sc[nt][3] *= 0.125f;
                if (need_mask) {
                    if (ck     > gr0) sc[nt][0] = -1e30f;
                    if (ck + 1 > gr0) sc[nt][1] = -1e30f;
                    if (ck     > gr1) sc[nt][2] = -1e30f;
                    if (ck + 1 > gr1) sc[nt][3] = -1e30f;
                }
            }

            float rm0 = -1e30f, rm1 = -1e30f;
#pragma unroll
            for (int nt = 0; nt < 8; nt++) {
                rm0 = fmaxf(rm0, fmaxf(sc[nt][0], sc[nt][1]));
                rm1 = fmaxf(rm1, fmaxf(sc[nt][2], sc[nt][3]));
            }
            rm0 = fmaxf(rm0, __shfl_xor_sync(0xffffffffu, rm0, 1));
            rm0 = fmaxf(rm0, __shfl_xor_sync(0xffffffffu, rm0, 2));
            rm1 = fmaxf(rm1, __shfl_xor_sync(0xffffffffu, rm1, 1));
            rm1 = fmaxf(rm1, __shfl_xor_sync(0xffffffffu, rm1, 2));

            float nm0 = fmaxf(m0, rm0);
            float nm1 = fmaxf(m1, rm1);
            float cr0 = __expf(m0 - nm0);
            float cr1 = __expf(m1 - nm1);

            float s0 = 0.0f, s1 = 0.0f;
#pragma unroll
            for (int nt = 0; nt < 8; nt++) {
                sc[nt][0] = __expf(sc[nt][0] - nm0);
                sc[nt][1] = __expf(sc[nt][1] - nm0);
                sc[nt][2] = __expf(sc[nt][2] - nm1);
                sc[nt][3] = __expf(sc[nt][3] - nm1);
                s0 += sc[nt][0] + sc[nt][1];
                s1 += sc[nt][2] + sc[nt][3];
            }
            s0 += __shfl_xor_sync(0xffffffffu, s0, 1);
            s0 += __shfl_xor_sync(0xffffffffu, s0, 2);
            s1 += __shfl_xor_sync(0xffffffffu, s1, 1);
            s1 += __shfl_xor_sync(0xffffffffu, s1, 2);

            l0 = l0 * cr0 + s0;
            l1 = l1 * cr1 + s1;
            m0 = nm0; m1 = nm1;

#pragma unroll
            for (int nt = 0; nt < 8; nt++) {
                o[nt][0] *= cr0; o[nt][1] *= cr0;
                o[nt][2] *= cr1; o[nt][3] *= cr1;
            }

#pragma unroll
            for (int nt = 0; nt < 8; nt++) {
                int slot = (nt >> 1) * 16 + 4 * q + 2 * (nt & 1);
                *(unsigned*)(Ps + r0 * AP + slot) = f2h2(sc[nt][0], sc[nt][1]);
                *(unsigned*)(Ps + r1 * AP + slot) = f2h2(sc[nt][2], sc[nt][3]);
            }
            __syncwarp();

#pragma unroll
            for (int ks = 0; ks < 4; ks++) {
                uint2 a0 = *(const uint2*)(Ps + r0 * AP + ks * 16 + 4 * q);
                uint2 a1 = *(const uint2*)(Ps + r1 * AP + ks * 16 + 4 * q);
#pragma unroll
                for (int nt = 0; nt < 8; nt++) {
                    uint2 b = *(const uint2*)(Vs + (nt * 8 + g) * AP + ks * 16 + 4 * q);
                    mma_f16(o[nt], a0.x, a1.x, a0.y, a1.y, b.x, b.y);
                }
            }
        }
        __syncthreads();
    }

    const float inv0 = 1.0f / l0;
    const float inv1 = 1.0f / l1;
    const int b = bh >> 4;
    const int h = bh & 15;
    __half* y0 = Y + ((size_t)b * SEQ + gr0) * D_MODEL + h * HEAD_DIM;
    __half* y1 = Y + ((size_t)b * SEQ + gr1) * D_MODEL + h * HEAD_DIM;
#pragma unroll
    for (int nt = 0; nt < 8; nt++) {
        int slot = (nt >> 1) * 16 + 4 * q + 2 * (nt & 1);
        *(unsigned*)(y0 + slot) = f2h2(o[nt][0] * inv0, o[nt][1] * inv0);
        *(unsigned*)(y1 + slot) = f2h2(o[nt][2] * inv1, o[nt][3] * inv1);
    }
#undef A_FILL
}

// ---------------------------------------------------------------------------
// Launch
// ---------------------------------------------------------------------------
extern "C" void kernel_launch(void* const* d_in, const int* in_sizes, int n_in,
                              void* d_out, int out_size)
{
    const float* x  = (const float*)d_in[0];
    const float* Wq = (const float*)d_in[1];
    const float* bq = (const float*)d_in[2];
    const float* Wk = (const float*)d_in[3];
    const float* bk = (const float*)d_in[4];
    const float* Wv = (const float*)d_in[5];
    const float* bv = (const float*)d_in[6];
    const float* Wo = (const float*)d_in[7];
    const float* bo = (const float*)d_in[8];
    float* out = (float*)d_out;

    __half *xt, *Wqt, *Wkt, *Wvt, *Wot, *Qb, *Kb, *Vb, *Yb;
    cudaGetSymbolAddress((void**)&xt,  g_xt);
    cudaGetSymbolAddress((void**)&Wqt, g_Wqt);
    cudaGetSymbolAddress((void**)&Wkt, g_Wkt);
    cudaGetSymbolAddress((void**)&Wvt, g_Wvt);
    cudaGetSymbolAddress((void**)&Wot, g_Wot);
    cudaGetSymbolAddress((void**)&Qb,  g_Q);
    cudaGetSymbolAddress((void**)&Kb,  g_K);
    cudaGetSymbolAddress((void**)&Vb,  g_Vt);
    cudaGetSymbolAddress((void**)&Yb,  g_Y);

    static bool attr_set = false;
    if (!attr_set) {
        cudaFuncSetAttribute(gemm_qkv_kernel,
                             cudaFuncAttributeMaxDynamicSharedMemorySize, Q_SMEM);
        cudaFuncSetAttribute(gemm_o_kernel,
                             cudaFuncAttributeMaxDynamicSharedMemorySize, G_SMEM);
        cudaFuncSetAttribute(attn_h_kernel,
                             cudaFuncAttributeMaxDynamicSharedMemorySize, ATTN_SMEM);
        attr_set = true;
    }

    // fp16 + k-permute pre-conversion: one fused launch
    const int TOT4 = XN4 + 4 * WN4;
    cvt_all_kernel<<<TOT4 / 256, 256>>>(
        (const float4*)x,  (unsigned*)xt,
        (const float4*)Wq, (unsigned*)Wqt,
        (const float4*)Wk, (unsigned*)Wkt,
        (const float4*)Wv, (unsigned*)Wvt,
        (const float4*)Wo, (unsigned*)Wot);

    // Fused QKV projections: fine tiles, 3 CTAs/SM
    dim3 qkvgrid(GN / 64, M_TOTAL / 128, 3);    // (16, 64, 3) = 3072
    gemm_qkv_kernel<<<qkvgrid, Q_THREADS, Q_SMEM>>>(
        xt, Wqt, bq, Qb, Wkt, bk, Kb, Wvt, bv, Vb);

    dim3 agrid(SEQ / 128, BATCH * N_HEADS);     // (16, 64)
    attn_h_kernel<<<agrid, 256, ATTN_SMEM>>>(Qb, Kb, Vb, Yb);

    // Output projection
    dim3 ogrid(GN / 128, M_TOTAL / 128);        // (8, 64) = 512
    gemm_o_kernel<<<ogrid, G_THREADS, G_SMEM>>>(Yb, Wot, bo, out);
}

// round 13
// speedup vs baseline: 2.2203x; 1.0403x over previous
#include <cuda_runtime.h>
#include <cuda_fp16.h>
#include <math.h>

#define D_MODEL  1024
#define N_HEADS  16
#define HEAD_DIM 64
#define BATCH    4
#define SEQ      2048
#define M_TOTAL  (BATCH * SEQ)   // 8192
#define GK 1024
#define GN 1024

// ---------------------------------------------------------------------------
// Scratch (fp16; k-dims stored permuted per 16-group: j=8h+2q+e -> 4q+2h+e)
// Wq is pre-scaled by 0.125 (exact power of 2) so attention skips 1/sqrt(d).
// ---------------------------------------------------------------------------
__device__ __align__(256) __half g_xt [(size_t)M_TOTAL * D_MODEL];
__device__ __align__(256) __half g_Wqt[(size_t)D_MODEL * D_MODEL];
__device__ __align__(256) __half g_Wkt[(size_t)D_MODEL * D_MODEL];
__device__ __align__(256) __half g_Wvt[(size_t)D_MODEL * D_MODEL];
__device__ __align__(256) __half g_Wot[(size_t)D_MODEL * D_MODEL];
__device__ __align__(256) __half g_Q  [(size_t)M_TOTAL * D_MODEL];  // [B,H,T,Dh] d-perm (pre-scaled)
__device__ __align__(256) __half g_K  [(size_t)M_TOTAL * D_MODEL];  // [B,H,T,Dh] d-perm
__device__ __align__(256) __half g_Vt [(size_t)M_TOTAL * D_MODEL];  // [B,H,Dh,T] t-perm
__device__ __align__(256) __half g_Y  [(size_t)M_TOTAL * D_MODEL];  // [B,T,D] D-perm

// ---------------------------------------------------------------------------
// helpers
// ---------------------------------------------------------------------------
__device__ __forceinline__ unsigned f2h2(float lo, float hi) {
    __half2 h = __floats2half2_rn(lo, hi);
    return *(unsigned*)&h;
}
__device__ __forceinline__ unsigned short f2h(float v) {
    __half h = __float2half_rn(v);
    return *(unsigned short*)&h;
}

__device__ __forceinline__ void mma_f16(float c[4],
    unsigned a0, unsigned a1, unsigned a2, unsigned a3,
    unsigned b0, unsigned b1)
{
    asm volatile(
        "mma.sync.aligned.m16n8k16.row.col.f32.f16.f16.f32 "
        "{%0,%1,%2,%3}, {%4,%5,%6,%7}, {%8,%9}, {%0,%1,%2,%3};"
        : "+f"(c[0]), "+f"(c[1]), "+f"(c[2]), "+f"(c[3])
        : "r"(a0), "r"(a1), "r"(a2), "r"(a3), "r"(b0), "r"(b1));
}

__device__ __forceinline__ void cpa16(unsigned saddr, const void* gptr) {
    asm volatile("cp.async.cg.shared.global [%0], [%1], 16;"
                 :: "r"(saddr), "l"(gptr));
}

// ---------------------------------------------------------------------------
// fp32 -> fp16 + k-permute, fused over x + 4 weights (one launch).
// Wq gets scale 0.125 (exact).
// ---------------------------------------------------------------------------
#define XN4 (M_TOTAL * D_MODEL / 4)    // 2097152
#define WN4 (D_MODEL * D_MODEL / 4)    // 262144

__device__ __forceinline__ void cvt_one(const float4* __restrict__ src,
                                        unsigned* __restrict__ dst, int i, float s)
{
    float4 v = src[i];
    int wi = i * 4;
    int h2 = ((wi & ~15) >> 1) + 2 * ((wi >> 1) & 3) + ((wi >> 3) & 1);
    dst[h2]     = f2h2(v.x * s, v.y * s);
    dst[h2 + 2] = f2h2(v.z * s, v.w * s);
}

__global__ void cvt_all_kernel(
    const float4* __restrict__ x,  unsigned* __restrict__ xt,
    const float4* __restrict__ w0, unsigned* __restrict__ t0,
    const float4* __restrict__ w1, unsigned* __restrict__ t1,
    const float4* __restrict__ w2, unsigned* __restrict__ t2,
    const float4* __restrict__ w3, unsigned* __restrict__ t3)
{
    int i = blockIdx.x * blockDim.x + threadIdx.x;
    if (i < XN4) { cvt_one(x, xt, i, 1.0f); return; }
    int j = i - XN4;
    int wsel = j >> 18;
    int r    = j & (WN4 - 1);
    if      (wsel == 0) cvt_one(w0, t0, r, 0.125f);   // Wq pre-scaled
    else if (wsel == 1) cvt_one(w1, t1, r, 1.0f);
    else if (wsel == 2) cvt_one(w2, t2, r, 1.0f);
    else                cvt_one(w3, t3, r, 1.0f);
}

// ---------------------------------------------------------------------------
// QKV GEMM: BM=128, BN=64, BK=64; 128 threads = 4 warps (2m x 2n),
// warp tile 64x32. 2-stage cp.async; 61.4 KB smem -> 3 CTAs/SM.
// z selects (B,bias,C); z<2 -> [B,H,T,Dh] d-perm; z=2 -> [B,H,Dh,T] t-perm.
// z==0 (Q): bias scaled by 0.125 to match pre-scaled Wq.
// ---------------------------------------------------------------------------
#define Q_P   80
#define Q_AH  (128 * Q_P)
#define Q_BH  (64 * Q_P)
#define Q_SH  (Q_AH + Q_BH)
#define Q_SMEM (2 * Q_SH * 2)          // 61440 B
#define Q_ITERS (GK / 64)              // 16
#define Q_THREADS 128

__global__ void __launch_bounds__(Q_THREADS, 3) gemm_qkv_kernel(
    const __half* __restrict__ A,
    const __half* __restrict__ B0, const float* __restrict__ bias0, __half* __restrict__ C0,
    const __half* __restrict__ B1, const float* __restrict__ bias1, __half* __restrict__ C1,
    const __half* __restrict__ B2, const float* __restrict__ bias2, __half* __restrict__ C2)
{
    extern __shared__ __align__(128) __half smh[];
    const int z = blockIdx.z;
    const __half* B    = (z == 0) ? B0    : (z == 1) ? B1    : B2;
    const float* bias  = (z == 0) ? bias0 : (z == 1) ? bias1 : bias2;
    __half*      C     = (z == 0) ? C0    : (z == 1) ? C1    : C2;
    const float bscale = (z == 0) ? 0.125f : 1.0f;

    const int tid  = threadIdx.x;
    const int lane = tid & 31;
    const int w    = tid >> 5;
    const int wm   = w >> 1;
    const int wn   = w & 1;
    const int g    = lane >> 2;
    const int q    = lane & 3;
    const int bm   = blockIdx.y;
    const int bn   = blockIdx.x;     // head index

    const __half* Ab = A + (size_t)bm * 128 * GK;
    const __half* Bb = B + (size_t)bn * 64 * GK;
    const unsigned sb = (unsigned)__cvta_generic_to_shared(smh);

    float acc[4][4][4];
#pragma unroll
    for (int mt = 0; mt < 4; mt++)
#pragma unroll
        for (int nt = 0; nt < 4; nt++)
#pragma unroll
            for (int i = 0; i < 4; i++) acc[mt][nt][i] = 0.0f;

#define Q_FILL(S, KC)                                                        \
    {                                                                        \
        unsigned abase = sb + (unsigned)(S) * (Q_SH * 2);                    \
        unsigned bbase = abase + (Q_AH * 2);                                 \
        _Pragma("unroll")                                                    \
        for (int i = 0; i < 8; i++) {                                        \
            int idx = i * Q_THREADS + tid;                                   \
            int r = idx >> 3, c8 = idx & 7;                                  \
            cpa16(abase + (unsigned)(r * Q_P + c8 * 8) * 2u,                 \
                  Ab + (size_t)r * GK + (KC) * 64 + c8 * 8);                 \
        }                                                                    \
        _Pragma("unroll")                                                    \
        for (int i = 0; i < 4; i++) {                                        \
            int idx = i * Q_THREADS + tid;                                   \
            int r = idx >> 3, c8 = idx & 7;                                  \
            cpa16(bbase + (unsigned)(r * Q_P + c8 * 8) * 2u,                 \
                  Bb + (size_t)r * GK + (KC) * 64 + c8 * 8);                 \
        }                                                                    \
    }

    Q_FILL(0, 0);
    asm volatile("cp.async.commit_group;" ::: "memory");

    for (int it = 0; it < Q_ITERS; it++) {
        const int buf = it & 1;
        if (it + 1 < Q_ITERS) {
            Q_FILL(buf ^ 1, it + 1);
        }
        asm volatile("cp.async.commit_group;" ::: "memory");
        asm volatile("cp.async.wait_group 1;" ::: "memory");
        __syncthreads();

        const __half* As = smh + buf * Q_SH;
        const __half* Bs = As + Q_AH;

#pragma unroll
        for (int ks = 0; ks < 4; ks++) {
            uint2 af[4][2];
            uint2 bf[4];
#pragma unroll
            for (int mt = 0; mt < 4; mt++) {
                int r = wm * 64 + mt * 16 + g;
                af[mt][0] = *(const uint2*)(As + r * Q_P + ks * 16 + 4 * q);
                af[mt][1] = *(const uint2*)(As + (r + 8) * Q_P + ks * 16 + 4 * q);
            }
#pragma unroll
            for (int nt = 0; nt < 4; nt++) {
                int c = wn * 32 + nt * 8 + g;
                bf[nt] = *(const uint2*)(Bs + c * Q_P + ks * 16 + 4 * q);
            }
#pragma unroll
            for (int mt = 0; mt < 4; mt++)
#pragma unroll
                for (int nt = 0; nt < 4; nt++)
                    mma_f16(acc[mt][nt],
                            af[mt][0].x, af[mt][1].x,
                            af[mt][0].y, af[mt][1].y,
                            bf[nt].x,    bf[nt].y);
        }
        __syncthreads();
    }
#undef Q_FILL

    // Epilogue: head h == bn
    const int h = bn;
#pragma unroll
    for (int mt = 0; mt < 4; mt++) {
        int m0 = bm * 128 + wm * 64 + mt * 16 + g;
        int m1 = m0 + 8;
        int bb0 = m0 / SEQ, t0 = m0 % SEQ;
        int bb1 = m1 / SEQ, t1 = m1 % SEQ;
#pragma unroll
        for (int nt = 0; nt < 4; nt++) {
            int nb = wn * 32 + nt * 8;
            int n0 = bn * 64 + nb + 2 * q;
            float b0 = bias[n0] * bscale, b1 = bias[n0 + 1] * bscale;
            float v00 = acc[mt][nt][0] + b0;
            float v01 = acc[mt][nt][1] + b1;
            float v10 = acc[mt][nt][2] + b0;
            float v11 = acc[mt][nt][3] + b1;
            if (z != 2) {
                int slot = (nb & ~15) + 4 * q + 2 * (nt & 1);
                size_t r0o = (((size_t)(bb0 * N_HEADS + h) * SEQ) + t0) * HEAD_DIM;
                size_t r1o = (((size_t)(bb1 * N_HEADS + h) * SEQ) + t1) * HEAD_DIM;
                *(unsigned*)(C + r0o + slot) = f2h2(v00, v01);
                *(unsigned*)(C + r1o + slot) = f2h2(v10, v11);
            } else {
                int d0 = nb + 2 * q;
                int t0p = (t0 & ~15) + 4 * (g >> 1) + (g & 1);
                int t1p = (t1 & ~15) + 4 * (g >> 1) + 2 + (g & 1);
                size_t base0 = ((size_t)(bb0 * N_HEADS + h) * HEAD_DIM + d0) * SEQ;
                size_t base1 = ((size_t)(bb1 * N_HEADS + h) * HEAD_DIM + d0) * SEQ;
                ((unsigned short*)C)[base0 + t0p]       = f2h(v00);
                ((unsigned short*)C)[base0 + SEQ + t0p] = f2h(v01);
                ((unsigned short*)C)[base1 + t1p]       = f2h(v10);
                ((unsigned short*)C)[base1 + SEQ + t1p] = f2h(v11);
            }
        }
    }
}

// ---------------------------------------------------------------------------
// O-proj GEMM: BM=128, BN=128, 256 threads = 8 warps (2m x 4n), 2-stage,
// 80 KB smem -> 2 CTAs/SM. fp32 [M,N] output.
// ---------------------------------------------------------------------------
#define G_P   80
#define G_AH  (128 * G_P)
#define G_BH  (128 * G_P)
#define G_SH  (G_AH + G_BH)
#define G_SMEM (2 * G_SH * 2)          // 81920 B
#define G_ITERS (GK / 64)
#define G_THREADS 256

__global__ void __launch_bounds__(G_THREADS, 2) gemm_o_kernel(
    const __half* __restrict__ A, const __half* __restrict__ B,
    const float* __restrict__ bias, float* __restrict__ C)
{
    extern __shared__ __align__(128) __half smh[];

    const int tid  = threadIdx.x;
    const int lane = tid & 31;
    const int w    = tid >> 5;
    const int wm   = w >> 2;
    const int wn   = w & 3;
    const int g    = lane >> 2;
    const int q    = lane & 3;
    const int bm   = blockIdx.y;
    const int bn   = blockIdx.x;

    const __half* Ab = A + (size_t)bm * 128 * GK;
    const __half* Bb = B + (size_t)bn * 128 * GK;
    const unsigned sb = (unsigned)__cvta_generic_to_shared(smh);

    float acc[4][4][4];
#pragma unroll
    for (int mt = 0; mt < 4; mt++)
#pragma unroll
        for (int nt = 0; nt < 4; nt++)
#pragma unroll
            for (int i = 0; i < 4; i++) acc[mt][nt][i] = 0.0f;

#define G_FILL(S, KC)                                                        \
    {                                                                        \
        unsigned abase = sb + (unsigned)(S) * (G_SH * 2);                    \
        unsigned bbase = abase + (G_AH * 2);                                 \
        _Pragma("unroll")                                                    \
        for (int i = 0; i < 4; i++) {                                        \
            int idx = i * G_THREADS + tid;                                   \
            int r = idx >> 3, c8 = idx & 7;                                  \
            cpa16(abase + (unsigned)(r * G_P + c8 * 8) * 2u,                 \
                  Ab + (size_t)r * GK + (KC) * 64 + c8 * 8);                 \
        }                                                                    \
        _Pragma("unroll")                                                    \
        for (int i = 0; i < 4; i++) {                                        \
            int idx = i * G_THREADS + tid;                                   \
            int r = idx >> 3, c8 = idx & 7;                                  \
            cpa16(bbase + (unsigned)(r * G_P + c8 * 8) * 2u,                 \
                  Bb + (size_t)r * GK + (KC) * 64 + c8 * 8);                 \
        }                                                                    \
    }

    G_FILL(0, 0);
    asm volatile("cp.async.commit_group;" ::: "memory");

    for (int it = 0; it < G_ITERS; it++) {
        const int buf = it & 1;
        if (it + 1 < G_ITERS) {
            G_FILL(buf ^ 1, it + 1);
        }
        asm volatile("cp.async.commit_group;" ::: "memory");
        asm volatile("cp.async.wait_group 1;" ::: "memory");
        __syncthreads();

        const __half* As = smh + buf * G_SH;
        const __half* Bs = As + G_AH;

#pragma unroll
        for (int ks = 0; ks < 4; ks++) {
            uint2 af[4][2];
            uint2 bf[4];
#pragma unroll
            for (int mt = 0; mt < 4; mt++) {
                int r = wm * 64 + mt * 16 + g;
                af[mt][0] = *(const uint2*)(As + r * G_P + ks * 16 + 4 * q);
                af[mt][1] = *(const uint2*)(As + (r + 8) * G_P + ks * 16 + 4 * q);
            }
#pragma unroll
            for (int nt = 0; nt < 4; nt++) {
                int c = wn * 32 + nt * 8 + g;
                bf[nt] = *(const uint2*)(Bs + c * G_P + ks * 16 + 4 * q);
            }
#pragma unroll
            for (int mt = 0; mt < 4; mt++)
#pragma unroll
                for (int nt = 0; nt < 4; nt++)
                    mma_f16(acc[mt][nt],
                            af[mt][0].x, af[mt][1].x,
                            af[mt][0].y, af[mt][1].y,
                            bf[nt].x,    bf[nt].y);
        }
        __syncthreads();
    }
#undef G_FILL

#pragma unroll
    for (int mt = 0; mt < 4; mt++) {
        int m0 = bm * 128 + wm * 64 + mt * 16 + g;
        int m1 = m0 + 8;
#pragma unroll
        for (int nt = 0; nt < 4; nt++) {
            int n0 = bn * 128 + wn * 32 + nt * 8 + 2 * q;
            float b0 = bias[n0], b1 = bias[n0 + 1];
            float2 u0; u0.x = acc[mt][nt][0] + b0; u0.y = acc[mt][nt][1] + b1;
            *(float2*)&C[(size_t)m0 * GN + n0] = u0;
            float2 u1; u1.x = acc[mt][nt][2] + b0; u1.y = acc[mt][nt][3] + b1;
            *(float2*)&C[(size_t)m1 * GN + n0] = u1;
        }
    }
}

// ---------------------------------------------------------------------------
// Flash attention (fp16 mma): CTA = 128 q-rows for one (b,h), 64-key tiles.
// P stays in registers (QK accumulator fragment == PV A-operand fragment).
// K/V via cp.async double buffer. smem 61.4 KB.
// ---------------------------------------------------------------------------
#define AP 80
#define A_TILEH (64 * AP)
#define A_KS0 0
#define A_VS0 A_TILEH
#define A_KS1 (2 * A_TILEH)
#define A_VS1 (3 * A_TILEH)
#define A_QS  (4 * A_TILEH)
#define ATTN_SMEM ((A_QS + 128 * AP) * 2)   // 61440 B

__global__ void __launch_bounds__(256, 2) attn_h_kernel(
    const __half* __restrict__ Q, const __half* __restrict__ K,
    const __half* __restrict__ Vt, __half* __restrict__ Y)
{
    extern __shared__ __half smha[];
    __half* Qs = smha + A_QS;

    const int tid  = threadIdx.x;
    const int lane = tid & 31;
    const int w    = tid >> 5;
    const int g    = lane >> 2;
    const int q    = lane & 3;
    const int qt   = (int)gridDim.x - 1 - (int)blockIdx.x;
    const int bh   = blockIdx.y;
    const int q0   = qt * 128;

    const int r0  = w * 16 + g;
    const int r1  = r0 + 8;
    const int gr0 = q0 + r0;
    const int gr1 = q0 + r1;
    const int gw0 = q0 + w * 16;

    const unsigned sb = (unsigned)__cvta_generic_to_shared(smha);
    const __half* Kb = K  + (size_t)bh * SEQ * HEAD_DIM;
    const __half* Vb = Vt + (size_t)bh * HEAD_DIM * SEQ;

#define A_FILL(S, K0)                                                        \
    {                                                                        \
        unsigned kba = sb + (unsigned)((S) ? A_KS1 : A_KS0) * 2u;            \
        unsigned vba = sb + (unsigned)((S) ? A_VS1 : A_VS0) * 2u;            \
        _Pragma("unroll")                                                    \
        for (int i = 0; i < 2; i++) {                                        \
            int idx = i * 256 + tid;                                         \
            int row = idx >> 3, c8 = idx & 7;                                \
            cpa16(kba + (unsigned)(row * AP + c8 * 8) * 2u,                  \
                  Kb + ((size_t)(K0) + row) * HEAD_DIM + c8 * 8);            \
            cpa16(vba + (unsigned)(row * AP + c8 * 8) * 2u,                  \
                  Vb + (size_t)row * SEQ + (K0) + c8 * 8);                   \
        }                                                                    \
    }

    {
        const __half* Qp = Q + ((size_t)bh * SEQ + q0) * HEAD_DIM;
#pragma unroll
        for (int i = 0; i < 4; i++) {
            int idx = i * 256 + tid;
            int row = idx >> 3, c8 = idx & 7;
            *(uint4*)(Qs + row * AP + c8 * 8) =
                *(const uint4*)(Qp + row * HEAD_DIM + c8 * 8);
        }
    }

    float o[8][4];
#pragma unroll
    for (int nt = 0; nt < 8; nt++)
#pragma unroll
        for (int i = 0; i < 4; i++) o[nt][i] = 0.0f;
    float m0 = -1e30f, m1 = -1e30f, l0 = 0.0f, l1 = 0.0f;

    const int kt_max = 2 * qt + 2;

    A_FILL(0, 0);
    asm volatile("cp.async.commit_group;" ::: "memory");

    for (int kt = 0; kt < kt_max; kt++) {
        const int buf = kt & 1;
        if (kt + 1 < kt_max) {
            A_FILL(buf ^ 1, (kt + 1) * 64);
        }
        asm volatile("cp.async.commit_group;" ::: "memory");
        asm volatile("cp.async.wait_group 1;" ::: "memory");
        __syncthreads();

        const __half* Ks = smha + (buf ? A_KS1 : A_KS0);
        const __half* Vs = smha + (buf ? A_VS1 : A_VS0);
        const int k0 = kt * 64;

        if (k0 <= gw0 + 15) {
            // ---- S = Q @ K^T (Q pre-scaled by 1/sqrt(d))
            float sc[8][4];
#pragma unroll
            for (int nt = 0; nt < 8; nt++)
#pragma unroll
                for (int i = 0; i < 4; i++) sc[nt][i] = 0.0f;

#pragma unroll
            for (int ks = 0; ks < 4; ks++) {
                uint2 a0 = *(const uint2*)(Qs + r0 * AP + ks * 16 + 4 * q);
                uint2 a1 = *(const uint2*)(Qs + r1 * AP + ks * 16 + 4 * q);
#pragma unroll
                for (int nt = 0; nt < 8; nt++) {
                    uint2 b = *(const uint2*)(Ks + (nt * 8 + g) * AP + ks * 16 + 4 * q);
                    mma_f16(sc[nt], a0.x, a1.x, a0.y, a1.y, b.x, b.y);
                }
            }

            const bool need_mask = (k0 + 63 > gr0 - g);
            if (need_mask) {
#pragma unroll
                for (int nt = 0; nt < 8; nt++) {
                    int ck = k0 + nt * 8 + 2 * q;
                    if (ck     > gr0) sc[nt][0] = -1e30f;
                    if (ck + 1 > gr0) sc[nt][1] = -1e30f;
                    if (ck     > gr1) sc[nt][2] = -1e30f;
                    if (ck + 1 > gr1) sc[nt][3] = -1e30f;
                }
            }

            // ---- warp-local online softmax
            float rm0 = -1e30f, rm1 = -1e30f;
#pragma unroll
            for (int nt = 0; nt < 8; nt++) {
                rm0 = fmaxf(rm0, fmaxf(sc[nt][0], sc[nt][1]));
                rm1 = fmaxf(rm1, fmaxf(sc[nt][2], sc[nt][3]));
            }
            rm0 = fmaxf(rm0, __shfl_xor_sync(0xffffffffu, rm0, 1));
            rm0 = fmaxf(rm0, __shfl_xor_sync(0xffffffffu, rm0, 2));
            rm1 = fmaxf(rm1, __shfl_xor_sync(0xffffffffu, rm1, 1));
            rm1 = fmaxf(rm1, __shfl_xor_sync(0xffffffffu, rm1, 2));

            float nm0 = fmaxf(m0, rm0);
            float nm1 = fmaxf(m1, rm1);
            float cr0 = __expf(m0 - nm0);
            float cr1 = __expf(m1 - nm1);

            float s0 = 0.0f, s1 = 0.0f;
#pragma unroll
            for (int nt = 0; nt < 8; nt++) {
                sc[nt][0] = __expf(sc[nt][0] - nm0);
                sc[nt][1] = __expf(sc[nt][1] - nm0);
                sc[nt][2] = __expf(sc[nt][2] - nm1);
                sc[nt][3] = __expf(sc[nt][3] - nm1);
                s0 += sc[nt][0] + sc[nt][1];
                s1 += sc[nt][2] + sc[nt][3];
            }
            s0 += __shfl_xor_sync(0xffffffffu, s0, 1);
            s0 += __shfl_xor_sync(0xffffffffu, s0, 2);
            s1 += __shfl_xor_sync(0xffffffffu, s1, 1);
            s1 += __shfl_xor_sync(0xffffffffu, s1, 2);

            l0 = l0 * cr0 + s0;
            l1 = l1 * cr1 + s1;
            m0 = nm0; m1 = nm1;

#pragma unroll
            for (int nt = 0; nt < 8; nt++) {
                o[nt][0] *= cr0; o[nt][1] *= cr0;
                o[nt][2] *= cr1; o[nt][3] *= cr1;
            }

            // ---- O += P @ V : P built directly in registers.
            // QK accumulator frag (rows g,g+8 x cols nt*8+2q,+1) maps exactly
            // onto the PV A-frag for k-step ks via nt = 2ks (k), 2ks+1 (k+8).
#pragma unroll
            for (int ks = 0; ks < 4; ks++) {
                unsigned pa0 = f2h2(sc[2*ks][0],     sc[2*ks][1]);
                unsigned pa1 = f2h2(sc[2*ks][2],     sc[2*ks][3]);
                unsigned pa2 = f2h2(sc[2*ks + 1][0], sc[2*ks + 1][1]);
                unsigned pa3 = f2h2(sc[2*ks + 1][2], sc[2*ks + 1][3]);
#pragma unroll
                for (int nt = 0; nt < 8; nt++) {
                    uint2 b = *(const uint2*)(Vs + (nt * 8 + g) * AP + ks * 16 + 4 * q);
                    mma_f16(o[nt], pa0, pa1, pa2, pa3, b.x, b.y);
                }
            }
        }
        __syncthreads();
    }

    const float inv0 = 1.0f / l0;
    const float inv1 = 1.0f / l1;
    const int b = bh >> 4;
    const int h = bh & 15;
    __half* y0 = Y + ((size_t)b * SEQ + gr0) * D_MODEL + h * HEAD_DIM;
    __half* y1 = Y + ((size_t)b * SEQ + gr1) * D_MODEL + h * HEAD_DIM;
#pragma unroll
    for (int nt = 0; nt < 8; nt++) {
        int slot = (nt >> 1) * 16 + 4 * q + 2 * (nt & 1);
        *(unsigned*)(y0 + slot) = f2h2(o[nt][0] * inv0, o[nt][1] * inv0);
        *(unsigned*)(y1 + slot) = f2h2(o[nt][2] * inv1, o[nt][3] * inv1);
    }
#undef A_FILL
}

// ---------------------------------------------------------------------------
// Launch
// ---------------------------------------------------------------------------
extern "C" void kernel_launch(void* const* d_in, const int* in_sizes, int n_in,
                              void* d_out, int out_size)
{
    const float* x  = (const float*)d_in[0];
    const float* Wq = (const float*)d_in[1];
    const float* bq = (const float*)d_in[2];
    const float* Wk = (const float*)d_in[3];
    const float* bk = (const float*)d_in[4];
    const float* Wv = (const float*)d_in[5];
    const float* bv = (const float*)d_in[6];
    const float* Wo = (const float*)d_in[7];
    const float* bo = (const float*)d_in[8];
    float* out = (float*)d_out;

    __half *xt, *Wqt, *Wkt, *Wvt, *Wot, *Qb, *Kb, *Vb, *Yb;
    cudaGetSymbolAddress((void**)&xt,  g_xt);
    cudaGetSymbolAddress((void**)&Wqt, g_Wqt);
    cudaGetSymbolAddress((void**)&Wkt, g_Wkt);
    cudaGetSymbolAddress((void**)&Wvt, g_Wvt);
    cudaGetSymbolAddress((void**)&Wot, g_Wot);
    cudaGetSymbolAddress((void**)&Qb,  g_Q);
    cudaGetSymbolAddress((void**)&Kb,  g_K);
    cudaGetSymbolAddress((void**)&Vb,  g_Vt);
    cudaGetSymbolAddress((void**)&Yb,  g_Y);

    static bool attr_set = false;
    if (!attr_set) {
        cudaFuncSetAttribute(gemm_qkv_kernel,
                             cudaFuncAttributeMaxDynamicSharedMemorySize, Q_SMEM);
        cudaFuncSetAttribute(gemm_o_kernel,
                             cudaFuncAttributeMaxDynamicSharedMemorySize, G_SMEM);
        cudaFuncSetAttribute(attn_h_kernel,
                             cudaFuncAttributeMaxDynamicSharedMemorySize, ATTN_SMEM);
        attr_set = true;
    }

    // fp16 + k-permute pre-conversion (Wq pre-scaled by 0.125)
    const int TOT4 = XN4 + 4 * WN4;
    cvt_all_kernel<<<TOT4 / 256, 256>>>(
        (const float4*)x,  (unsigned*)xt,
        (const float4*)Wq, (unsigned*)Wqt,
        (const float4*)Wk, (unsigned*)Wkt,
        (const float4*)Wv, (unsigned*)Wvt,
        (const float4*)Wo, (unsigned*)Wot);

    // Fused QKV projections
    dim3 qkvgrid(GN / 64, M_TOTAL / 128, 3);    // (16, 64, 3)
    gemm_qkv_kernel<<<qkvgrid, Q_THREADS, Q_SMEM>>>(
        xt, Wqt, bq, Qb, Wkt, bk, Kb, Wvt, bv, Vb);

    dim3 agrid(SEQ / 128, BATCH * N_HEADS);     // (16, 64)
    attn_h_kernel<<<agrid, 256, ATTN_SMEM>>>(Qb, Kb, Vb, Yb);

    // Output projection
    dim3 ogrid(GN / 128, M_TOTAL / 128);        // (8, 64)
    gemm_o_kernel<<<ogrid, G_THREADS, G_SMEM>>>(Yb, Wot, bo, out);
}

// round 15
// speedup vs baseline: 2.2937x; 1.0331x over previous
#include <cuda_runtime.h>
#include <cuda_fp16.h>
#include <math.h>

#define D_MODEL  1024
#define N_HEADS  16
#define HEAD_DIM 64
#define BATCH    4
#define SEQ      2048
#define M_TOTAL  (BATCH * SEQ)   // 8192
#define GK 1024
#define GN 1024

// ---------------------------------------------------------------------------
// Scratch (fp16; k-dims stored permuted per 16-group: j=8h+2q+e -> 4q+2h+e)
// Wq is pre-scaled by 0.125*log2(e) so attention does base-2 softmax with
// no scale multiply at all.
// ---------------------------------------------------------------------------
__device__ __align__(256) __half g_xt [(size_t)M_TOTAL * D_MODEL];
__device__ __align__(256) __half g_Wqt[(size_t)D_MODEL * D_MODEL];
__device__ __align__(256) __half g_Wkt[(size_t)D_MODEL * D_MODEL];
__device__ __align__(256) __half g_Wvt[(size_t)D_MODEL * D_MODEL];
__device__ __align__(256) __half g_Wot[(size_t)D_MODEL * D_MODEL];
__device__ __align__(256) __half g_Q  [(size_t)M_TOTAL * D_MODEL];  // [B,H,T,Dh] d-perm (pre-scaled)
__device__ __align__(256) __half g_K  [(size_t)M_TOTAL * D_MODEL];  // [B,H,T,Dh] d-perm
__device__ __align__(256) __half g_Vt [(size_t)M_TOTAL * D_MODEL];  // [B,H,Dh,T] t-perm
__device__ __align__(256) __half g_Y  [(size_t)M_TOTAL * D_MODEL];  // [B,T,D] D-perm

#define QSCALE (0.125f * 1.4426950408889634f)   // 1/sqrt(64) * log2(e)

// ---------------------------------------------------------------------------
// helpers
// ---------------------------------------------------------------------------
__device__ __forceinline__ unsigned f2h2(float lo, float hi) {
    __half2 h = __floats2half2_rn(lo, hi);
    return *(unsigned*)&h;
}
__device__ __forceinline__ unsigned short f2h(float v) {
    __half h = __float2half_rn(v);
    return *(unsigned short*)&h;
}

__device__ __forceinline__ void mma_f16(float c[4],
    unsigned a0, unsigned a1, unsigned a2, unsigned a3,
    unsigned b0, unsigned b1)
{
    asm volatile(
        "mma.sync.aligned.m16n8k16.row.col.f32.f16.f16.f32 "
        "{%0,%1,%2,%3}, {%4,%5,%6,%7}, {%8,%9}, {%0,%1,%2,%3};"
        : "+f"(c[0]), "+f"(c[1]), "+f"(c[2]), "+f"(c[3])
        : "r"(a0), "r"(a1), "r"(a2), "r"(a3), "r"(b0), "r"(b1));
}

__device__ __forceinline__ void cpa16(unsigned saddr, const void* gptr) {
    asm volatile("cp.async.cg.shared.global [%0], [%1], 16;"
                 :: "r"(saddr), "l"(gptr));
}

// ---------------------------------------------------------------------------
// fp32 -> fp16 + k-permute, fused over x + 4 weights (one launch).
// ---------------------------------------------------------------------------
#define XN4 (M_TOTAL * D_MODEL / 4)    // 2097152
#define WN4 (D_MODEL * D_MODEL / 4)    // 262144

__device__ __forceinline__ void cvt_one(const float4* __restrict__ src,
                                        unsigned* __restrict__ dst, int i, float s)
{
    float4 v = src[i];
    int wi = i * 4;
    int h2 = ((wi & ~15) >> 1) + 2 * ((wi >> 1) & 3) + ((wi >> 3) & 1);
    dst[h2]     = f2h2(v.x * s, v.y * s);
    dst[h2 + 2] = f2h2(v.z * s, v.w * s);
}

__global__ void cvt_all_kernel(
    const float4* __restrict__ x,  unsigned* __restrict__ xt,
    const float4* __restrict__ w0, unsigned* __restrict__ t0,
    const float4* __restrict__ w1, unsigned* __restrict__ t1,
    const float4* __restrict__ w2, unsigned* __restrict__ t2,
    const float4* __restrict__ w3, unsigned* __restrict__ t3)
{
    int i = blockIdx.x * blockDim.x + threadIdx.x;
    if (i < XN4) { cvt_one(x, xt, i, 1.0f); return; }
    int j = i - XN4;
    int wsel = j >> 18;
    int r    = j & (WN4 - 1);
    if      (wsel == 0) cvt_one(w0, t0, r, QSCALE);   // Wq pre-scaled
    else if (wsel == 1) cvt_one(w1, t1, r, 1.0f);
    else if (wsel == 2) cvt_one(w2, t2, r, 1.0f);
    else                cvt_one(w3, t3, r, 1.0f);
}

// ---------------------------------------------------------------------------
// QKV GEMM: BM=128, BN=64, BK=64; 128 threads = 4 warps (2m x 2n).
// 2-stage cp.async, SINGLE barrier per iter; 61.4 KB smem -> 3 CTAs/SM.
// z<2 -> [B,H,T,Dh] d-perm; z=2 -> [B,H,Dh,T] t-perm. z==0 bias scaled.
// ---------------------------------------------------------------------------
#define Q_P   80
#define Q_AH  (128 * Q_P)
#define Q_BH  (64 * Q_P)
#define Q_SH  (Q_AH + Q_BH)
#define Q_SMEM (2 * Q_SH * 2)          // 61440 B
#define Q_ITERS (GK / 64)              // 16
#define Q_THREADS 128

__global__ void __launch_bounds__(Q_THREADS, 3) gemm_qkv_kernel(
    const __half* __restrict__ A,
    const __half* __restrict__ B0, const float* __restrict__ bias0, __half* __restrict__ C0,
    const __half* __restrict__ B1, const float* __restrict__ bias1, __half* __restrict__ C1,
    const __half* __restrict__ B2, const float* __restrict__ bias2, __half* __restrict__ C2)
{
    extern __shared__ __align__(128) __half smh[];
    const int z = blockIdx.z;
    const __half* B    = (z == 0) ? B0    : (z == 1) ? B1    : B2;
    const float* bias  = (z == 0) ? bias0 : (z == 1) ? bias1 : bias2;
    __half*      C     = (z == 0) ? C0    : (z == 1) ? C1    : C2;
    const float bscale = (z == 0) ? QSCALE : 1.0f;

    const int tid  = threadIdx.x;
    const int lane = tid & 31;
    const int w    = tid >> 5;
    const int wm   = w >> 1;
    const int wn   = w & 1;
    const int g    = lane >> 2;
    const int q    = lane & 3;
    const int bm   = blockIdx.y;
    const int bn   = blockIdx.x;     // head index

    const __half* Ab = A + (size_t)bm * 128 * GK;
    const __half* Bb = B + (size_t)bn * 64 * GK;
    const unsigned sb = (unsigned)__cvta_generic_to_shared(smh);

    float acc[4][4][4];
#pragma unroll
    for (int mt = 0; mt < 4; mt++)
#pragma unroll
        for (int nt = 0; nt < 4; nt++)
#pragma unroll
            for (int i = 0; i < 4; i++) acc[mt][nt][i] = 0.0f;

#define Q_FILL(S, KC)                                                        \
    {                                                                        \
        unsigned abase = sb + (unsigned)(S) * (Q_SH * 2);                    \
        unsigned bbase = abase + (Q_AH * 2);                                 \
        _Pragma("unroll")                                                    \
        for (int i = 0; i < 8; i++) {                                        \
            int idx = i * Q_THREADS + tid;                                   \
            int r = idx >> 3, c8 = idx & 7;                                  \
            cpa16(abase + (unsigned)(r * Q_P + c8 * 8) * 2u,                 \
                  Ab + (size_t)r * GK + (KC) * 64 + c8 * 8);                 \
        }                                                                    \
        _Pragma("unroll")                                                    \
        for (int i = 0; i < 4; i++) {                                        \
            int idx = i * Q_THREADS + tid;                                   \
            int r = idx >> 3, c8 = idx & 7;                                  \
            cpa16(bbase + (unsigned)(r * Q_P + c8 * 8) * 2u,                 \
                  Bb + (size_t)r * GK + (KC) * 64 + c8 * 8);                 \
        }                                                                    \
    }

    Q_FILL(0, 0);
    asm volatile("cp.async.commit_group;" ::: "memory");

    for (int it = 0; it < Q_ITERS; it++) {
        const int buf = it & 1;
        // drain fill(it); barrier also proves compute(it-1) done on buf^1
        asm volatile("cp.async.wait_group 0;" ::: "memory");
        __syncthreads();
        if (it + 1 < Q_ITERS) {
            Q_FILL(buf ^ 1, it + 1);
        }
        asm volatile("cp.async.commit_group;" ::: "memory");

        const __half* As = smh + buf * Q_SH;
        const __half* Bs = As + Q_AH;

#pragma unroll
        for (int ks = 0; ks < 4; ks++) {
            uint2 af[4][2];
            uint2 bf[4];
#pragma unroll
            for (int mt = 0; mt < 4; mt++) {
                int r = wm * 64 + mt * 16 + g;
                af[mt][0] = *(const uint2*)(As + r * Q_P + ks * 16 + 4 * q);
                af[mt][1] = *(const uint2*)(As + (r + 8) * Q_P + ks * 16 + 4 * q);
            }
#pragma unroll
            for (int nt = 0; nt < 4; nt++) {
                int c = wn * 32 + nt * 8 + g;
                bf[nt] = *(const uint2*)(Bs + c * Q_P + ks * 16 + 4 * q);
            }
#pragma unroll
            for (int mt = 0; mt < 4; mt++)
#pragma unroll
                for (int nt = 0; nt < 4; nt++)
                    mma_f16(acc[mt][nt],
                            af[mt][0].x, af[mt][1].x,
                            af[mt][0].y, af[mt][1].y,
                            bf[nt].x,    bf[nt].y);
        }
    }
#undef Q_FILL

    const int h = bn;
#pragma unroll
    for (int mt = 0; mt < 4; mt++) {
        int m0 = bm * 128 + wm * 64 + mt * 16 + g;
        int m1 = m0 + 8;
        int bb0 = m0 / SEQ, t0 = m0 % SEQ;
        int bb1 = m1 / SEQ, t1 = m1 % SEQ;
#pragma unroll
        for (int nt = 0; nt < 4; nt++) {
            int nb = wn * 32 + nt * 8;
            int n0 = bn * 64 + nb + 2 * q;
            float b0 = bias[n0] * bscale, b1 = bias[n0 + 1] * bscale;
            float v00 = acc[mt][nt][0] + b0;
            float v01 = acc[mt][nt][1] + b1;
            float v10 = acc[mt][nt][2] + b0;
            float v11 = acc[mt][nt][3] + b1;
            if (z != 2) {
                int slot = (nb & ~15) + 4 * q + 2 * (nt & 1);
                size_t r0o = (((size_t)(bb0 * N_HEADS + h) * SEQ) + t0) * HEAD_DIM;
                size_t r1o = (((size_t)(bb1 * N_HEADS + h) * SEQ) + t1) * HEAD_DIM;
                *(unsigned*)(C + r0o + slot) = f2h2(v00, v01);
                *(unsigned*)(C + r1o + slot) = f2h2(v10, v11);
            } else {
                int d0 = nb + 2 * q;
                int t0p = (t0 & ~15) + 4 * (g >> 1) + (g & 1);
                int t1p = (t1 & ~15) + 4 * (g >> 1) + 2 + (g & 1);
                size_t base0 = ((size_t)(bb0 * N_HEADS + h) * HEAD_DIM + d0) * SEQ;
                size_t base1 = ((size_t)(bb1 * N_HEADS + h) * HEAD_DIM + d0) * SEQ;
                ((unsigned short*)C)[base0 + t0p]       = f2h(v00);
                ((unsigned short*)C)[base0 + SEQ + t0p] = f2h(v01);
                ((unsigned short*)C)[base1 + t1p]       = f2h(v10);
                ((unsigned short*)C)[base1 + SEQ + t1p] = f2h(v11);
            }
        }
    }
}

// ---------------------------------------------------------------------------
// O-proj GEMM: BM=128, BN=128, 256 threads = 8 warps (2m x 4n), 2-stage,
// single barrier per iter, 80 KB smem -> 2 CTAs/SM. fp32 [M,N] output.
// ---------------------------------------------------------------------------
#define G_P   80
#define G_AH  (128 * G_P)
#define G_BH  (128 * G_P)
#define G_SH  (G_AH + G_BH)
#define G_SMEM (2 * G_SH * 2)          // 81920 B
#define G_ITERS (GK / 64)
#define G_THREADS 256

__global__ void __launch_bounds__(G_THREADS, 2) gemm_o_kernel(
    const __half* __restrict__ A, const __half* __restrict__ B,
    const float* __restrict__ bias, float* __restrict__ C)
{
    extern __shared__ __align__(128) __half smh[];

    const int tid  = threadIdx.x;
    const int lane = tid & 31;
    const int w    = tid >> 5;
    const int wm   = w >> 2;
    const int wn   = w & 3;
    const int g    = lane >> 2;
    const int q    = lane & 3;
    const int bm   = blockIdx.y;
    const int bn   = blockIdx.x;

    const __half* Ab = A + (size_t)bm * 128 * GK;
    const __half* Bb = B + (size_t)bn * 128 * GK;
    const unsigned sb = (unsigned)__cvta_generic_to_shared(smh);

    float acc[4][4][4];
#pragma unroll
    for (int mt = 0; mt < 4; mt++)
#pragma unroll
        for (int nt = 0; nt < 4; nt++)
#pragma unroll
            for (int i = 0; i < 4; i++) acc[mt][nt][i] = 0.0f;

#define G_FILL(S, KC)                                                        \
    {                                                                        \
        unsigned abase = sb + (unsigned)(S) * (G_SH * 2);                    \
        unsigned bbase = abase + (G_AH * 2);                                 \
        _Pragma("unroll")                                                    \
        for (int i = 0; i < 4; i++) {                                        \
            int idx = i * G_THREADS + tid;                                   \
            int r = idx >> 3, c8 = idx & 7;                                  \
            cpa16(abase + (unsigned)(r * G_P + c8 * 8) * 2u,                 \
                  Ab + (size_t)r * GK + (KC) * 64 + c8 * 8);                 \
        }                                                                    \
        _Pragma("unroll")                                                    \
        for (int i = 0; i < 4; i++) {                                        \
            int idx = i * G_THREADS + tid;                                   \
            int r = idx >> 3, c8 = idx & 7;                                  \
            cpa16(bbase + (unsigned)(r * G_P + c8 * 8) * 2u,                 \
                  Bb + (size_t)r * GK + (KC) * 64 + c8 * 8);                 \
        }                                                                    \
    }

    G_FILL(0, 0);
    asm volatile("cp.async.commit_group;" ::: "memory");

    for (int it = 0; it < G_ITERS; it++) {
        const int buf = it & 1;
        asm volatile("cp.async.wait_group 0;" ::: "memory");
        __syncthreads();
        if (it + 1 < G_ITERS) {
            G_FILL(buf ^ 1, it + 1);
        }
        asm volatile("cp.async.commit_group;" ::: "memory");

        const __half* As = smh + buf * G_SH;
        const __half* Bs = As + G_AH;

#pragma unroll
        for (int ks = 0; ks < 4; ks++) {
            uint2 af[4][2];
            uint2 bf[4];
#pragma unroll
            for (int mt = 0; mt < 4; mt++) {
                int r = wm * 64 + mt * 16 + g;
                af[mt][0] = *(const uint2*)(As + r * G_P + ks * 16 + 4 * q);
                af[mt][1] = *(const uint2*)(As + (r + 8) * G_P + ks * 16 + 4 * q);
            }
#pragma unroll
            for (int nt = 0; nt < 4; nt++) {
                int c = wn * 32 + nt * 8 + g;
                bf[nt] = *(const uint2*)(Bs + c * G_P + ks * 16 + 4 * q);
            }
#pragma unroll
            for (int mt = 0; mt < 4; mt++)
#pragma unroll
                for (int nt = 0; nt < 4; nt++)
                    mma_f16(acc[mt][nt],
                            af[mt][0].x, af[mt][1].x,
                            af[mt][0].y, af[mt][1].y,
                            bf[nt].x,    bf[nt].y);
        }
    }
#undef G_FILL

#pragma unroll
    for (int mt = 0; mt < 4; mt++) {
        int m0 = bm * 128 + wm * 64 + mt * 16 + g;
        int m1 = m0 + 8;
#pragma unroll
        for (int nt = 0; nt < 4; nt++) {
            int n0 = bn * 128 + wn * 32 + nt * 8 + 2 * q;
            float b0 = bias[n0], b1 = bias[n0 + 1];
            float2 u0; u0.x = acc[mt][nt][0] + b0; u0.y = acc[mt][nt][1] + b1;
            *(float2*)&C[(size_t)m0 * GN + n0] = u0;
            float2 u1; u1.x = acc[mt][nt][2] + b0; u1.y = acc[mt][nt][3] + b1;
            *(float2*)&C[(size_t)m1 * GN + n0] = u1;
        }
    }
}

// ---------------------------------------------------------------------------
// Flash attention (fp16 mma, base-2 softmax): CTA = 128 q-rows, 64-key tiles.
// P in registers; K/V cp.async double buffer, single barrier per tile.
// ---------------------------------------------------------------------------
#define AP 80
#define A_TILEH (64 * AP)
#define A_KS0 0
#define A_VS0 A_TILEH
#define A_KS1 (2 * A_TILEH)
#define A_VS1 (3 * A_TILEH)
#define A_QS  (4 * A_TILEH)
#define ATTN_SMEM ((A_QS + 128 * AP) * 2)   // 61440 B

__global__ void __launch_bounds__(256, 2) attn_h_kernel(
    const __half* __restrict__ Q, const __half* __restrict__ K,
    const __half* __restrict__ Vt, __half* __restrict__ Y)
{
    extern __shared__ __half smha[];
    __half* Qs = smha + A_QS;

    const int tid  = threadIdx.x;
    const int lane = tid & 31;
    const int w    = tid >> 5;
    const int g    = lane >> 2;
    const int q    = lane & 3;
    const int qt   = (int)gridDim.x - 1 - (int)blockIdx.x;
    const int bh   = blockIdx.y;
    const int q0   = qt * 128;

    const int r0  = w * 16 + g;
    const int r1  = r0 + 8;
    const int gr0 = q0 + r0;
    const int gr1 = q0 + r1;
    const int gw0 = q0 + w * 16;

    const unsigned sb = (unsigned)__cvta_generic_to_shared(smha);
    const __half* Kb = K  + (size_t)bh * SEQ * HEAD_DIM;
    const __half* Vb = Vt + (size_t)bh * HEAD_DIM * SEQ;

#define A_FILL(S, K0)                                                        \
    {                                                                        \
        unsigned kba = sb + (unsigned)((S) ? A_KS1 : A_KS0) * 2u;            \
        unsigned vba = sb + (unsigned)((S) ? A_VS1 : A_VS0) * 2u;            \
        _Pragma("unroll")                                                    \
        for (int i = 0; i < 2; i++) {                                        \
            int idx = i * 256 + tid;                                         \
            int row = idx >> 3, c8 = idx & 7;                                \
            cpa16(kba + (unsigned)(row * AP + c8 * 8) * 2u,                  \
                  Kb + ((size_t)(K0) + row) * HEAD_DIM + c8 * 8);            \
            cpa16(vba + (unsigned)(row * AP + c8 * 8) * 2u,                  \
                  Vb + (size_t)row * SEQ + (K0) + c8 * 8);                   \
        }                                                                    \
    }

    {
        const __half* Qp = Q + ((size_t)bh * SEQ + q0) * HEAD_DIM;
#pragma unroll
        for (int i = 0; i < 4; i++) {
            int idx = i * 256 + tid;
            int row = idx >> 3, c8 = idx & 7;
            *(uint4*)(Qs + row * AP + c8 * 8) =
                *(const uint4*)(Qp + row * HEAD_DIM + c8 * 8);
        }
    }

    float o[8][4];
#pragma unroll
    for (int nt = 0; nt < 8; nt++)
#pragma unroll
        for (int i = 0; i < 4; i++) o[nt][i] = 0.0f;
    float m0 = -1e30f, m1 = -1e30f, l0 = 0.0f, l1 = 0.0f;

    const int kt_max = 2 * qt + 2;

    A_FILL(0, 0);
    asm volatile("cp.async.commit_group;" ::: "memory");

    for (int kt = 0; kt < kt_max; kt++) {
        const int buf = kt & 1;
        asm volatile("cp.async.wait_group 0;" ::: "memory");
        __syncthreads();   // fill(kt) visible; compute(kt-1) done on buf^1
        if (kt + 1 < kt_max) {
            A_FILL(buf ^ 1, (kt + 1) * 64);
        }
        asm volatile("cp.async.commit_group;" ::: "memory");

        const __half* Ks = smha + (buf ? A_KS1 : A_KS0);
        const __half* Vs = smha + (buf ? A_VS1 : A_VS0);
        const int k0 = kt * 64;

        if (k0 <= gw0 + 15) {
            // ---- S2 = Q @ K^T (already in log2 domain via pre-scaled Q)
            float sc[8][4];
#pragma unroll
            for (int nt = 0; nt < 8; nt++)
#pragma unroll
                for (int i = 0; i < 4; i++) sc[nt][i] = 0.0f;

#pragma unroll
            for (int ks = 0; ks < 4; ks++) {
                uint2 a0 = *(const uint2*)(Qs + r0 * AP + ks * 16 + 4 * q);
                uint2 a1 = *(const uint2*)(Qs + r1 * AP + ks * 16 + 4 * q);
#pragma unroll
                for (int nt = 0; nt < 8; nt++) {
                    uint2 b = *(const uint2*)(Ks + (nt * 8 + g) * AP + ks * 16 + 4 * q);
                    mma_f16(sc[nt], a0.x, a1.x, a0.y, a1.y, b.x, b.y);
                }
            }

            const bool need_mask = (k0 + 63 > gr0 - g);
            if (need_mask) {
#pragma unroll
                for (int nt = 0; nt < 8; nt++) {
                    int ck = k0 + nt * 8 + 2 * q;
                    if (ck     > gr0) sc[nt][0] = -1e30f;
                    if (ck + 1 > gr0) sc[nt][1] = -1e30f;
                    if (ck     > gr1) sc[nt][2] = -1e30f;
                    if (ck + 1 > gr1) sc[nt][3] = -1e30f;
                }
            }

            // ---- warp-local online softmax (base 2)
            float rm0 = -1e30f, rm1 = -1e30f;
#pragma unroll
            for (int nt = 0; nt < 8; nt++) {
                rm0 = fmaxf(rm0, fmaxf(sc[nt][0], sc[nt][1]));
                rm1 = fmaxf(rm1, fmaxf(sc[nt][2], sc[nt][3]));
            }
            rm0 = fmaxf(rm0, __shfl_xor_sync(0xffffffffu, rm0, 1));
            rm0 = fmaxf(rm0, __shfl_xor_sync(0xffffffffu, rm0, 2));
            rm1 = fmaxf(rm1, __shfl_xor_sync(0xffffffffu, rm1, 1));
            rm1 = fmaxf(rm1, __shfl_xor_sync(0xffffffffu, rm1, 2));

            float nm0 = fmaxf(m0, rm0);
            float nm1 = fmaxf(m1, rm1);
            float cr0 = exp2f(m0 - nm0);
            float cr1 = exp2f(m1 - nm1);

            float s0 = 0.0f, s1 = 0.0f;
#pragma unroll
            for (int nt = 0; nt < 8; nt++) {
                sc[nt][0] = exp2f(sc[nt][0] - nm0);
                sc[nt][1] = exp2f(sc[nt][1] - nm0);
                sc[nt][2] = exp2f(sc[nt][2] - nm1);
                sc[nt][3] = exp2f(sc[nt][3] - nm1);
                s0 += sc[nt][0] + sc[nt][1];
                s1 += sc[nt][2] + sc[nt][3];
            }
            s0 += __shfl_xor_sync(0xffffffffu, s0, 1);
            s0 += __shfl_xor_sync(0xffffffffu, s0, 2);
            s1 += __shfl_xor_sync(0xffffffffu, s1, 1);
            s1 += __shfl_xor_sync(0xffffffffu, s1, 2);

            l0 = l0 * cr0 + s0;
            l1 = l1 * cr1 + s1;
            m0 = nm0; m1 = nm1;

#pragma unroll
            for (int nt = 0; nt < 8; nt++) {
                o[nt][0] *= cr0; o[nt][1] *= cr0;
                o[nt][2] *= cr1; o[nt][3] *= cr1;
            }

            // ---- O += P @ V (P built in registers)
#pragma unroll
            for (int ks = 0; ks < 4; ks++) {
                unsigned pa0 = f2h2(sc[2*ks][0],     sc[2*ks][1]);
                unsigned pa1 = f2h2(sc[2*ks][2],     sc[2*ks][3]);
                unsigned pa2 = f2h2(sc[2*ks + 1][0], sc[2*ks + 1][1]);
                unsigned pa3 = f2h2(sc[2*ks + 1][2], sc[2*ks + 1][3]);
#pragma unroll
                for (int nt = 0; nt < 8; nt++) {
                    uint2 b = *(const uint2*)(Vs + (nt * 8 + g) * AP + ks * 16 + 4 * q);
                    mma_f16(o[nt], pa0, pa1, pa2, pa3, b.x, b.y);
                }
            }
        }
    }

    const float inv0 = 1.0f / l0;
    const float inv1 = 1.0f / l1;
    const int b = bh >> 4;
    const int h = bh & 15;
    __half* y0 = Y + ((size_t)b * SEQ + gr0) * D_MODEL + h * HEAD_DIM;
    __half* y1 = Y + ((size_t)b * SEQ + gr1) * D_MODEL + h * HEAD_DIM;
#pragma unroll
    for (int nt = 0; nt < 8; nt++) {
        int slot = (nt >> 1) * 16 + 4 * q + 2 * (nt & 1);
        *(unsigned*)(y0 + slot) = f2h2(o[nt][0] * inv0, o[nt][1] * inv0);
        *(unsigned*)(y1 + slot) = f2h2(o[nt][2] * inv1, o[nt][3] * inv1);
    }
#undef A_FILL
}

// ---------------------------------------------------------------------------
// Launch
// ---------------------------------------------------------------------------
extern "C" void kernel_launch(void* const* d_in, const int* in_sizes, int n_in,
                              void* d_out, int out_size)
{
    const float* x  = (const float*)d_in[0];
    const float* Wq = (const float*)d_in[1];
    const float* bq = (const float*)d_in[2];
    const float* Wk = (const float*)d_in[3];
    const float* bk = (const float*)d_in[4];
    const float* Wv = (const float*)d_in[5];
    const float* bv = (const float*)d_in[6];
    const float* Wo = (const float*)d_in[7];
    const float* bo = (const float*)d_in[8];
    float* out = (float*)d_out;

    __half *xt, *Wqt, *Wkt, *Wvt, *Wot, *Qb, *Kb, *Vb, *Yb;
    cudaGetSymbolAddress((void**)&xt,  g_xt);
    cudaGetSymbolAddress((void**)&Wqt, g_Wqt);
    cudaGetSymbolAddress((void**)&Wkt, g_Wkt);
    cudaGetSymbolAddress((void**)&Wvt, g_Wvt);
    cudaGetSymbolAddress((void**)&Wot, g_Wot);
    cudaGetSymbolAddress((void**)&Qb,  g_Q);
    cudaGetSymbolAddress((void**)&Kb,  g_K);
    cudaGetSymbolAddress((void**)&Vb,  g_Vt);
    cudaGetSymbolAddress((void**)&Yb,  g_Y);

    static bool attr_set = false;
    if (!attr_set) {
        cudaFuncSetAttribute(gemm_qkv_kernel,
                             cudaFuncAttributeMaxDynamicSharedMemorySize, Q_SMEM);
        cudaFuncSetAttribute(gemm_o_kernel,
                             cudaFuncAttributeMaxDynamicSharedMemorySize, G_SMEM);
        cudaFuncSetAttribute(attn_h_kernel,
                             cudaFuncAttributeMaxDynamicSharedMemorySize, ATTN_SMEM);
        attr_set = true;
    }

    // fp16 + k-permute pre-conversion (Wq pre-scaled by 0.125*log2e)
    const int TOT4 = XN4 + 4 * WN4;
    cvt_all_kernel<<<TOT4 / 256, 256>>>(
        (const float4*)x,  (unsigned*)xt,
        (const float4*)Wq, (unsigned*)Wqt,
        (const float4*)Wk, (unsigned*)Wkt,
        (const float4*)Wv, (unsigned*)Wvt,
        (const float4*)Wo, (unsigned*)Wot);

    // Fused QKV projections
    dim3 qkvgrid(GN / 64, M_TOTAL / 128, 3);    // (16, 64, 3)
    gemm_qkv_kernel<<<qkvgrid, Q_THREADS, Q_SMEM>>>(
        xt, Wqt, bq, Qb, Wkt, bk, Kb, Wvt, bv, Vb);

    dim3 agrid(SEQ / 128, BATCH * N_HEADS);     // (16, 64)
    attn_h_kernel<<<agrid, 256, ATTN_SMEM>>>(Qb, Kb, Vb, Yb);

    // Output projection
    dim3 ogrid(GN / 128, M_TOTAL / 128);        // (8, 64)
    gemm_o_kernel<<<ogrid, G_THREADS, G_SMEM>>>(Yb, Wot, bo, out);
}